// round 2
// baseline (speedup 1.0000x reference)
#include <cuda_runtime.h>
#include <math.h>

#define NATOMS 40001
#define NBONDS 160001
#define NNB    6
#define AFDIM  133
#define BFDIM  147
#define HD     300
#define NMOLS  1000
#define ASIZE  40
#define NSEQ   (NMOLS * ASIZE)   /* 40000 */

// ---------------- scratch (static device globals; no runtime allocation) ----------------
__device__ float g_input_atom  [NATOMS * HD];
__device__ float g_message_atom[NATOMS * HD];
__device__ float g_input_bond  [NBONDS * HD];
__device__ float g_message_bond[NBONDS * HD];
__device__ float g_mb          [NBONDS * HD];
__device__ float g_concat      [NSEQ * 3 * HD];
__device__ float g_aggW        [NSEQ * HD];
__device__ float g_msg         [NSEQ * HD];
__device__ float g_xpf         [NSEQ * 3 * HD];
__device__ float g_xpb         [NSEQ * 3 * HD];
__device__ float g_h0          [NMOLS * HD];
__device__ float g_h           [NMOLS * HD];
__device__ float g_gh          [NMOLS * 3 * HD];
__device__ float g_out         [NSEQ * 2 * HD];
__device__ float g_hid         [NSEQ * HD];

// ---------------- generic tiled SGEMM ----------------
// C[M,N] = epilogue(A[M,K] * B)   B row-major [K,N], or TRANSB: B is W[N,K] row-major
// EPI: 0 = none, 1 = relu, 2 = relu(acc + ADD), 3 = acc + bias, 4 = relu(acc + bias)
template<bool TRANSB, int EPI>
__global__ void sgemm_kernel(const float* __restrict__ A, const float* __restrict__ B,
                             const float* __restrict__ ADD, const float* __restrict__ bias,
                             float* __restrict__ C, int M, int N, int K)
{
    __shared__ float As[16][65];
    __shared__ float Bs[16][65];

    const int tid = threadIdx.x;
    const int tx  = tid & 15;   // n direction
    const int ty  = tid >> 4;   // m direction
    const int blockM = blockIdx.y * 64;
    const int blockN = blockIdx.x * 64;

    float acc[4][4] = {};

    for (int kt = 0; kt < K; kt += 16) {
        // load A tile: 64 rows x 16 k
        #pragma unroll
        for (int r = 0; r < 4; r++) {
            int idx = tid + r * 256;
            int m = idx >> 4, k = idx & 15;
            int gm = blockM + m, gk = kt + k;
            As[k][m] = (gm < M && gk < K) ? A[gm * K + gk] : 0.f;
        }
        if (!TRANSB) {
            #pragma unroll
            for (int r = 0; r < 4; r++) {
                int idx = tid + r * 256;
                int k = idx >> 6, n = idx & 63;
                int gk = kt + k, gn = blockN + n;
                Bs[k][n] = (gk < K && gn < N) ? B[gk * N + gn] : 0.f;
            }
        } else {
            #pragma unroll
            for (int r = 0; r < 4; r++) {
                int idx = tid + r * 256;
                int n = idx >> 4, k = idx & 15;
                int gk = kt + k, gn = blockN + n;
                Bs[k][n] = (gk < K && gn < N) ? B[gn * K + gk] : 0.f;
            }
        }
        __syncthreads();

        #pragma unroll
        for (int kk = 0; kk < 16; kk++) {
            float ra[4], rb[4];
            #pragma unroll
            for (int i = 0; i < 4; i++) ra[i] = As[kk][ty + 16 * i];
            #pragma unroll
            for (int j = 0; j < 4; j++) rb[j] = Bs[kk][tx + 16 * j];
            #pragma unroll
            for (int i = 0; i < 4; i++)
                #pragma unroll
                for (int j = 0; j < 4; j++)
                    acc[i][j] = fmaf(ra[i], rb[j], acc[i][j]);
        }
        __syncthreads();
    }

    #pragma unroll
    for (int i = 0; i < 4; i++) {
        int gm = blockM + ty + 16 * i;
        if (gm >= M) continue;
        #pragma unroll
        for (int j = 0; j < 4; j++) {
            int gn = blockN + tx + 16 * j;
            if (gn >= N) continue;
            float v = acc[i][j];
            if (EPI == 2)               v += ADD[gm * N + gn];
            if (EPI == 3 || EPI == 4)   v += bias[gn];
            if (EPI == 1 || EPI == 2 || EPI == 4) v = fmaxf(v, 0.f);
            C[gm * N + gn] = v;
        }
    }
}

// ---------------- message-passing helpers ----------------

// message_atom[a] += sum_j(nei) * max_j(nei), nei = message_bond[a2b[a,j]]
__global__ void agg_update_kernel(const float* __restrict__ mbond, const int* __restrict__ a2b,
                                  float* __restrict__ matom)
{
    int idx = blockIdx.x * blockDim.x + threadIdx.x;
    if (idx >= NATOMS * HD) return;
    int a = idx / HD, h = idx - a * HD;
    float s = 0.f, mx = -INFINITY;
    #pragma unroll
    for (int j = 0; j < NNB; j++) {
        int b = __ldg(&a2b[a * NNB + j]);
        float v = __ldg(&mbond[b * HD + h]);
        s += v;
        mx = fmaxf(mx, v);
    }
    matom[idx] += s * mx;
}

// mb[b] = message_atom[b2a[b]] - message_bond[b2revb[b]]
__global__ void mb_kernel(const float* __restrict__ matom, const float* __restrict__ mbond,
                          const int* __restrict__ b2a, const int* __restrict__ b2revb,
                          float* __restrict__ mb)
{
    int idx = blockIdx.x * blockDim.x + threadIdx.x;
    if (idx >= NBONDS * HD) return;
    int b = idx / HD, h = idx - b * HD;
    mb[idx] = __ldg(&matom[__ldg(&b2a[b]) * HD + h]) - __ldg(&mbond[__ldg(&b2revb[b]) * HD + h]);
}

// concat[row] = [ sum*max(nei of atom row+1), message_atom[row+1], input_atom[row+1] ]
__global__ void final_concat_kernel(const float* __restrict__ mbond, const int* __restrict__ a2b,
                                    const float* __restrict__ matom, const float* __restrict__ iatom,
                                    float* __restrict__ cc)
{
    int idx = blockIdx.x * blockDim.x + threadIdx.x;
    if (idx >= NSEQ * HD) return;
    int row = idx / HD, h = idx - row * HD;
    int a = row + 1;
    float s = 0.f, mx = -INFINITY;
    #pragma unroll
    for (int j = 0; j < NNB; j++) {
        int b = __ldg(&a2b[a * NNB + j]);
        float v = __ldg(&mbond[b * HD + h]);
        s += v;
        mx = fmaxf(mx, v);
    }
    cc[row * (3 * HD) + h]            = s * mx;
    cc[row * (3 * HD) + HD + h]       = matom[a * HD + h];
    cc[row * (3 * HD) + 2 * HD + h]   = iatom[a * HD + h];
}

// msg = relu(aggW + gru_bias)
__global__ void msg_kernel(const float* __restrict__ aggW, const float* __restrict__ gbias,
                           float* __restrict__ msg)
{
    int idx = blockIdx.x * blockDim.x + threadIdx.x;
    if (idx >= NSEQ * HD) return;
    int h = idx % HD;
    msg[idx] = fmaxf(aggW[idx] + __ldg(&gbias[h]), 0.f);
}

// h0[mol] = max over t of aggW[mol*ASIZE + t]
__global__ void h0_kernel(const float* __restrict__ aggW, float* __restrict__ h0)
{
    int idx = blockIdx.x * blockDim.x + threadIdx.x;
    if (idx >= NMOLS * HD) return;
    int mol = idx / HD, h = idx - mol * HD;
    float mx = -INFINITY;
    for (int t = 0; t < ASIZE; t++)
        mx = fmaxf(mx, aggW[(mol * ASIZE + t) * HD + h]);
    h0[idx] = mx;
}

__global__ void copy4_kernel(const float4* __restrict__ src, float4* __restrict__ dst, int n4)
{
    int idx = blockIdx.x * blockDim.x + threadIdx.x;
    if (idx < n4) dst[idx] = src[idx];
}

__device__ __forceinline__ float sigmoidf_(float x) { return 1.f / (1.f + expf(-x)); }

// one GRU pointwise step: consumes xp slice at time t, gh = h@Whh^T + bhh, updates h, writes out
__global__ void gru_point_kernel(const float* __restrict__ xp, int t,
                                 const float* __restrict__ gh,
                                 float* __restrict__ h, float* __restrict__ out, int dir)
{
    int idx = blockIdx.x * blockDim.x + threadIdx.x;
    if (idx >= NMOLS * HD) return;
    int mol = idx / HD, hh = idx - mol * HD;
    int row = mol * ASIZE + t;
    float ir = xp[row * (3 * HD) + hh];
    float iz = xp[row * (3 * HD) + HD + hh];
    float in = xp[row * (3 * HD) + 2 * HD + hh];
    float hr = gh[mol * (3 * HD) + hh];
    float hz = gh[mol * (3 * HD) + HD + hh];
    float hn = gh[mol * (3 * HD) + 2 * HD + hh];
    float r = sigmoidf_(ir + hr);
    float z = sigmoidf_(iz + hz);
    float n = tanhf(in + r * hn);
    float hprev = h[idx];
    float hnew = (1.f - z) * n + z * hprev;
    h[idx] = hnew;
    out[row * (2 * HD) + dir * HD + hh] = hnew;
}

// mol_vecs[mol] = mean_t hid[mol*ASIZE + t]
__global__ void mean_kernel(const float* __restrict__ hid, float* __restrict__ out)
{
    int idx = blockIdx.x * blockDim.x + threadIdx.x;
    if (idx >= NMOLS * HD) return;
    int mol = idx / HD, h = idx - mol * HD;
    float s = 0.f;
    for (int t = 0; t < ASIZE; t++)
        s += hid[(mol * ASIZE + t) * HD + h];
    out[idx] = s * (1.f / ASIZE);
}

// ---------------- host orchestration ----------------
static inline dim3 gemm_grid(int M, int N) { return dim3((N + 63) / 64, (M + 63) / 64); }
static inline int  blocks_for(int n)       { return (n + 255) / 256; }

extern "C" void kernel_launch(void* const* d_in, const int* in_sizes, int n_in,
                              void* d_out, int out_size)
{
    const float* f_atoms  = (const float*)d_in[0];
    const float* f_bonds  = (const float*)d_in[1];
    const float* Wi_atom  = (const float*)d_in[2];
    const float* Wi_bond  = (const float*)d_in[3];
    const float* Wh0      = (const float*)d_in[4];
    const float* Wh1      = (const float*)d_in[5];
    const float* W_lr     = (const float*)d_in[6];
    const float* W_o      = (const float*)d_in[7];
    const float* b_o      = (const float*)d_in[8];
    const float* gru_bias = (const float*)d_in[9];
    const float* gWih_f   = (const float*)d_in[10];
    const float* gWhh_f   = (const float*)d_in[11];
    const float* gbih_f   = (const float*)d_in[12];
    const float* gbhh_f   = (const float*)d_in[13];
    const float* gWih_b   = (const float*)d_in[14];
    const float* gWhh_b   = (const float*)d_in[15];
    const float* gbih_b   = (const float*)d_in[16];
    const float* gbhh_b   = (const float*)d_in[17];
    const int*   a2b      = (const int*)d_in[18];
    const int*   b2a      = (const int*)d_in[19];
    const int*   b2revb   = (const int*)d_in[20];
    float* out = (float*)d_out;

    float *inA, *mA, *inB, *mB, *mb, *cc, *aggW, *msg, *xpf, *xpb, *h0, *h, *gh, *gout, *hid;
    cudaGetSymbolAddress((void**)&inA,  g_input_atom);
    cudaGetSymbolAddress((void**)&mA,   g_message_atom);
    cudaGetSymbolAddress((void**)&inB,  g_input_bond);
    cudaGetSymbolAddress((void**)&mB,   g_message_bond);
    cudaGetSymbolAddress((void**)&mb,   g_mb);
    cudaGetSymbolAddress((void**)&cc,   g_concat);
    cudaGetSymbolAddress((void**)&aggW, g_aggW);
    cudaGetSymbolAddress((void**)&msg,  g_msg);
    cudaGetSymbolAddress((void**)&xpf,  g_xpf);
    cudaGetSymbolAddress((void**)&xpb,  g_xpb);
    cudaGetSymbolAddress((void**)&h0,   g_h0);
    cudaGetSymbolAddress((void**)&h,    g_h);
    cudaGetSymbolAddress((void**)&gh,   g_gh);
    cudaGetSymbolAddress((void**)&gout, g_out);
    cudaGetSymbolAddress((void**)&hid,  g_hid);

    // 1. input_atom = relu(f_atoms @ Wi_atom); message_atom = input_atom
    sgemm_kernel<false, 1><<<gemm_grid(NATOMS, HD), 256>>>(f_atoms, Wi_atom, nullptr, nullptr, inA, NATOMS, HD, AFDIM);
    copy4_kernel<<<blocks_for(NATOMS * HD / 4), 256>>>((const float4*)inA, (float4*)mA, NATOMS * HD / 4);

    // 2. input_bond = relu(f_bonds @ Wi_bond); message_bond = input_bond
    sgemm_kernel<false, 1><<<gemm_grid(NBONDS, HD), 256>>>(f_bonds, Wi_bond, nullptr, nullptr, inB, NBONDS, HD, BFDIM);
    copy4_kernel<<<blocks_for(NBONDS * HD / 4), 256>>>((const float4*)inB, (float4*)mB, NBONDS * HD / 4);

    // 3. two message-passing steps
    const float* Whs[2] = { Wh0, Wh1 };
    for (int step = 0; step < 2; step++) {
        agg_update_kernel<<<blocks_for(NATOMS * HD), 256>>>(mB, a2b, mA);
        mb_kernel<<<blocks_for(NBONDS * HD), 256>>>(mA, mB, b2a, b2revb, mb);
        sgemm_kernel<false, 2><<<gemm_grid(NBONDS, HD), 256>>>(mb, Whs[step], inB, nullptr, mB, NBONDS, HD, HD);
    }

    // 4. final aggregation + concat + W_lr   (atom rows 1..NSEQ only; row 0 is unused downstream)
    final_concat_kernel<<<blocks_for(NSEQ * HD), 256>>>(mB, a2b, mA, inA, cc);
    sgemm_kernel<false, 0><<<gemm_grid(NSEQ, HD), 256>>>(cc, W_lr, nullptr, nullptr, aggW, NSEQ, HD, 3 * HD);

    // 5. BatchGRU prep
    msg_kernel<<<blocks_for(NSEQ * HD), 256>>>(aggW, gru_bias, msg);
    h0_kernel<<<blocks_for(NMOLS * HD), 256>>>(aggW, h0);

    // input projections for both directions: xp = msg @ Wih^T + bih
    sgemm_kernel<true, 3><<<gemm_grid(NSEQ, 3 * HD), 256>>>(msg, gWih_f, nullptr, gbih_f, xpf, NSEQ, 3 * HD, HD);
    sgemm_kernel<true, 3><<<gemm_grid(NSEQ, 3 * HD), 256>>>(msg, gWih_b, nullptr, gbih_b, xpb, NSEQ, 3 * HD, HD);

    // 6. forward GRU
    copy4_kernel<<<blocks_for(NMOLS * HD / 4), 256>>>((const float4*)h0, (float4*)h, NMOLS * HD / 4);
    for (int t = 0; t < ASIZE; t++) {
        sgemm_kernel<true, 3><<<gemm_grid(NMOLS, 3 * HD), 256>>>(h, gWhh_f, nullptr, gbhh_f, gh, NMOLS, 3 * HD, HD);
        gru_point_kernel<<<blocks_for(NMOLS * HD), 256>>>(xpf, t, gh, h, gout, 0);
    }

    // 7. backward GRU (iterate t = ASIZE-1 .. 0 over un-reversed buffers)
    copy4_kernel<<<blocks_for(NMOLS * HD / 4), 256>>>((const float4*)h0, (float4*)h, NMOLS * HD / 4);
    for (int t = ASIZE - 1; t >= 0; t--) {
        sgemm_kernel<true, 3><<<gemm_grid(NMOLS, 3 * HD), 256>>>(h, gWhh_b, nullptr, gbhh_b, gh, NMOLS, 3 * HD, HD);
        gru_point_kernel<<<blocks_for(NMOLS * HD), 256>>>(xpb, t, gh, h, gout, 1);
    }

    // 8. atom_hiddens = relu(out @ W_o + b_o);  mol_vecs = per-mol mean
    sgemm_kernel<false, 4><<<gemm_grid(NSEQ, HD), 256>>>(gout, W_o, nullptr, b_o, hid, NSEQ, HD, 2 * HD);
    mean_kernel<<<blocks_for(NMOLS * HD), 256>>>(hid, out);
}

// round 5
// speedup vs baseline: 1.2547x; 1.2547x over previous
#include <cuda_runtime.h>
#include <math.h>
#include <stdint.h>

#define NATOMS 40001
#define NBONDS 160001
#define NNB    6
#define AFDIM  133
#define BFDIM  147
#define HD     300
#define NMOLS  1000
#define ASIZE  40
#define NSEQ   (NMOLS * ASIZE)   /* 40000 */

// ---------------- scratch (static device globals; no runtime allocation) ----------------
__device__ float g_input_atom  [NATOMS * HD];
__device__ float g_message_atom[NATOMS * HD];
__device__ float g_input_bond  [NBONDS * HD];
__device__ float g_message_bond[NBONDS * HD];
__device__ float g_mb          [NBONDS * HD];
__device__ float g_concat      [NSEQ * 3 * HD];
__device__ float g_aggW        [NSEQ * HD];
__device__ float g_msg         [NSEQ * HD];
__device__ float g_xpf         [NSEQ * 3 * HD];
__device__ float g_xpb         [NSEQ * 3 * HD];
__device__ float g_h0          [NMOLS * HD];
__device__ float g_out         [NSEQ * 2 * HD];
__device__ float g_hid         [NSEQ * HD];

// ======================= 3xTF32 split-precision tensor-core GEMM =======================
// C[M,N] = epi(A[M,K] @ B)   B row-major [K,N]; TRANSB: B is W[N,K] row-major.
// Each fp32 value is split x = x_hi(tf32) + x_lo(tf32); products computed as
// hi*hi + hi*lo + lo*hi with fp32 accumulation -> ~fp32 accuracy (error ~2^-23).
// EPI: 0 none, 1 relu, 2 relu(acc+ADD), 3 acc+bias, 4 relu(acc+bias)
// DUAL: also store result to C2.
// Block tile 128x64, 256 threads = 8 warps (4m x 2n), warp tile 32x32, K-chunk 16.

__device__ __forceinline__ void mma_tf32(float c[4], const uint32_t a[4], const uint32_t b[2]) {
    asm volatile(
        "mma.sync.aligned.m16n8k8.row.col.f32.tf32.tf32.f32 "
        "{%0,%1,%2,%3}, {%4,%5,%6,%7}, {%8,%9}, {%0,%1,%2,%3};"
        : "+f"(c[0]), "+f"(c[1]), "+f"(c[2]), "+f"(c[3])
        : "r"(a[0]), "r"(a[1]), "r"(a[2]), "r"(a[3]), "r"(b[0]), "r"(b[1]));
}

__device__ __forceinline__ float f2tf32(float v) {
    uint32_t t;
    asm("cvt.rna.tf32.f32 %0, %1;" : "=r"(t) : "f"(v));
    return __uint_as_float(t);
}

template<bool TRANSB, int EPI, bool DUAL>
__global__ __launch_bounds__(256)
void mma_gemm(const float* __restrict__ A, const float* __restrict__ B,
              const float* __restrict__ ADD, const float* __restrict__ bias,
              float* __restrict__ C, float* __restrict__ C2, int M, int N, int K)
{
    __shared__ float Ah[128][20], Al[128][20];   // [m][k]
    __shared__ float Bh[16][68],  Bl[16][68];    // [k][n]

    const int tid  = threadIdx.x;
    const int warp = tid >> 5, lane = tid & 31;
    const int wm   = warp & 3, wn = warp >> 2;
    const int gid  = lane >> 2, tig = lane & 3;
    const int bM   = blockIdx.y * 128, bN = blockIdx.x * 64;

    const int aRow = tid >> 2;
    const int aCol = (tid & 3) * 4;

    float aR[8], bR[4];
    float c[2][4][4] = {};

    const int nCh = (K + 15) >> 4;

    // ---- load chunk 0 ----
    {
        #pragma unroll
        for (int r = 0; r < 2; r++)
            #pragma unroll
            for (int i = 0; i < 4; i++) {
                int gm = bM + aRow + 64 * r, gk = aCol + i;
                aR[r*4+i] = (gm < M && gk < K) ? A[(size_t)gm * K + gk] : 0.f;
            }
        if (!TRANSB) {
            int k = tid >> 4, n0 = (tid & 15) * 4;
            #pragma unroll
            for (int i = 0; i < 4; i++) {
                int gn = bN + n0 + i;
                bR[i] = (k < K && gn < N) ? B[(size_t)k * N + gn] : 0.f;
            }
        } else {
            int n = tid >> 2, k0 = (tid & 3) * 4;
            #pragma unroll
            for (int i = 0; i < 4; i++) {
                int gk = k0 + i, gn = bN + n;
                bR[i] = (gk < K && gn < N) ? B[(size_t)gn * K + gk] : 0.f;
            }
        }
    }

    for (int ch = 0; ch < nCh; ch++) {
        // ---- STS with hi/lo split ----
        #pragma unroll
        for (int r = 0; r < 2; r++) {
            float4 h, l;
            float v0 = aR[r*4+0], v1 = aR[r*4+1], v2 = aR[r*4+2], v3 = aR[r*4+3];
            h = make_float4(f2tf32(v0), f2tf32(v1), f2tf32(v2), f2tf32(v3));
            l = make_float4(f2tf32(v0 - h.x), f2tf32(v1 - h.y), f2tf32(v2 - h.z), f2tf32(v3 - h.w));
            *(float4*)&Ah[aRow + 64*r][aCol] = h;
            *(float4*)&Al[aRow + 64*r][aCol] = l;
        }
        if (!TRANSB) {
            int k = tid >> 4, n0 = (tid & 15) * 4;
            float4 h = make_float4(f2tf32(bR[0]), f2tf32(bR[1]), f2tf32(bR[2]), f2tf32(bR[3]));
            float4 l = make_float4(f2tf32(bR[0] - h.x), f2tf32(bR[1] - h.y),
                                   f2tf32(bR[2] - h.z), f2tf32(bR[3] - h.w));
            *(float4*)&Bh[k][n0] = h;
            *(float4*)&Bl[k][n0] = l;
        } else {
            int n = tid >> 2, k0 = (tid & 3) * 4;
            #pragma unroll
            for (int i = 0; i < 4; i++) {
                float h = f2tf32(bR[i]);
                Bh[k0 + i][n] = h;
                Bl[k0 + i][n] = f2tf32(bR[i] - h);
            }
        }
        __syncthreads();

        // ---- prefetch next chunk ----
        if (ch + 1 < nCh) {
            int kt = (ch + 1) << 4;
            #pragma unroll
            for (int r = 0; r < 2; r++)
                #pragma unroll
                for (int i = 0; i < 4; i++) {
                    int gm = bM + aRow + 64 * r, gk = kt + aCol + i;
                    aR[r*4+i] = (gm < M && gk < K) ? A[(size_t)gm * K + gk] : 0.f;
                }
            if (!TRANSB) {
                int k = tid >> 4, n0 = (tid & 15) * 4;
                #pragma unroll
                for (int i = 0; i < 4; i++) {
                    int gk = kt + k, gn = bN + n0 + i;
                    bR[i] = (gk < K && gn < N) ? B[(size_t)gk * N + gn] : 0.f;
                }
            } else {
                int n = tid >> 2, k0 = (tid & 3) * 4;
                #pragma unroll
                for (int i = 0; i < 4; i++) {
                    int gk = kt + k0 + i, gn = bN + n;
                    bR[i] = (gk < K && gn < N) ? B[(size_t)gn * K + gk] : 0.f;
                }
            }
        }

        // ---- compute chunk: 3 mma per (mt,nt) per k8 ----
        #pragma unroll
        for (int kk = 0; kk < 16; kk += 8) {
            uint32_t ah[2][4], al[2][4], bh_[4][2], bl_[4][2];
            #pragma unroll
            for (int mt = 0; mt < 2; mt++) {
                int m0 = wm * 32 + mt * 16 + gid;
                ah[mt][0] = __float_as_uint(Ah[m0    ][kk + tig]);
                ah[mt][1] = __float_as_uint(Ah[m0 + 8][kk + tig]);
                ah[mt][2] = __float_as_uint(Ah[m0    ][kk + tig + 4]);
                ah[mt][3] = __float_as_uint(Ah[m0 + 8][kk + tig + 4]);
                al[mt][0] = __float_as_uint(Al[m0    ][kk + tig]);
                al[mt][1] = __float_as_uint(Al[m0 + 8][kk + tig]);
                al[mt][2] = __float_as_uint(Al[m0    ][kk + tig + 4]);
                al[mt][3] = __float_as_uint(Al[m0 + 8][kk + tig + 4]);
            }
            #pragma unroll
            for (int nt = 0; nt < 4; nt++) {
                int n0 = wn * 32 + nt * 8 + gid;
                bh_[nt][0] = __float_as_uint(Bh[kk + tig    ][n0]);
                bh_[nt][1] = __float_as_uint(Bh[kk + tig + 4][n0]);
                bl_[nt][0] = __float_as_uint(Bl[kk + tig    ][n0]);
                bl_[nt][1] = __float_as_uint(Bl[kk + tig + 4][n0]);
            }
            #pragma unroll
            for (int mt = 0; mt < 2; mt++)
                #pragma unroll
                for (int nt = 0; nt < 4; nt++) {
                    mma_tf32(c[mt][nt], ah[mt], bl_[nt]);   // hi*lo
                    mma_tf32(c[mt][nt], al[mt], bh_[nt]);   // lo*hi
                    mma_tf32(c[mt][nt], ah[mt], bh_[nt]);   // hi*hi
                }
        }
        __syncthreads();
    }

    // ---- epilogue ----
    #pragma unroll
    for (int mt = 0; mt < 2; mt++)
        #pragma unroll
        for (int nt = 0; nt < 4; nt++)
            #pragma unroll
            for (int e = 0; e < 4; e++) {
                int row = bM + wm * 32 + mt * 16 + gid + ((e >= 2) ? 8 : 0);
                int col = bN + wn * 32 + nt * 8 + tig * 2 + (e & 1);
                if (row < M && col < N) {
                    float v = c[mt][nt][e];
                    if (EPI == 2)             v += ADD[(size_t)row * N + col];
                    if (EPI == 3 || EPI == 4) v += bias[col];
                    if (EPI == 1 || EPI == 2 || EPI == 4) v = fmaxf(v, 0.f);
                    C[(size_t)row * N + col] = v;
                    if (DUAL) C2[(size_t)row * N + col] = v;
                }
            }
}

// ======================= message-passing helpers =======================

__global__ void agg_update_kernel(const float* __restrict__ mbond, const int* __restrict__ a2b,
                                  float* __restrict__ matom)
{
    int idx = blockIdx.x * blockDim.x + threadIdx.x;
    if (idx >= NATOMS * HD) return;
    int a = idx / HD, h = idx - a * HD;
    float s = 0.f, mx = -INFINITY;
    #pragma unroll
    for (int j = 0; j < NNB; j++) {
        int b = __ldg(&a2b[a * NNB + j]);
        float v = __ldg(&mbond[b * HD + h]);
        s += v; mx = fmaxf(mx, v);
    }
    matom[idx] += s * mx;
}

__global__ void mb_kernel(const float* __restrict__ matom, const float* __restrict__ mbond,
                          const int* __restrict__ b2a, const int* __restrict__ b2revb,
                          float* __restrict__ mb)
{
    int idx = blockIdx.x * blockDim.x + threadIdx.x;
    if (idx >= NBONDS * HD) return;
    int b = idx / HD, h = idx - b * HD;
    mb[idx] = __ldg(&matom[__ldg(&b2a[b]) * HD + h]) - __ldg(&mbond[__ldg(&b2revb[b]) * HD + h]);
}

__global__ void final_concat_kernel(const float* __restrict__ mbond, const int* __restrict__ a2b,
                                    const float* __restrict__ matom, const float* __restrict__ iatom,
                                    float* __restrict__ cc)
{
    int idx = blockIdx.x * blockDim.x + threadIdx.x;
    if (idx >= NSEQ * HD) return;
    int row = idx / HD, h = idx - row * HD;
    int a = row + 1;
    float s = 0.f, mx = -INFINITY;
    #pragma unroll
    for (int j = 0; j < NNB; j++) {
        int b = __ldg(&a2b[a * NNB + j]);
        float v = __ldg(&mbond[b * HD + h]);
        s += v; mx = fmaxf(mx, v);
    }
    cc[row * (3*HD) + h]          = s * mx;
    cc[row * (3*HD) + HD + h]     = matom[a * HD + h];
    cc[row * (3*HD) + 2*HD + h]   = iatom[a * HD + h];
}

__global__ void msg_kernel(const float* __restrict__ aggW, const float* __restrict__ gbias,
                           float* __restrict__ msg)
{
    int idx = blockIdx.x * blockDim.x + threadIdx.x;
    if (idx >= NSEQ * HD) return;
    int h = idx % HD;
    msg[idx] = fmaxf(aggW[idx] + __ldg(&gbias[h]), 0.f);
}

__global__ void h0_kernel(const float* __restrict__ aggW, float* __restrict__ h0)
{
    int idx = blockIdx.x * blockDim.x + threadIdx.x;
    if (idx >= NMOLS * HD) return;
    int mol = idx / HD, h = idx - mol * HD;
    float mx = -INFINITY;
    for (int t = 0; t < ASIZE; t++)
        mx = fmaxf(mx, aggW[(mol * ASIZE + t) * HD + h]);
    h0[idx] = mx;
}

__global__ void mean_kernel(const float* __restrict__ hid, float* __restrict__ out)
{
    int idx = blockIdx.x * blockDim.x + threadIdx.x;
    if (idx >= NMOLS * HD) return;
    int mol = idx / HD, h = idx - mol * HD;
    float s = 0.f;
    for (int t = 0; t < ASIZE; t++)
        s += hid[(mol * ASIZE + t) * HD + h];
    out[idx] = s * (1.f / ASIZE);
}

// ======================= fused bidirectional GRU (fp32, verified) =======================
#define MPB 16

__device__ __forceinline__ float sigmoidf_(float x) { return 1.f / (1.f + expf(-x)); }

__global__ __launch_bounds__(256)
void gru_fused(const float* __restrict__ xp_f, const float* __restrict__ xp_b,
               const float* __restrict__ Whh_f, const float* __restrict__ Whh_b,  // [3H, H]
               const float* __restrict__ bhh_f, const float* __restrict__ bhh_b,
               const float* __restrict__ h0, float* __restrict__ out)
{
    extern __shared__ float sm[];
    float* h_s  = sm;               // [MPB][304]
    float* gh_s = sm + MPB * 304;   // [MPB][912]

    const int tid  = threadIdx.x;
    const int dir  = blockIdx.y;
    const int mol0 = blockIdx.x * MPB;
    const int mc   = min(MPB, NMOLS - mol0);

    const float* xp  = dir ? xp_b  : xp_f;
    const float* Whh = dir ? Whh_b : Whh_f;
    const float* bhh = dir ? bhh_b : bhh_f;

    for (int i = tid; i < MPB * 304; i += 256) h_s[i] = 0.f;
    __syncthreads();
    for (int i = tid; i < mc * HD; i += 256) {
        int m = i / HD, hh = i - m * HD;
        h_s[m * 304 + hh] = h0[(mol0 + m) * HD + hh];
    }
    __syncthreads();

    const int c3ok = (tid + 768 < 3 * HD);

    for (int s = 0; s < ASIZE; s++) {
        const int t = dir ? (ASIZE - 1 - s) : s;

        float acc[4][MPB];
        #pragma unroll
        for (int j = 0; j < 4; j++)
            #pragma unroll
            for (int m = 0; m < MPB; m++) acc[j][m] = 0.f;

        for (int k = 0; k < HD; k += 4) {
            float4 w[4];
            #pragma unroll
            for (int j = 0; j < 3; j++)
                w[j] = *(const float4*)&Whh[(tid + j * 256) * HD + k];
            w[3] = c3ok ? *(const float4*)&Whh[(tid + 768) * HD + k]
                        : make_float4(0.f, 0.f, 0.f, 0.f);
            #pragma unroll
            for (int m = 0; m < MPB; m++) {
                float4 hv = *(const float4*)&h_s[m * 304 + k];
                #pragma unroll
                for (int j = 0; j < 4; j++) {
                    acc[j][m] = fmaf(w[j].x, hv.x, acc[j][m]);
                    acc[j][m] = fmaf(w[j].y, hv.y, acc[j][m]);
                    acc[j][m] = fmaf(w[j].z, hv.z, acc[j][m]);
                    acc[j][m] = fmaf(w[j].w, hv.w, acc[j][m]);
                }
            }
        }
        #pragma unroll
        for (int j = 0; j < 4; j++) {
            int cc = tid + j * 256;
            if (cc < 3 * HD) {
                float bb = bhh[cc];
                #pragma unroll
                for (int m = 0; m < MPB; m++)
                    gh_s[m * 912 + cc] = acc[j][m] + bb;
            }
        }
        __syncthreads();

        for (int i = tid; i < mc * HD; i += 256) {
            int m = i / HD, hh = i - m * HD;
            int row = (mol0 + m) * ASIZE + t;
            float ir = xp[row * (3*HD) + hh];
            float iz = xp[row * (3*HD) + HD + hh];
            float in = xp[row * (3*HD) + 2*HD + hh];
            float hr = gh_s[m * 912 + hh];
            float hz = gh_s[m * 912 + HD + hh];
            float hn = gh_s[m * 912 + 2*HD + hh];
            float r = sigmoidf_(ir + hr);
            float z = sigmoidf_(iz + hz);
            float n = tanhf(in + r * hn);
            float hp = h_s[m * 304 + hh];
            float hnew = (1.f - z) * n + z * hp;
            h_s[m * 304 + hh] = hnew;
            out[row * (2*HD) + dir * HD + hh] = hnew;
        }
        __syncthreads();
    }
}

// ======================= host orchestration =======================
static inline dim3 mma_grid(int M, int N) { return dim3((N + 63) / 64, (M + 127) / 128); }
static inline int  blocks_for(int n)      { return (n + 255) / 256; }

extern "C" void kernel_launch(void* const* d_in, const int* in_sizes, int n_in,
                              void* d_out, int out_size)
{
    const float* f_atoms  = (const float*)d_in[0];
    const float* f_bonds  = (const float*)d_in[1];
    const float* Wi_atom  = (const float*)d_in[2];
    const float* Wi_bond  = (const float*)d_in[3];
    const float* Wh0      = (const float*)d_in[4];
    const float* Wh1      = (const float*)d_in[5];
    const float* W_lr     = (const float*)d_in[6];
    const float* W_o      = (const float*)d_in[7];
    const float* b_o      = (const float*)d_in[8];
    const float* gru_bias = (const float*)d_in[9];
    const float* gWih_f   = (const float*)d_in[10];
    const float* gWhh_f   = (const float*)d_in[11];
    const float* gbih_f   = (const float*)d_in[12];
    const float* gbhh_f   = (const float*)d_in[13];
    const float* gWih_b   = (const float*)d_in[14];
    const float* gWhh_b   = (const float*)d_in[15];
    const float* gbih_b   = (const float*)d_in[16];
    const float* gbhh_b   = (const float*)d_in[17];
    const int*   a2b      = (const int*)d_in[18];
    const int*   b2a      = (const int*)d_in[19];
    const int*   b2revb   = (const int*)d_in[20];
    float* out = (float*)d_out;

    float *inA, *mA, *inB, *mB, *mb, *cc, *aggW, *msg, *xpf, *xpb, *h0, *gout, *hid;
    cudaGetSymbolAddress((void**)&inA,  g_input_atom);
    cudaGetSymbolAddress((void**)&mA,   g_message_atom);
    cudaGetSymbolAddress((void**)&inB,  g_input_bond);
    cudaGetSymbolAddress((void**)&mB,   g_message_bond);
    cudaGetSymbolAddress((void**)&mb,   g_mb);
    cudaGetSymbolAddress((void**)&cc,   g_concat);
    cudaGetSymbolAddress((void**)&aggW, g_aggW);
    cudaGetSymbolAddress((void**)&msg,  g_msg);
    cudaGetSymbolAddress((void**)&xpf,  g_xpf);
    cudaGetSymbolAddress((void**)&xpb,  g_xpb);
    cudaGetSymbolAddress((void**)&h0,   g_h0);
    cudaGetSymbolAddress((void**)&gout, g_out);
    cudaGetSymbolAddress((void**)&hid,  g_hid);

    const int gru_smem = (MPB * 304 + MPB * 912) * (int)sizeof(float);  // 77,824 B
    cudaFuncSetAttribute(gru_fused, cudaFuncAttributeMaxDynamicSharedMemorySize, gru_smem);

    // 1. input_atom = relu(f_atoms @ Wi_atom); dual-store into message_atom
    mma_gemm<false, 1, true><<<mma_grid(NATOMS, HD), 256>>>(f_atoms, Wi_atom, nullptr, nullptr, inA, mA, NATOMS, HD, AFDIM);

    // 2. input_bond = relu(f_bonds @ Wi_bond); dual-store into message_bond
    mma_gemm<false, 1, true><<<mma_grid(NBONDS, HD), 256>>>(f_bonds, Wi_bond, nullptr, nullptr, inB, mB, NBONDS, HD, BFDIM);

    // 3. two message-passing steps
    const float* Whs[2] = { Wh0, Wh1 };
    for (int step = 0; step < 2; step++) {
        agg_update_kernel<<<blocks_for(NATOMS * HD), 256>>>(mB, a2b, mA);
        mb_kernel<<<blocks_for(NBONDS * HD), 256>>>(mA, mB, b2a, b2revb, mb);
        mma_gemm<false, 2, false><<<mma_grid(NBONDS, HD), 256>>>(mb, Whs[step], inB, nullptr, mB, nullptr, NBONDS, HD, HD);
    }

    // 4. final aggregation + concat + W_lr  (atom rows 1..NSEQ; row 0 unused downstream)
    final_concat_kernel<<<blocks_for(NSEQ * HD), 256>>>(mB, a2b, mA, inA, cc);
    mma_gemm<false, 0, false><<<mma_grid(NSEQ, HD), 256>>>(cc, W_lr, nullptr, nullptr, aggW, nullptr, NSEQ, HD, 3 * HD);

    // 5. BatchGRU prep
    msg_kernel<<<blocks_for(NSEQ * HD), 256>>>(aggW, gru_bias, msg);
    h0_kernel<<<blocks_for(NMOLS * HD), 256>>>(aggW, h0);

    // input projections: xp = msg @ Wih^T + bih
    mma_gemm<true, 3, false><<<mma_grid(NSEQ, 3 * HD), 256>>>(msg, gWih_f, nullptr, gbih_f, xpf, nullptr, NSEQ, 3 * HD, HD);
    mma_gemm<true, 3, false><<<mma_grid(NSEQ, 3 * HD), 256>>>(msg, gWih_b, nullptr, gbih_b, xpb, nullptr, NSEQ, 3 * HD, HD);

    // 6+7. both GRU directions, all 40 steps, one kernel
    {
        dim3 grid((NMOLS + MPB - 1) / MPB, 2);
        gru_fused<<<grid, 256, gru_smem>>>(xpf, xpb, gWhh_f, gWhh_b, gbhh_f, gbhh_b, h0, gout);
    }

    // 8. atom_hiddens = relu(out @ W_o + b_o); mol_vecs = per-mol mean
    mma_gemm<false, 4, false><<<mma_grid(NSEQ, HD), 256>>>(gout, W_o, nullptr, b_o, hid, nullptr, NSEQ, HD, 2 * HD);
    mean_kernel<<<blocks_for(NMOLS * HD), 256>>>(hid, out);
}

// round 7
// speedup vs baseline: 1.4283x; 1.1384x over previous
#include <cuda_runtime.h>
#include <math.h>
#include <stdint.h>

#define NATOMS 40001
#define NBONDS 160001
#define NNB    6
#define AFDIM  133
#define BFDIM  147
#define HD     300
#define NMOLS  1000
#define ASIZE  40
#define NSEQ   (NMOLS * ASIZE)   /* 40000 */

// ---------------- scratch (static device globals; no runtime allocation) ----------------
__device__ float g_input_atom  [NATOMS * HD];
__device__ float g_message_atom[NATOMS * HD];
__device__ float g_input_bond  [NBONDS * HD];
__device__ float g_bondA       [NBONDS * HD];   // bond-message ping
__device__ float g_bondB       [NBONDS * HD];   // bond-message pong
__device__ float g_concat      [NSEQ * 3 * HD];
__device__ float g_aggW        [NSEQ * HD];
__device__ float g_msg         [NSEQ * HD];
__device__ float g_xpf         [NSEQ * 3 * HD];
__device__ float g_xpb         [NSEQ * 3 * HD];
__device__ float g_h0          [NMOLS * HD];
__device__ float g_out         [NSEQ * 2 * HD];
__device__ float g_hid         [NSEQ * HD];

// ======================= 3xTF32 split-precision tensor-core GEMM =======================
// C[M,N] = epi(A' @ B);  A' = A[M,K]  or (GATHER) A'[m] = GA[idxA[m]] - GB[idxB[m]].
// GATHER REQUIRES C to not alias GA/GB (ping-pong buffers at call site!).
// B row-major [K,N]; TRANSB: B is W[N,K] row-major.
// x = x_hi(tf32) + x_lo(tf32); hi*hi + hi*lo + lo*hi with fp32 accum (~fp32 accuracy).
// EPI: 0 none, 1 relu, 2 relu(acc+ADD), 3 acc+bias, 4 relu(acc+bias). DUAL: also store C2.
// Block tile 128x64, 256 threads = 8 warps (4m x 2n), warp tile 32x32, K-chunk 16.

__device__ __forceinline__ void mma_tf32(float c[4], const uint32_t a[4], const uint32_t b[2]) {
    asm volatile(
        "mma.sync.aligned.m16n8k8.row.col.f32.tf32.tf32.f32 "
        "{%0,%1,%2,%3}, {%4,%5,%6,%7}, {%8,%9}, {%0,%1,%2,%3};"
        : "+f"(c[0]), "+f"(c[1]), "+f"(c[2]), "+f"(c[3])
        : "r"(a[0]), "r"(a[1]), "r"(a[2]), "r"(a[3]), "r"(b[0]), "r"(b[1]));
}

__device__ __forceinline__ float f2tf32(float v) {
    uint32_t t;
    asm("cvt.rna.tf32.f32 %0, %1;" : "=r"(t) : "f"(v));
    return __uint_as_float(t);
}

template<bool TRANSB, int EPI, bool DUAL, bool GATHER>
__global__ __launch_bounds__(256)
void mma_gemm(const float* __restrict__ A, const float* __restrict__ B,
              const float* __restrict__ ADD, const float* __restrict__ bias,
              float* __restrict__ C, float* __restrict__ C2,
              const int* __restrict__ idxA, const int* __restrict__ idxB,
              const float* __restrict__ GA, const float* __restrict__ GB,
              int M, int N, int K)
{
    __shared__ float Ah[128][20], Al[128][20];   // [m][k]
    __shared__ float Bh[16][68],  Bl[16][68];    // [k][n]

    const int tid  = threadIdx.x;
    const int warp = tid >> 5, lane = tid & 31;
    const int wm   = warp & 3, wn = warp >> 2;
    const int gid  = lane >> 2, tig = lane & 3;
    const int bM   = blockIdx.y * 128, bN = blockIdx.x * 64;

    const int aRow = tid >> 2;
    const int aCol = (tid & 3) * 4;

    float aR[8], bR[4];
    float c[2][4][4] = {};

    const int nCh = (K + 15) >> 4;

    auto loadA = [&](int kt) {
        #pragma unroll
        for (int r = 0; r < 2; r++) {
            int gm  = bM + aRow + 64 * r;
            int gk0 = kt + aCol;
            if (GATHER) {
                if (gm < M) {
                    int ia = __ldg(&idxA[gm]);
                    int ib = __ldg(&idxB[gm]);
                    if (gk0 + 3 < K) {   // rows are 16B aligned (HD*4 % 16 == 0)
                        float4 va = __ldg((const float4*)&GA[(size_t)ia * K + gk0]);
                        float4 vb = __ldg((const float4*)&GB[(size_t)ib * K + gk0]);
                        aR[r*4+0] = va.x - vb.x; aR[r*4+1] = va.y - vb.y;
                        aR[r*4+2] = va.z - vb.z; aR[r*4+3] = va.w - vb.w;
                    } else {
                        #pragma unroll
                        for (int i = 0; i < 4; i++) {
                            int gk = gk0 + i;
                            aR[r*4+i] = (gk < K)
                                ? __ldg(&GA[(size_t)ia * K + gk]) - __ldg(&GB[(size_t)ib * K + gk])
                                : 0.f;
                        }
                    }
                } else {
                    #pragma unroll
                    for (int i = 0; i < 4; i++) aR[r*4+i] = 0.f;
                }
            } else {
                #pragma unroll
                for (int i = 0; i < 4; i++) {
                    int gk = gk0 + i;
                    aR[r*4+i] = (gm < M && gk < K) ? A[(size_t)gm * K + gk] : 0.f;
                }
            }
        }
    };
    auto loadB = [&](int kt) {
        if (!TRANSB) {
            int k = tid >> 4, n0 = (tid & 15) * 4;
            #pragma unroll
            for (int i = 0; i < 4; i++) {
                int gk = kt + k, gn = bN + n0 + i;
                bR[i] = (gk < K && gn < N) ? B[(size_t)gk * N + gn] : 0.f;
            }
        } else {
            int n = tid >> 2, k0 = (tid & 3) * 4;
            #pragma unroll
            for (int i = 0; i < 4; i++) {
                int gk = kt + k0 + i, gn = bN + n;
                bR[i] = (gk < K && gn < N) ? B[(size_t)gn * K + gk] : 0.f;
            }
        }
    };

    loadA(0);
    loadB(0);

    for (int ch = 0; ch < nCh; ch++) {
        // ---- STS with hi/lo split ----
        #pragma unroll
        for (int r = 0; r < 2; r++) {
            float v0 = aR[r*4+0], v1 = aR[r*4+1], v2 = aR[r*4+2], v3 = aR[r*4+3];
            float4 h = make_float4(f2tf32(v0), f2tf32(v1), f2tf32(v2), f2tf32(v3));
            float4 l = make_float4(f2tf32(v0 - h.x), f2tf32(v1 - h.y),
                                   f2tf32(v2 - h.z), f2tf32(v3 - h.w));
            *(float4*)&Ah[aRow + 64*r][aCol] = h;
            *(float4*)&Al[aRow + 64*r][aCol] = l;
        }
        if (!TRANSB) {
            int k = tid >> 4, n0 = (tid & 15) * 4;
            float4 h = make_float4(f2tf32(bR[0]), f2tf32(bR[1]), f2tf32(bR[2]), f2tf32(bR[3]));
            float4 l = make_float4(f2tf32(bR[0] - h.x), f2tf32(bR[1] - h.y),
                                   f2tf32(bR[2] - h.z), f2tf32(bR[3] - h.w));
            *(float4*)&Bh[k][n0] = h;
            *(float4*)&Bl[k][n0] = l;
        } else {
            int n = tid >> 2, k0 = (tid & 3) * 4;
            #pragma unroll
            for (int i = 0; i < 4; i++) {
                float h = f2tf32(bR[i]);
                Bh[k0 + i][n] = h;
                Bl[k0 + i][n] = f2tf32(bR[i] - h);
            }
        }
        __syncthreads();

        if (ch + 1 < nCh) {
            loadA((ch + 1) << 4);
            loadB((ch + 1) << 4);
        }

        // ---- compute chunk: 3 mma per (mt,nt) per k8 ----
        #pragma unroll
        for (int kk = 0; kk < 16; kk += 8) {
            uint32_t ah[2][4], al[2][4], bh_[4][2], bl_[4][2];
            #pragma unroll
            for (int mt = 0; mt < 2; mt++) {
                int m0 = wm * 32 + mt * 16 + gid;
                ah[mt][0] = __float_as_uint(Ah[m0    ][kk + tig]);
                ah[mt][1] = __float_as_uint(Ah[m0 + 8][kk + tig]);
                ah[mt][2] = __float_as_uint(Ah[m0    ][kk + tig + 4]);
                ah[mt][3] = __float_as_uint(Ah[m0 + 8][kk + tig + 4]);
                al[mt][0] = __float_as_uint(Al[m0    ][kk + tig]);
                al[mt][1] = __float_as_uint(Al[m0 + 8][kk + tig]);
                al[mt][2] = __float_as_uint(Al[m0    ][kk + tig + 4]);
                al[mt][3] = __float_as_uint(Al[m0 + 8][kk + tig + 4]);
            }
            #pragma unroll
            for (int nt = 0; nt < 4; nt++) {
                int n0 = wn * 32 + nt * 8 + gid;
                bh_[nt][0] = __float_as_uint(Bh[kk + tig    ][n0]);
                bh_[nt][1] = __float_as_uint(Bh[kk + tig + 4][n0]);
                bl_[nt][0] = __float_as_uint(Bl[kk + tig    ][n0]);
                bl_[nt][1] = __float_as_uint(Bl[kk + tig + 4][n0]);
            }
            #pragma unroll
            for (int mt = 0; mt < 2; mt++)
                #pragma unroll
                for (int nt = 0; nt < 4; nt++) {
                    mma_tf32(c[mt][nt], ah[mt], bl_[nt]);
                    mma_tf32(c[mt][nt], al[mt], bh_[nt]);
                    mma_tf32(c[mt][nt], ah[mt], bh_[nt]);
                }
        }
        __syncthreads();
    }

    // ---- epilogue ----
    #pragma unroll
    for (int mt = 0; mt < 2; mt++)
        #pragma unroll
        for (int nt = 0; nt < 4; nt++)
            #pragma unroll
            for (int e = 0; e < 4; e++) {
                int row = bM + wm * 32 + mt * 16 + gid + ((e >= 2) ? 8 : 0);
                int col = bN + wn * 32 + nt * 8 + tig * 2 + (e & 1);
                if (row < M && col < N) {
                    float v = c[mt][nt][e];
                    if (EPI == 2)             v += ADD[(size_t)row * N + col];
                    if (EPI == 3 || EPI == 4) v += bias[col];
                    if (EPI == 1 || EPI == 2 || EPI == 4) v = fmaxf(v, 0.f);
                    C[(size_t)row * N + col] = v;
                    if (DUAL) C2[(size_t)row * N + col] = v;
                }
            }
}

// ======================= float4 gather/pointwise helpers =======================
#define HD4 (HD / 4)   /* 75 */

__device__ __forceinline__ float4 f4max(float4 a, float4 b) {
    return make_float4(fmaxf(a.x,b.x), fmaxf(a.y,b.y), fmaxf(a.z,b.z), fmaxf(a.w,b.w));
}
__device__ __forceinline__ float4 f4add(float4 a, float4 b) {
    return make_float4(a.x+b.x, a.y+b.y, a.z+b.z, a.w+b.w);
}

__global__ void agg_update_kernel(const float* __restrict__ mbond, const int* __restrict__ a2b,
                                  float* __restrict__ matom)
{
    int idx = blockIdx.x * blockDim.x + threadIdx.x;
    if (idx >= NATOMS * HD4) return;
    int a = idx / HD4, h4 = idx - a * HD4;
    float4 s  = make_float4(0.f, 0.f, 0.f, 0.f);
    float4 mx = make_float4(-INFINITY, -INFINITY, -INFINITY, -INFINITY);
    #pragma unroll
    for (int j = 0; j < NNB; j++) {
        int b = __ldg(&a2b[a * NNB + j]);
        float4 v = __ldg((const float4*)&mbond[b * HD] + h4);
        s = f4add(s, v); mx = f4max(mx, v);
    }
    float4* dst = (float4*)&matom[a * HD] + h4;
    float4 cur = *dst;
    cur.x += s.x * mx.x; cur.y += s.y * mx.y; cur.z += s.z * mx.z; cur.w += s.w * mx.w;
    *dst = cur;
}

__global__ void final_concat_kernel(const float* __restrict__ mbond, const int* __restrict__ a2b,
                                    const float* __restrict__ matom, const float* __restrict__ iatom,
                                    float* __restrict__ cc)
{
    int idx = blockIdx.x * blockDim.x + threadIdx.x;
    if (idx >= NSEQ * HD4) return;
    int row = idx / HD4, h4 = idx - row * HD4;
    int a = row + 1;
    float4 s  = make_float4(0.f, 0.f, 0.f, 0.f);
    float4 mx = make_float4(-INFINITY, -INFINITY, -INFINITY, -INFINITY);
    #pragma unroll
    for (int j = 0; j < NNB; j++) {
        int b = __ldg(&a2b[a * NNB + j]);
        float4 v = __ldg((const float4*)&mbond[b * HD] + h4);
        s = f4add(s, v); mx = f4max(mx, v);
    }
    float4 agg = make_float4(s.x*mx.x, s.y*mx.y, s.z*mx.z, s.w*mx.w);
    *((float4*)&cc[row * (3*HD)] + h4)            = agg;
    *((float4*)&cc[row * (3*HD) + HD] + h4)       = __ldg((const float4*)&matom[a * HD] + h4);
    *((float4*)&cc[row * (3*HD) + 2*HD] + h4)     = __ldg((const float4*)&iatom[a * HD] + h4);
}

__global__ void msg_kernel(const float* __restrict__ aggW, const float* __restrict__ gbias,
                           float* __restrict__ msg)
{
    int idx = blockIdx.x * blockDim.x + threadIdx.x;
    if (idx >= NSEQ * HD4) return;
    int h4 = idx % HD4;
    float4 v = __ldg((const float4*)aggW + idx);
    float4 b = __ldg((const float4*)gbias + h4);
    ((float4*)msg)[idx] = make_float4(fmaxf(v.x+b.x,0.f), fmaxf(v.y+b.y,0.f),
                                      fmaxf(v.z+b.z,0.f), fmaxf(v.w+b.w,0.f));
}

__global__ void h0_kernel(const float* __restrict__ aggW, float* __restrict__ h0)
{
    int idx = blockIdx.x * blockDim.x + threadIdx.x;
    if (idx >= NMOLS * HD4) return;
    int mol = idx / HD4, h4 = idx - mol * HD4;
    float4 mx = make_float4(-INFINITY, -INFINITY, -INFINITY, -INFINITY);
    for (int t = 0; t < ASIZE; t++)
        mx = f4max(mx, __ldg((const float4*)&aggW[(mol * ASIZE + t) * HD] + h4));
    ((float4*)h0)[idx] = mx;
}

__global__ void mean_kernel(const float* __restrict__ hid, float* __restrict__ out)
{
    int idx = blockIdx.x * blockDim.x + threadIdx.x;
    if (idx >= NMOLS * HD4) return;
    int mol = idx / HD4, h4 = idx - mol * HD4;
    float4 s = make_float4(0.f, 0.f, 0.f, 0.f);
    for (int t = 0; t < ASIZE; t++)
        s = f4add(s, __ldg((const float4*)&hid[(mol * ASIZE + t) * HD] + h4));
    ((float4*)out)[idx] = make_float4(s.x*(1.f/ASIZE), s.y*(1.f/ASIZE),
                                      s.z*(1.f/ASIZE), s.w*(1.f/ASIZE));
}

// ======================= fused bidirectional GRU (fp32) =======================
#define MPB 14   /* 72 blocks x 2 dirs = 144 <= 148 SMs, single wave */

__device__ __forceinline__ float sigmoidf_(float x) { return 1.f / (1.f + expf(-x)); }

__global__ __launch_bounds__(256)
void gru_fused(const float* __restrict__ xp_f, const float* __restrict__ xp_b,
               const float* __restrict__ Whh_f, const float* __restrict__ Whh_b,  // [3H, H]
               const float* __restrict__ bhh_f, const float* __restrict__ bhh_b,
               const float* __restrict__ h0, float* __restrict__ out)
{
    extern __shared__ float sm[];
    float* h_s  = sm;               // [MPB][304]
    float* gh_s = sm + MPB * 304;   // [MPB][912]

    const int tid  = threadIdx.x;
    const int dir  = blockIdx.y;
    const int mol0 = blockIdx.x * MPB;
    const int mc   = min(MPB, NMOLS - mol0);

    const float* xp  = dir ? xp_b  : xp_f;
    const float* Whh = dir ? Whh_b : Whh_f;
    const float* bhh = dir ? bhh_b : bhh_f;

    for (int i = tid; i < MPB * 304; i += 256) h_s[i] = 0.f;
    __syncthreads();
    for (int i = tid; i < mc * HD; i += 256) {
        int m = i / HD, hh = i - m * HD;
        h_s[m * 304 + hh] = h0[(mol0 + m) * HD + hh];
    }
    __syncthreads();

    const int c3ok = (tid + 768 < 3 * HD);

    for (int s = 0; s < ASIZE; s++) {
        const int t = dir ? (ASIZE - 1 - s) : s;

        float acc[4][MPB];
        #pragma unroll
        for (int j = 0; j < 4; j++)
            #pragma unroll
            for (int m = 0; m < MPB; m++) acc[j][m] = 0.f;

        for (int k = 0; k < HD; k += 4) {
            float4 w[4];
            #pragma unroll
            for (int j = 0; j < 3; j++)
                w[j] = *(const float4*)&Whh[(tid + j * 256) * HD + k];
            w[3] = c3ok ? *(const float4*)&Whh[(tid + 768) * HD + k]
                        : make_float4(0.f, 0.f, 0.f, 0.f);
            #pragma unroll
            for (int m = 0; m < MPB; m++) {
                float4 hv = *(const float4*)&h_s[m * 304 + k];
                #pragma unroll
                for (int j = 0; j < 4; j++) {
                    acc[j][m] = fmaf(w[j].x, hv.x, acc[j][m]);
                    acc[j][m] = fmaf(w[j].y, hv.y, acc[j][m]);
                    acc[j][m] = fmaf(w[j].z, hv.z, acc[j][m]);
                    acc[j][m] = fmaf(w[j].w, hv.w, acc[j][m]);
                }
            }
        }
        #pragma unroll
        for (int j = 0; j < 4; j++) {
            int cc = tid + j * 256;
            if (cc < 3 * HD) {
                float bb = bhh[cc];
                #pragma unroll
                for (int m = 0; m < MPB; m++)
                    gh_s[m * 912 + cc] = acc[j][m] + bb;
            }
        }
        __syncthreads();

        for (int i = tid; i < mc * HD; i += 256) {
            int m = i / HD, hh = i - m * HD;
            int row = (mol0 + m) * ASIZE + t;
            float ir = xp[row * (3*HD) + hh];
            float iz = xp[row * (3*HD) + HD + hh];
            float in = xp[row * (3*HD) + 2*HD + hh];
            float hr = gh_s[m * 912 + hh];
            float hz = gh_s[m * 912 + HD + hh];
            float hn = gh_s[m * 912 + 2*HD + hh];
            float r = sigmoidf_(ir + hr);
            float z = sigmoidf_(iz + hz);
            float n = tanhf(in + r * hn);
            float hp = h_s[m * 304 + hh];
            float hnew = (1.f - z) * n + z * hp;
            h_s[m * 304 + hh] = hnew;
            out[row * (2*HD) + dir * HD + hh] = hnew;
        }
        __syncthreads();
    }
}

// ======================= host orchestration =======================
static inline dim3 mma_grid(int M, int N) { return dim3((N + 63) / 64, (M + 127) / 128); }
static inline int  blocks_for(int n)      { return (n + 255) / 256; }

extern "C" void kernel_launch(void* const* d_in, const int* in_sizes, int n_in,
                              void* d_out, int out_size)
{
    const float* f_atoms  = (const float*)d_in[0];
    const float* f_bonds  = (const float*)d_in[1];
    const float* Wi_atom  = (const float*)d_in[2];
    const float* Wi_bond  = (const float*)d_in[3];
    const float* Wh0      = (const float*)d_in[4];
    const float* Wh1      = (const float*)d_in[5];
    const float* W_lr     = (const float*)d_in[6];
    const float* W_o      = (const float*)d_in[7];
    const float* b_o      = (const float*)d_in[8];
    const float* gru_bias = (const float*)d_in[9];
    const float* gWih_f   = (const float*)d_in[10];
    const float* gWhh_f   = (const float*)d_in[11];
    const float* gbih_f   = (const float*)d_in[12];
    const float* gbhh_f   = (const float*)d_in[13];
    const float* gWih_b   = (const float*)d_in[14];
    const float* gWhh_b   = (const float*)d_in[15];
    const float* gbih_b   = (const float*)d_in[16];
    const float* gbhh_b   = (const float*)d_in[17];
    const int*   a2b      = (const int*)d_in[18];
    const int*   b2a      = (const int*)d_in[19];
    const int*   b2revb   = (const int*)d_in[20];
    float* out = (float*)d_out;

    float *inA, *mA, *inB, *mB0, *mB1, *cc, *aggW, *msg, *xpf, *xpb, *h0, *gout, *hid;
    cudaGetSymbolAddress((void**)&inA,  g_input_atom);
    cudaGetSymbolAddress((void**)&mA,   g_message_atom);
    cudaGetSymbolAddress((void**)&inB,  g_input_bond);
    cudaGetSymbolAddress((void**)&mB0,  g_bondA);
    cudaGetSymbolAddress((void**)&mB1,  g_bondB);
    cudaGetSymbolAddress((void**)&cc,   g_concat);
    cudaGetSymbolAddress((void**)&aggW, g_aggW);
    cudaGetSymbolAddress((void**)&msg,  g_msg);
    cudaGetSymbolAddress((void**)&xpf,  g_xpf);
    cudaGetSymbolAddress((void**)&xpb,  g_xpb);
    cudaGetSymbolAddress((void**)&h0,   g_h0);
    cudaGetSymbolAddress((void**)&gout, g_out);
    cudaGetSymbolAddress((void**)&hid,  g_hid);

    const int gru_smem = (MPB * 304 + MPB * 912) * (int)sizeof(float);
    cudaFuncSetAttribute(gru_fused, cudaFuncAttributeMaxDynamicSharedMemorySize, gru_smem);

    // 1. input_atom = relu(f_atoms @ Wi_atom); dual-store into message_atom
    mma_gemm<false, 1, true, false><<<mma_grid(NATOMS, HD), 256>>>(
        f_atoms, Wi_atom, nullptr, nullptr, inA, mA, nullptr, nullptr, nullptr, nullptr,
        NATOMS, HD, AFDIM);

    // 2. input_bond = relu(f_bonds @ Wi_bond); dual-store into bond-message ping (mB0)
    mma_gemm<false, 1, true, false><<<mma_grid(NBONDS, HD), 256>>>(
        f_bonds, Wi_bond, nullptr, nullptr, inB, mB0, nullptr, nullptr, nullptr, nullptr,
        NBONDS, HD, BFDIM);

    // 3. two message-passing steps; mb gather fused into GEMM A-loader.
    //    PING-PONG: gather source and GEMM output must be different buffers.
    // step 0: read mB0 -> write mB1
    agg_update_kernel<<<blocks_for(NATOMS * HD4), 256>>>(mB0, a2b, mA);
    mma_gemm<false, 2, false, true><<<mma_grid(NBONDS, HD), 256>>>(
        nullptr, Wh0, inB, nullptr, mB1, nullptr, b2a, b2revb, mA, mB0,
        NBONDS, HD, HD);
    // step 1: read mB1 -> write mB0
    agg_update_kernel<<<blocks_for(NATOMS * HD4), 256>>>(mB1, a2b, mA);
    mma_gemm<false, 2, false, true><<<mma_grid(NBONDS, HD), 256>>>(
        nullptr, Wh1, inB, nullptr, mB0, nullptr, b2a, b2revb, mA, mB1,
        NBONDS, HD, HD);

    // 4. final aggregation + concat + W_lr  (reads mB0; atom rows 1..NSEQ)
    final_concat_kernel<<<blocks_for(NSEQ * HD4), 256>>>(mB0, a2b, mA, inA, cc);
    mma_gemm<false, 0, false, false><<<mma_grid(NSEQ, HD), 256>>>(
        cc, W_lr, nullptr, nullptr, aggW, nullptr, nullptr, nullptr, nullptr, nullptr,
        NSEQ, HD, 3 * HD);

    // 5. BatchGRU prep
    msg_kernel<<<blocks_for(NSEQ * HD4), 256>>>(aggW, gru_bias, msg);
    h0_kernel<<<blocks_for(NMOLS * HD4), 256>>>(aggW, h0);

    // input projections: xp = msg @ Wih^T + bih
    mma_gemm<true, 3, false, false><<<mma_grid(NSEQ, 3 * HD), 256>>>(
        msg, gWih_f, nullptr, gbih_f, xpf, nullptr, nullptr, nullptr, nullptr, nullptr,
        NSEQ, 3 * HD, HD);
    mma_gemm<true, 3, false, false><<<mma_grid(NSEQ, 3 * HD), 256>>>(
        msg, gWih_b, nullptr, gbih_b, xpb, nullptr, nullptr, nullptr, nullptr, nullptr,
        NSEQ, 3 * HD, HD);

    // 6+7. both GRU directions, all 40 steps, one kernel
    {
        dim3 grid((NMOLS + MPB - 1) / MPB, 2);
        gru_fused<<<grid, 256, gru_smem>>>(xpf, xpb, gWhh_f, gWhh_b, gbhh_f, gbhh_b, h0, gout);
    }

    // 8. atom_hiddens = relu(out @ W_o + b_o); mol_vecs = per-mol mean
    mma_gemm<false, 4, false, false><<<mma_grid(NSEQ, HD), 256>>>(
        gout, W_o, nullptr, b_o, hid, nullptr, nullptr, nullptr, nullptr, nullptr,
        NSEQ, HD, 2 * HD);
    mean_kernel<<<blocks_for(NMOLS * HD4), 256>>>(hid, out);
}

// round 8
// speedup vs baseline: 1.4756x; 1.0331x over previous
#include <cuda_runtime.h>
#include <math.h>
#include <stdint.h>

#define NATOMS 40001
#define NBONDS 160001
#define NNB    6
#define AFDIM  133
#define BFDIM  147
#define HD     300
#define NMOLS  1000
#define ASIZE  40
#define NSEQ   (NMOLS * ASIZE)   /* 40000 */

// ---------------- scratch (static device globals; no runtime allocation) ----------------
__device__ float g_input_atom  [NATOMS * HD];
__device__ float g_message_atom[NATOMS * HD];
__device__ float g_input_bond  [NBONDS * HD];
__device__ float g_bondA       [NBONDS * HD];   // bond-message ping
__device__ float g_bondB       [NBONDS * HD];   // bond-message pong
__device__ float g_concat      [NSEQ * 3 * HD];
__device__ float g_aggW        [NSEQ * HD];
__device__ float g_msg         [NSEQ * HD];
__device__ float g_xpf         [NSEQ * 3 * HD];
__device__ float g_xpb         [NSEQ * 3 * HD];
__device__ float g_h0          [NMOLS * HD];
__device__ float g_out         [NSEQ * 2 * HD];
__device__ float g_hid         [NSEQ * HD];

// ======================= 3xTF32 split-precision tensor-core GEMM =======================
// C[M,N] = epi(A' @ B);  A' = A[M,K]  or (GATHER) A'[m] = GA[idxA[m]] - GB[idxB[m]].
// GATHER REQUIRES C to not alias GA/GB (ping-pong buffers at call site!).
// B row-major [K,N]; TRANSB: B is W[N,K] row-major.
// SMEM holds raw fp32 (single copy); the hi/lo tf32 split (x = hi + lo, exact
// residual) is computed in REGISTERS after the fragment LDS -> halves LDS/L1
// traffic vs storing hi & lo separately, with bitwise-identical results.
// hi*hi + hi*lo + lo*hi with fp32 accum (~fp32 accuracy).
// EPI: 0 none, 1 relu, 2 relu(acc+ADD), 3 acc+bias, 4 relu(acc+bias). DUAL: also store C2.
// Block tile 128x64, 256 threads = 8 warps (4m x 2n), warp tile 32x32, K-chunk 16.

__device__ __forceinline__ void mma_tf32(float c[4], const uint32_t a[4], const uint32_t b[2]) {
    asm volatile(
        "mma.sync.aligned.m16n8k8.row.col.f32.tf32.tf32.f32 "
        "{%0,%1,%2,%3}, {%4,%5,%6,%7}, {%8,%9}, {%0,%1,%2,%3};"
        : "+f"(c[0]), "+f"(c[1]), "+f"(c[2]), "+f"(c[3])
        : "r"(a[0]), "r"(a[1]), "r"(a[2]), "r"(a[3]), "r"(b[0]), "r"(b[1]));
}

__device__ __forceinline__ float f2tf32(float v) {
    uint32_t t;
    asm("cvt.rna.tf32.f32 %0, %1;" : "=r"(t) : "f"(v));
    return __uint_as_float(t);
}

// split one fp32 into tf32 hi + tf32 lo (as uint bit patterns)
__device__ __forceinline__ void split_tf32(float v, uint32_t& hi, uint32_t& lo) {
    float h = f2tf32(v);
    hi = __float_as_uint(h);
    lo = __float_as_uint(f2tf32(v - h));
}

template<bool TRANSB, int EPI, bool DUAL, bool GATHER>
__global__ __launch_bounds__(256)
void mma_gemm(const float* __restrict__ A, const float* __restrict__ B,
              const float* __restrict__ ADD, const float* __restrict__ bias,
              float* __restrict__ C, float* __restrict__ C2,
              const int* __restrict__ idxA, const int* __restrict__ idxB,
              const float* __restrict__ GA, const float* __restrict__ GB,
              int M, int N, int K)
{
    __shared__ float As[128][20];   // [m][k] raw fp32
    __shared__ float Bs[16][68];    // [k][n] raw fp32

    const int tid  = threadIdx.x;
    const int warp = tid >> 5, lane = tid & 31;
    const int wm   = warp & 3, wn = warp >> 2;
    const int gid  = lane >> 2, tig = lane & 3;
    const int bM   = blockIdx.y * 128, bN = blockIdx.x * 64;

    const int aRow = tid >> 2;
    const int aCol = (tid & 3) * 4;

    float aR[8], bR[4];
    float c[2][4][4] = {};

    const int nCh = (K + 15) >> 4;

    auto loadA = [&](int kt) {
        #pragma unroll
        for (int r = 0; r < 2; r++) {
            int gm  = bM + aRow + 64 * r;
            int gk0 = kt + aCol;
            if (GATHER) {
                if (gm < M) {
                    int ia = __ldg(&idxA[gm]);
                    int ib = __ldg(&idxB[gm]);
                    if (gk0 + 3 < K) {   // rows are 16B aligned (HD*4 % 16 == 0)
                        float4 va = __ldg((const float4*)&GA[(size_t)ia * K + gk0]);
                        float4 vb = __ldg((const float4*)&GB[(size_t)ib * K + gk0]);
                        aR[r*4+0] = va.x - vb.x; aR[r*4+1] = va.y - vb.y;
                        aR[r*4+2] = va.z - vb.z; aR[r*4+3] = va.w - vb.w;
                    } else {
                        #pragma unroll
                        for (int i = 0; i < 4; i++) {
                            int gk = gk0 + i;
                            aR[r*4+i] = (gk < K)
                                ? __ldg(&GA[(size_t)ia * K + gk]) - __ldg(&GB[(size_t)ib * K + gk])
                                : 0.f;
                        }
                    }
                } else {
                    #pragma unroll
                    for (int i = 0; i < 4; i++) aR[r*4+i] = 0.f;
                }
            } else {
                #pragma unroll
                for (int i = 0; i < 4; i++) {
                    int gk = gk0 + i;
                    aR[r*4+i] = (gm < M && gk < K) ? A[(size_t)gm * K + gk] : 0.f;
                }
            }
        }
    };
    auto loadB = [&](int kt) {
        if (!TRANSB) {
            int k = tid >> 4, n0 = (tid & 15) * 4;
            #pragma unroll
            for (int i = 0; i < 4; i++) {
                int gk = kt + k, gn = bN + n0 + i;
                bR[i] = (gk < K && gn < N) ? B[(size_t)gk * N + gn] : 0.f;
            }
        } else {
            int n = tid >> 2, k0 = (tid & 3) * 4;
            #pragma unroll
            for (int i = 0; i < 4; i++) {
                int gk = kt + k0 + i, gn = bN + n;
                bR[i] = (gk < K && gn < N) ? B[(size_t)gn * K + gk] : 0.f;
            }
        }
    };

    loadA(0);
    loadB(0);

    for (int ch = 0; ch < nCh; ch++) {
        // ---- STS raw fp32 (single copy) ----
        #pragma unroll
        for (int r = 0; r < 2; r++)
            *(float4*)&As[aRow + 64*r][aCol] =
                make_float4(aR[r*4+0], aR[r*4+1], aR[r*4+2], aR[r*4+3]);
        if (!TRANSB) {
            int k = tid >> 4, n0 = (tid & 15) * 4;
            *(float4*)&Bs[k][n0] = make_float4(bR[0], bR[1], bR[2], bR[3]);
        } else {
            int n = tid >> 2, k0 = (tid & 3) * 4;
            #pragma unroll
            for (int i = 0; i < 4; i++) Bs[k0 + i][n] = bR[i];
        }
        __syncthreads();

        if (ch + 1 < nCh) {
            loadA((ch + 1) << 4);
            loadB((ch + 1) << 4);
        }

        // ---- compute chunk: LDS fp32, split in regs, 3 mma per (mt,nt) per k8 ----
        #pragma unroll
        for (int kk = 0; kk < 16; kk += 8) {
            uint32_t ah[2][4], al[2][4], bh_[4][2], bl_[4][2];
            #pragma unroll
            for (int mt = 0; mt < 2; mt++) {
                int m0 = wm * 32 + mt * 16 + gid;
                split_tf32(As[m0    ][kk + tig    ], ah[mt][0], al[mt][0]);
                split_tf32(As[m0 + 8][kk + tig    ], ah[mt][1], al[mt][1]);
                split_tf32(As[m0    ][kk + tig + 4], ah[mt][2], al[mt][2]);
                split_tf32(As[m0 + 8][kk + tig + 4], ah[mt][3], al[mt][3]);
            }
            #pragma unroll
            for (int nt = 0; nt < 4; nt++) {
                int n0 = wn * 32 + nt * 8 + gid;
                split_tf32(Bs[kk + tig    ][n0], bh_[nt][0], bl_[nt][0]);
                split_tf32(Bs[kk + tig + 4][n0], bh_[nt][1], bl_[nt][1]);
            }
            #pragma unroll
            for (int mt = 0; mt < 2; mt++)
                #pragma unroll
                for (int nt = 0; nt < 4; nt++) {
                    mma_tf32(c[mt][nt], ah[mt], bl_[nt]);
                    mma_tf32(c[mt][nt], al[mt], bh_[nt]);
                    mma_tf32(c[mt][nt], ah[mt], bh_[nt]);
                }
        }
        __syncthreads();
    }

    // ---- epilogue ----
    #pragma unroll
    for (int mt = 0; mt < 2; mt++)
        #pragma unroll
        for (int nt = 0; nt < 4; nt++)
            #pragma unroll
            for (int e = 0; e < 4; e++) {
                int row = bM + wm * 32 + mt * 16 + gid + ((e >= 2) ? 8 : 0);
                int col = bN + wn * 32 + nt * 8 + tig * 2 + (e & 1);
                if (row < M && col < N) {
                    float v = c[mt][nt][e];
                    if (EPI == 2)             v += ADD[(size_t)row * N + col];
                    if (EPI == 3 || EPI == 4) v += bias[col];
                    if (EPI == 1 || EPI == 2 || EPI == 4) v = fmaxf(v, 0.f);
                    C[(size_t)row * N + col] = v;
                    if (DUAL) C2[(size_t)row * N + col] = v;
                }
            }
}

// ======================= float4 gather/pointwise helpers =======================
#define HD4 (HD / 4)   /* 75 */

__device__ __forceinline__ float4 f4max(float4 a, float4 b) {
    return make_float4(fmaxf(a.x,b.x), fmaxf(a.y,b.y), fmaxf(a.z,b.z), fmaxf(a.w,b.w));
}
__device__ __forceinline__ float4 f4add(float4 a, float4 b) {
    return make_float4(a.x+b.x, a.y+b.y, a.z+b.z, a.w+b.w);
}

__global__ void agg_update_kernel(const float* __restrict__ mbond, const int* __restrict__ a2b,
                                  float* __restrict__ matom)
{
    int idx = blockIdx.x * blockDim.x + threadIdx.x;
    if (idx >= NATOMS * HD4) return;
    int a = idx / HD4, h4 = idx - a * HD4;
    float4 s  = make_float4(0.f, 0.f, 0.f, 0.f);
    float4 mx = make_float4(-INFINITY, -INFINITY, -INFINITY, -INFINITY);
    #pragma unroll
    for (int j = 0; j < NNB; j++) {
        int b = __ldg(&a2b[a * NNB + j]);
        float4 v = __ldg((const float4*)&mbond[b * HD] + h4);
        s = f4add(s, v); mx = f4max(mx, v);
    }
    float4* dst = (float4*)&matom[a * HD] + h4;
    float4 cur = *dst;
    cur.x += s.x * mx.x; cur.y += s.y * mx.y; cur.z += s.z * mx.z; cur.w += s.w * mx.w;
    *dst = cur;
}

__global__ void final_concat_kernel(const float* __restrict__ mbond, const int* __restrict__ a2b,
                                    const float* __restrict__ matom, const float* __restrict__ iatom,
                                    float* __restrict__ cc)
{
    int idx = blockIdx.x * blockDim.x + threadIdx.x;
    if (idx >= NSEQ * HD4) return;
    int row = idx / HD4, h4 = idx - row * HD4;
    int a = row + 1;
    float4 s  = make_float4(0.f, 0.f, 0.f, 0.f);
    float4 mx = make_float4(-INFINITY, -INFINITY, -INFINITY, -INFINITY);
    #pragma unroll
    for (int j = 0; j < NNB; j++) {
        int b = __ldg(&a2b[a * NNB + j]);
        float4 v = __ldg((const float4*)&mbond[b * HD] + h4);
        s = f4add(s, v); mx = f4max(mx, v);
    }
    float4 agg = make_float4(s.x*mx.x, s.y*mx.y, s.z*mx.z, s.w*mx.w);
    *((float4*)&cc[row * (3*HD)] + h4)            = agg;
    *((float4*)&cc[row * (3*HD) + HD] + h4)       = __ldg((const float4*)&matom[a * HD] + h4);
    *((float4*)&cc[row * (3*HD) + 2*HD] + h4)     = __ldg((const float4*)&iatom[a * HD] + h4);
}

__global__ void msg_kernel(const float* __restrict__ aggW, const float* __restrict__ gbias,
                           float* __restrict__ msg)
{
    int idx = blockIdx.x * blockDim.x + threadIdx.x;
    if (idx >= NSEQ * HD4) return;
    int h4 = idx % HD4;
    float4 v = __ldg((const float4*)aggW + idx);
    float4 b = __ldg((const float4*)gbias + h4);
    ((float4*)msg)[idx] = make_float4(fmaxf(v.x+b.x,0.f), fmaxf(v.y+b.y,0.f),
                                      fmaxf(v.z+b.z,0.f), fmaxf(v.w+b.w,0.f));
}

__global__ void h0_kernel(const float* __restrict__ aggW, float* __restrict__ h0)
{
    int idx = blockIdx.x * blockDim.x + threadIdx.x;
    if (idx >= NMOLS * HD4) return;
    int mol = idx / HD4, h4 = idx - mol * HD4;
    float4 mx = make_float4(-INFINITY, -INFINITY, -INFINITY, -INFINITY);
    for (int t = 0; t < ASIZE; t++)
        mx = f4max(mx, __ldg((const float4*)&aggW[(mol * ASIZE + t) * HD] + h4));
    ((float4*)h0)[idx] = mx;
}

__global__ void mean_kernel(const float* __restrict__ hid, float* __restrict__ out)
{
    int idx = blockIdx.x * blockDim.x + threadIdx.x;
    if (idx >= NMOLS * HD4) return;
    int mol = idx / HD4, h4 = idx - mol * HD4;
    float4 s = make_float4(0.f, 0.f, 0.f, 0.f);
    for (int t = 0; t < ASIZE; t++)
        s = f4add(s, __ldg((const float4*)&hid[(mol * ASIZE + t) * HD] + h4));
    ((float4*)out)[idx] = make_float4(s.x*(1.f/ASIZE), s.y*(1.f/ASIZE),
                                      s.z*(1.f/ASIZE), s.w*(1.f/ASIZE));
}

// ======================= fused bidirectional GRU (fp32) =======================
#define MPB 14   /* 72 blocks x 2 dirs = 144 <= 148 SMs, single wave */

__device__ __forceinline__ float sigmoidf_(float x) { return 1.f / (1.f + expf(-x)); }

__global__ __launch_bounds__(256)
void gru_fused(const float* __restrict__ xp_f, const float* __restrict__ xp_b,
               const float* __restrict__ Whh_f, const float* __restrict__ Whh_b,  // [3H, H]
               const float* __restrict__ bhh_f, const float* __restrict__ bhh_b,
               const float* __restrict__ h0, float* __restrict__ out)
{
    extern __shared__ float sm[];
    float* h_s  = sm;               // [MPB][304]
    float* gh_s = sm + MPB * 304;   // [MPB][912]

    const int tid  = threadIdx.x;
    const int dir  = blockIdx.y;
    const int mol0 = blockIdx.x * MPB;
    const int mc   = min(MPB, NMOLS - mol0);

    const float* xp  = dir ? xp_b  : xp_f;
    const float* Whh = dir ? Whh_b : Whh_f;
    const float* bhh = dir ? bhh_b : bhh_f;

    for (int i = tid; i < MPB * 304; i += 256) h_s[i] = 0.f;
    __syncthreads();
    for (int i = tid; i < mc * HD; i += 256) {
        int m = i / HD, hh = i - m * HD;
        h_s[m * 304 + hh] = h0[(mol0 + m) * HD + hh];
    }
    __syncthreads();

    const int c3ok = (tid + 768 < 3 * HD);

    for (int s = 0; s < ASIZE; s++) {
        const int t = dir ? (ASIZE - 1 - s) : s;

        float acc[4][MPB];
        #pragma unroll
        for (int j = 0; j < 4; j++)
            #pragma unroll
            for (int m = 0; m < MPB; m++) acc[j][m] = 0.f;

        for (int k = 0; k < HD; k += 4) {
            float4 w[4];
            #pragma unroll
            for (int j = 0; j < 3; j++)
                w[j] = *(const float4*)&Whh[(tid + j * 256) * HD + k];
            w[3] = c3ok ? *(const float4*)&Whh[(tid + 768) * HD + k]
                        : make_float4(0.f, 0.f, 0.f, 0.f);
            #pragma unroll
            for (int m = 0; m < MPB; m++) {
                float4 hv = *(const float4*)&h_s[m * 304 + k];
                #pragma unroll
                for (int j = 0; j < 4; j++) {
                    acc[j][m] = fmaf(w[j].x, hv.x, acc[j][m]);
                    acc[j][m] = fmaf(w[j].y, hv.y, acc[j][m]);
                    acc[j][m] = fmaf(w[j].z, hv.z, acc[j][m]);
                    acc[j][m] = fmaf(w[j].w, hv.w, acc[j][m]);
                }
            }
        }
        #pragma unroll
        for (int j = 0; j < 4; j++) {
            int cc = tid + j * 256;
            if (cc < 3 * HD) {
                float bb = bhh[cc];
                #pragma unroll
                for (int m = 0; m < MPB; m++)
                    gh_s[m * 912 + cc] = acc[j][m] + bb;
            }
        }
        __syncthreads();

        for (int i = tid; i < mc * HD; i += 256) {
            int m = i / HD, hh = i - m * HD;
            int row = (mol0 + m) * ASIZE + t;
            float ir = xp[row * (3*HD) + hh];
            float iz = xp[row * (3*HD) + HD + hh];
            float in = xp[row * (3*HD) + 2*HD + hh];
            float hr = gh_s[m * 912 + hh];
            float hz = gh_s[m * 912 + HD + hh];
            float hn = gh_s[m * 912 + 2*HD + hh];
            float r = sigmoidf_(ir + hr);
            float z = sigmoidf_(iz + hz);
            float n = tanhf(in + r * hn);
            float hp = h_s[m * 304 + hh];
            float hnew = (1.f - z) * n + z * hp;
            h_s[m * 304 + hh] = hnew;
            out[row * (2*HD) + dir * HD + hh] = hnew;
        }
        __syncthreads();
    }
}

// ======================= host orchestration =======================
static inline dim3 mma_grid(int M, int N) { return dim3((N + 63) / 64, (M + 127) / 128); }
static inline int  blocks_for(int n)      { return (n + 255) / 256; }

extern "C" void kernel_launch(void* const* d_in, const int* in_sizes, int n_in,
                              void* d_out, int out_size)
{
    const float* f_atoms  = (const float*)d_in[0];
    const float* f_bonds  = (const float*)d_in[1];
    const float* Wi_atom  = (const float*)d_in[2];
    const float* Wi_bond  = (const float*)d_in[3];
    const float* Wh0      = (const float*)d_in[4];
    const float* Wh1      = (const float*)d_in[5];
    const float* W_lr     = (const float*)d_in[6];
    const float* W_o      = (const float*)d_in[7];
    const float* b_o      = (const float*)d_in[8];
    const float* gru_bias = (const float*)d_in[9];
    const float* gWih_f   = (const float*)d_in[10];
    const float* gWhh_f   = (const float*)d_in[11];
    const float* gbih_f   = (const float*)d_in[12];
    const float* gbhh_f   = (const float*)d_in[13];
    const float* gWih_b   = (const float*)d_in[14];
    const float* gWhh_b   = (const float*)d_in[15];
    const float* gbih_b   = (const float*)d_in[16];
    const float* gbhh_b   = (const float*)d_in[17];
    const int*   a2b      = (const int*)d_in[18];
    const int*   b2a      = (const int*)d_in[19];
    const int*   b2revb   = (const int*)d_in[20];
    float* out = (float*)d_out;

    float *inA, *mA, *inB, *mB0, *mB1, *cc, *aggW, *msg, *xpf, *xpb, *h0, *gout, *hid;
    cudaGetSymbolAddress((void**)&inA,  g_input_atom);
    cudaGetSymbolAddress((void**)&mA,   g_message_atom);
    cudaGetSymbolAddress((void**)&inB,  g_input_bond);
    cudaGetSymbolAddress((void**)&mB0,  g_bondA);
    cudaGetSymbolAddress((void**)&mB1,  g_bondB);
    cudaGetSymbolAddress((void**)&cc,   g_concat);
    cudaGetSymbolAddress((void**)&aggW, g_aggW);
    cudaGetSymbolAddress((void**)&msg,  g_msg);
    cudaGetSymbolAddress((void**)&xpf,  g_xpf);
    cudaGetSymbolAddress((void**)&xpb,  g_xpb);
    cudaGetSymbolAddress((void**)&h0,   g_h0);
    cudaGetSymbolAddress((void**)&gout, g_out);
    cudaGetSymbolAddress((void**)&hid,  g_hid);

    const int gru_smem = (MPB * 304 + MPB * 912) * (int)sizeof(float);
    cudaFuncSetAttribute(gru_fused, cudaFuncAttributeMaxDynamicSharedMemorySize, gru_smem);

    // 1. input_atom = relu(f_atoms @ Wi_atom); dual-store into message_atom
    mma_gemm<false, 1, true, false><<<mma_grid(NATOMS, HD), 256>>>(
        f_atoms, Wi_atom, nullptr, nullptr, inA, mA, nullptr, nullptr, nullptr, nullptr,
        NATOMS, HD, AFDIM);

    // 2. input_bond = relu(f_bonds @ Wi_bond); dual-store into bond-message ping (mB0)
    mma_gemm<false, 1, true, false><<<mma_grid(NBONDS, HD), 256>>>(
        f_bonds, Wi_bond, nullptr, nullptr, inB, mB0, nullptr, nullptr, nullptr, nullptr,
        NBONDS, HD, BFDIM);

    // 3. two message-passing steps; mb gather fused into GEMM A-loader.
    //    PING-PONG: gather source and GEMM output must be different buffers.
    agg_update_kernel<<<blocks_for(NATOMS * HD4), 256>>>(mB0, a2b, mA);
    mma_gemm<false, 2, false, true><<<mma_grid(NBONDS, HD), 256>>>(
        nullptr, Wh0, inB, nullptr, mB1, nullptr, b2a, b2revb, mA, mB0,
        NBONDS, HD, HD);
    agg_update_kernel<<<blocks_for(NATOMS * HD4), 256>>>(mB1, a2b, mA);
    mma_gemm<false, 2, false, true><<<mma_grid(NBONDS, HD), 256>>>(
        nullptr, Wh1, inB, nullptr, mB0, nullptr, b2a, b2revb, mA, mB1,
        NBONDS, HD, HD);

    // 4. final aggregation + concat + W_lr  (reads mB0; atom rows 1..NSEQ)
    final_concat_kernel<<<blocks_for(NSEQ * HD4), 256>>>(mB0, a2b, mA, inA, cc);
    mma_gemm<false, 0, false, false><<<mma_grid(NSEQ, HD), 256>>>(
        cc, W_lr, nullptr, nullptr, aggW, nullptr, nullptr, nullptr, nullptr, nullptr,
        NSEQ, HD, 3 * HD);

    // 5. BatchGRU prep
    msg_kernel<<<blocks_for(NSEQ * HD4), 256>>>(aggW, gru_bias, msg);
    h0_kernel<<<blocks_for(NMOLS * HD4), 256>>>(aggW, h0);

    // input projections: xp = msg @ Wih^T + bih
    mma_gemm<true, 3, false, false><<<mma_grid(NSEQ, 3 * HD), 256>>>(
        msg, gWih_f, nullptr, gbih_f, xpf, nullptr, nullptr, nullptr, nullptr, nullptr,
        NSEQ, 3 * HD, HD);
    mma_gemm<true, 3, false, false><<<mma_grid(NSEQ, 3 * HD), 256>>>(
        msg, gWih_b, nullptr, gbih_b, xpb, nullptr, nullptr, nullptr, nullptr, nullptr,
        NSEQ, 3 * HD, HD);

    // 6+7. both GRU directions, all 40 steps, one kernel
    {
        dim3 grid((NMOLS + MPB - 1) / MPB, 2);
        gru_fused<<<grid, 256, gru_smem>>>(xpf, xpb, gWhh_f, gWhh_b, gbhh_f, gbhh_b, h0, gout);
    }

    // 8. atom_hiddens = relu(out @ W_o + b_o); mol_vecs = per-mol mean
    mma_gemm<false, 4, false, false><<<mma_grid(NSEQ, HD), 256>>>(
        gout, W_o, nullptr, b_o, hid, nullptr, nullptr, nullptr, nullptr, nullptr,
        NSEQ, HD, 2 * HD);
    mean_kernel<<<blocks_for(NMOLS * HD4), 256>>>(hid, out);
}

// round 9
// speedup vs baseline: 1.5635x; 1.0595x over previous
#include <cuda_runtime.h>
#include <math.h>
#include <stdint.h>

#define NATOMS 40001
#define NBONDS 160001
#define NNB    6
#define AFDIM  133
#define BFDIM  147
#define HD     300
#define NMOLS  1000
#define ASIZE  40
#define NSEQ   (NMOLS * ASIZE)   /* 40000 */

// ---------------- scratch (static device globals; no runtime allocation) ----------------
__device__ float g_input_atom  [NATOMS * HD];
__device__ float g_message_atom[NATOMS * HD];
__device__ float g_input_bond  [NBONDS * HD];
__device__ float g_bondA       [NBONDS * HD];   // bond-message ping
__device__ float g_bondB       [NBONDS * HD];   // bond-message pong
__device__ float g_concat      [NSEQ * 3 * HD];
__device__ float g_aggW        [NSEQ * HD];
__device__ float g_msg         [NSEQ * HD];
__device__ float g_xpf         [NSEQ * 3 * HD];
__device__ float g_xpb         [NSEQ * 3 * HD];
__device__ float g_h0          [NMOLS * HD];
__device__ float g_out         [NSEQ * 2 * HD];
__device__ float g_hid         [NSEQ * HD];

// ======================= 3xTF32 split-precision tensor-core GEMM =======================
// C[M,N] = epi(A' @ B);  A' = A[M,K]  or (GATHER) A'[m] = GA[idxA[m]] - GB[idxB[m]].
// GATHER REQUIRES C to not alias GA/GB (ping-pong buffers at call site!).
// B row-major [K,N]; TRANSB: B is W[N,K] row-major.
// ASYMMETRIC split placement:
//   A: raw fp32 in smem, hi/lo tf32 split in registers after fragment LDS
//      (each A value consumed by only 2 warps -> x2 redundancy, cheap).
//   B: pre-split Bh/Bl in smem, split computed ONCE by loader threads
//      (each B value consumed by 4 warps -> avoids x4 redundant ALU).
// x = hi + lo exact residual; hi*hi + hi*lo + lo*hi, fp32 accum (~fp32 accuracy).
// EPI: 0 none, 1 relu, 2 relu(acc+ADD), 3 acc+bias, 4 relu(acc+bias). DUAL: also store C2.
// Block tile 128x64, 256 threads = 8 warps (4m x 2n), warp tile 32x32, K-chunk 16.
// __launch_bounds__(256,3): cap regs at 85 so 3 blocks/SM fit (occupancy > latency hiding).

__device__ __forceinline__ void mma_tf32(float c[4], const uint32_t a[4], const uint32_t b[2]) {
    asm volatile(
        "mma.sync.aligned.m16n8k8.row.col.f32.tf32.tf32.f32 "
        "{%0,%1,%2,%3}, {%4,%5,%6,%7}, {%8,%9}, {%0,%1,%2,%3};"
        : "+f"(c[0]), "+f"(c[1]), "+f"(c[2]), "+f"(c[3])
        : "r"(a[0]), "r"(a[1]), "r"(a[2]), "r"(a[3]), "r"(b[0]), "r"(b[1]));
}

__device__ __forceinline__ float f2tf32(float v) {
    uint32_t t;
    asm("cvt.rna.tf32.f32 %0, %1;" : "=r"(t) : "f"(v));
    return __uint_as_float(t);
}

// split one fp32 into tf32 hi + tf32 lo (as uint bit patterns)
__device__ __forceinline__ void split_tf32(float v, uint32_t& hi, uint32_t& lo) {
    float h = f2tf32(v);
    hi = __float_as_uint(h);
    lo = __float_as_uint(f2tf32(v - h));
}

template<bool TRANSB, int EPI, bool DUAL, bool GATHER>
__global__ __launch_bounds__(256, 3)
void mma_gemm(const float* __restrict__ A, const float* __restrict__ B,
              const float* __restrict__ ADD, const float* __restrict__ bias,
              float* __restrict__ C, float* __restrict__ C2,
              const int* __restrict__ idxA, const int* __restrict__ idxB,
              const float* __restrict__ GA, const float* __restrict__ GB,
              int M, int N, int K)
{
    __shared__ float As[128][20];   // [m][k] raw fp32
    __shared__ float Bh[16][68];    // [k][n] tf32 hi
    __shared__ float Bl[16][68];    // [k][n] tf32 lo

    const int tid  = threadIdx.x;
    const int warp = tid >> 5, lane = tid & 31;
    const int wm   = warp & 3, wn = warp >> 2;
    const int gid  = lane >> 2, tig = lane & 3;
    const int bM   = blockIdx.y * 128, bN = blockIdx.x * 64;

    const int aRow = tid >> 2;
    const int aCol = (tid & 3) * 4;

    float aR[8], bR[4];
    float c[2][4][4] = {};

    const int nCh = (K + 15) >> 4;

    auto loadA = [&](int kt) {
        #pragma unroll
        for (int r = 0; r < 2; r++) {
            int gm  = bM + aRow + 64 * r;
            int gk0 = kt + aCol;
            if (GATHER) {
                if (gm < M) {
                    int ia = __ldg(&idxA[gm]);
                    int ib = __ldg(&idxB[gm]);
                    if (gk0 + 3 < K) {   // rows are 16B aligned (HD*4 % 16 == 0)
                        float4 va = __ldg((const float4*)&GA[(size_t)ia * K + gk0]);
                        float4 vb = __ldg((const float4*)&GB[(size_t)ib * K + gk0]);
                        aR[r*4+0] = va.x - vb.x; aR[r*4+1] = va.y - vb.y;
                        aR[r*4+2] = va.z - vb.z; aR[r*4+3] = va.w - vb.w;
                    } else {
                        #pragma unroll
                        for (int i = 0; i < 4; i++) {
                            int gk = gk0 + i;
                            aR[r*4+i] = (gk < K)
                                ? __ldg(&GA[(size_t)ia * K + gk]) - __ldg(&GB[(size_t)ib * K + gk])
                                : 0.f;
                        }
                    }
                } else {
                    #pragma unroll
                    for (int i = 0; i < 4; i++) aR[r*4+i] = 0.f;
                }
            } else {
                #pragma unroll
                for (int i = 0; i < 4; i++) {
                    int gk = gk0 + i;
                    aR[r*4+i] = (gm < M && gk < K) ? A[(size_t)gm * K + gk] : 0.f;
                }
            }
        }
    };
    auto loadB = [&](int kt) {
        if (!TRANSB) {
            int k = tid >> 4, n0 = (tid & 15) * 4;
            #pragma unroll
            for (int i = 0; i < 4; i++) {
                int gk = kt + k, gn = bN + n0 + i;
                bR[i] = (gk < K && gn < N) ? B[(size_t)gk * N + gn] : 0.f;
            }
        } else {
            int n = tid >> 2, k0 = (tid & 3) * 4;
            #pragma unroll
            for (int i = 0; i < 4; i++) {
                int gk = kt + k0 + i, gn = bN + n;
                bR[i] = (gk < K && gn < N) ? B[(size_t)gn * K + gk] : 0.f;
            }
        }
    };

    loadA(0);
    loadB(0);

    for (int ch = 0; ch < nCh; ch++) {
        // ---- STS: A raw; B split once here ----
        #pragma unroll
        for (int r = 0; r < 2; r++)
            *(float4*)&As[aRow + 64*r][aCol] =
                make_float4(aR[r*4+0], aR[r*4+1], aR[r*4+2], aR[r*4+3]);
        if (!TRANSB) {
            int k = tid >> 4, n0 = (tid & 15) * 4;
            float4 h, l;
            h.x = f2tf32(bR[0]); l.x = f2tf32(bR[0] - h.x);
            h.y = f2tf32(bR[1]); l.y = f2tf32(bR[1] - h.y);
            h.z = f2tf32(bR[2]); l.z = f2tf32(bR[2] - h.z);
            h.w = f2tf32(bR[3]); l.w = f2tf32(bR[3] - h.w);
            *(float4*)&Bh[k][n0] = h;
            *(float4*)&Bl[k][n0] = l;
        } else {
            int n = tid >> 2, k0 = (tid & 3) * 4;
            #pragma unroll
            for (int i = 0; i < 4; i++) {
                float h = f2tf32(bR[i]);
                Bh[k0 + i][n] = h;
                Bl[k0 + i][n] = f2tf32(bR[i] - h);
            }
        }
        __syncthreads();

        if (ch + 1 < nCh) {
            loadA((ch + 1) << 4);
            loadB((ch + 1) << 4);
        }

        // ---- compute chunk: A split in regs, B pre-split in smem ----
        #pragma unroll
        for (int kk = 0; kk < 16; kk += 8) {
            uint32_t ah[2][4], al[2][4], bh_[4][2], bl_[4][2];
            #pragma unroll
            for (int mt = 0; mt < 2; mt++) {
                int m0 = wm * 32 + mt * 16 + gid;
                split_tf32(As[m0    ][kk + tig    ], ah[mt][0], al[mt][0]);
                split_tf32(As[m0 + 8][kk + tig    ], ah[mt][1], al[mt][1]);
                split_tf32(As[m0    ][kk + tig + 4], ah[mt][2], al[mt][2]);
                split_tf32(As[m0 + 8][kk + tig + 4], ah[mt][3], al[mt][3]);
            }
            #pragma unroll
            for (int nt = 0; nt < 4; nt++) {
                int n0 = wn * 32 + nt * 8 + gid;
                bh_[nt][0] = __float_as_uint(Bh[kk + tig    ][n0]);
                bh_[nt][1] = __float_as_uint(Bh[kk + tig + 4][n0]);
                bl_[nt][0] = __float_as_uint(Bl[kk + tig    ][n0]);
                bl_[nt][1] = __float_as_uint(Bl[kk + tig + 4][n0]);
            }
            #pragma unroll
            for (int mt = 0; mt < 2; mt++)
                #pragma unroll
                for (int nt = 0; nt < 4; nt++) {
                    mma_tf32(c[mt][nt], ah[mt], bl_[nt]);
                    mma_tf32(c[mt][nt], al[mt], bh_[nt]);
                    mma_tf32(c[mt][nt], ah[mt], bh_[nt]);
                }
        }
        __syncthreads();
    }

    // ---- epilogue ----
    #pragma unroll
    for (int mt = 0; mt < 2; mt++)
        #pragma unroll
        for (int nt = 0; nt < 4; nt++)
            #pragma unroll
            for (int e = 0; e < 4; e++) {
                int row = bM + wm * 32 + mt * 16 + gid + ((e >= 2) ? 8 : 0);
                int col = bN + wn * 32 + nt * 8 + tig * 2 + (e & 1);
                if (row < M && col < N) {
                    float v = c[mt][nt][e];
                    if (EPI == 2)             v += ADD[(size_t)row * N + col];
                    if (EPI == 3 || EPI == 4) v += bias[col];
                    if (EPI == 1 || EPI == 2 || EPI == 4) v = fmaxf(v, 0.f);
                    C[(size_t)row * N + col] = v;
                    if (DUAL) C2[(size_t)row * N + col] = v;
                }
            }
}

// ======================= float4 gather/pointwise helpers =======================
#define HD4 (HD / 4)   /* 75 */

__device__ __forceinline__ float4 f4max(float4 a, float4 b) {
    return make_float4(fmaxf(a.x,b.x), fmaxf(a.y,b.y), fmaxf(a.z,b.z), fmaxf(a.w,b.w));
}
__device__ __forceinline__ float4 f4add(float4 a, float4 b) {
    return make_float4(a.x+b.x, a.y+b.y, a.z+b.z, a.w+b.w);
}

__global__ void agg_update_kernel(const float* __restrict__ mbond, const int* __restrict__ a2b,
                                  float* __restrict__ matom)
{
    int idx = blockIdx.x * blockDim.x + threadIdx.x;
    if (idx >= NATOMS * HD4) return;
    int a = idx / HD4, h4 = idx - a * HD4;
    float4 s  = make_float4(0.f, 0.f, 0.f, 0.f);
    float4 mx = make_float4(-INFINITY, -INFINITY, -INFINITY, -INFINITY);
    #pragma unroll
    for (int j = 0; j < NNB; j++) {
        int b = __ldg(&a2b[a * NNB + j]);
        float4 v = __ldg((const float4*)&mbond[b * HD] + h4);
        s = f4add(s, v); mx = f4max(mx, v);
    }
    float4* dst = (float4*)&matom[a * HD] + h4;
    float4 cur = *dst;
    cur.x += s.x * mx.x; cur.y += s.y * mx.y; cur.z += s.z * mx.z; cur.w += s.w * mx.w;
    *dst = cur;
}

__global__ void final_concat_kernel(const float* __restrict__ mbond, const int* __restrict__ a2b,
                                    const float* __restrict__ matom, const float* __restrict__ iatom,
                                    float* __restrict__ cc)
{
    int idx = blockIdx.x * blockDim.x + threadIdx.x;
    if (idx >= NSEQ * HD4) return;
    int row = idx / HD4, h4 = idx - row * HD4;
    int a = row + 1;
    float4 s  = make_float4(0.f, 0.f, 0.f, 0.f);
    float4 mx = make_float4(-INFINITY, -INFINITY, -INFINITY, -INFINITY);
    #pragma unroll
    for (int j = 0; j < NNB; j++) {
        int b = __ldg(&a2b[a * NNB + j]);
        float4 v = __ldg((const float4*)&mbond[b * HD] + h4);
        s = f4add(s, v); mx = f4max(mx, v);
    }
    float4 agg = make_float4(s.x*mx.x, s.y*mx.y, s.z*mx.z, s.w*mx.w);
    *((float4*)&cc[row * (3*HD)] + h4)            = agg;
    *((float4*)&cc[row * (3*HD) + HD] + h4)       = __ldg((const float4*)&matom[a * HD] + h4);
    *((float4*)&cc[row * (3*HD) + 2*HD] + h4)     = __ldg((const float4*)&iatom[a * HD] + h4);
}

__global__ void msg_kernel(const float* __restrict__ aggW, const float* __restrict__ gbias,
                           float* __restrict__ msg)
{
    int idx = blockIdx.x * blockDim.x + threadIdx.x;
    if (idx >= NSEQ * HD4) return;
    int h4 = idx % HD4;
    float4 v = __ldg((const float4*)aggW + idx);
    float4 b = __ldg((const float4*)gbias + h4);
    ((float4*)msg)[idx] = make_float4(fmaxf(v.x+b.x,0.f), fmaxf(v.y+b.y,0.f),
                                      fmaxf(v.z+b.z,0.f), fmaxf(v.w+b.w,0.f));
}

__global__ void h0_kernel(const float* __restrict__ aggW, float* __restrict__ h0)
{
    int idx = blockIdx.x * blockDim.x + threadIdx.x;
    if (idx >= NMOLS * HD4) return;
    int mol = idx / HD4, h4 = idx - mol * HD4;
    float4 mx = make_float4(-INFINITY, -INFINITY, -INFINITY, -INFINITY);
    for (int t = 0; t < ASIZE; t++)
        mx = f4max(mx, __ldg((const float4*)&aggW[(mol * ASIZE + t) * HD] + h4));
    ((float4*)h0)[idx] = mx;
}

__global__ void mean_kernel(const float* __restrict__ hid, float* __restrict__ out)
{
    int idx = blockIdx.x * blockDim.x + threadIdx.x;
    if (idx >= NMOLS * HD4) return;
    int mol = idx / HD4, h4 = idx - mol * HD4;
    float4 s = make_float4(0.f, 0.f, 0.f, 0.f);
    for (int t = 0; t < ASIZE; t++)
        s = f4add(s, __ldg((const float4*)&hid[(mol * ASIZE + t) * HD] + h4));
    ((float4*)out)[idx] = make_float4(s.x*(1.f/ASIZE), s.y*(1.f/ASIZE),
                                      s.z*(1.f/ASIZE), s.w*(1.f/ASIZE));
}

// ======================= fused bidirectional GRU (fp32) =======================
#define MPB 14   /* 72 blocks x 2 dirs = 144 <= 148 SMs, single wave */

__device__ __forceinline__ float sigmoidf_(float x) { return 1.f / (1.f + expf(-x)); }

__global__ __launch_bounds__(256)
void gru_fused(const float* __restrict__ xp_f, const float* __restrict__ xp_b,
               const float* __restrict__ Whh_f, const float* __restrict__ Whh_b,  // [3H, H]
               const float* __restrict__ bhh_f, const float* __restrict__ bhh_b,
               const float* __restrict__ h0, float* __restrict__ out)
{
    extern __shared__ float sm[];
    float* h_s  = sm;               // [MPB][304]
    float* gh_s = sm + MPB * 304;   // [MPB][912]

    const int tid  = threadIdx.x;
    const int dir  = blockIdx.y;
    const int mol0 = blockIdx.x * MPB;
    const int mc   = min(MPB, NMOLS - mol0);

    const float* xp  = dir ? xp_b  : xp_f;
    const float* Whh = dir ? Whh_b : Whh_f;
    const float* bhh = dir ? bhh_b : bhh_f;

    for (int i = tid; i < MPB * 304; i += 256) h_s[i] = 0.f;
    __syncthreads();
    for (int i = tid; i < mc * HD; i += 256) {
        int m = i / HD, hh = i - m * HD;
        h_s[m * 304 + hh] = h0[(mol0 + m) * HD + hh];
    }
    __syncthreads();

    const int c3ok = (tid + 768 < 3 * HD);

    for (int s = 0; s < ASIZE; s++) {
        const int t = dir ? (ASIZE - 1 - s) : s;

        float acc[4][MPB];
        #pragma unroll
        for (int j = 0; j < 4; j++)
            #pragma unroll
            for (int m = 0; m < MPB; m++) acc[j][m] = 0.f;

        for (int k = 0; k < HD; k += 4) {
            float4 w[4];
            #pragma unroll
            for (int j = 0; j < 3; j++)
                w[j] = *(const float4*)&Whh[(tid + j * 256) * HD + k];
            w[3] = c3ok ? *(const float4*)&Whh[(tid + 768) * HD + k]
                        : make_float4(0.f, 0.f, 0.f, 0.f);
            #pragma unroll
            for (int m = 0; m < MPB; m++) {
                float4 hv = *(const float4*)&h_s[m * 304 + k];
                #pragma unroll
                for (int j = 0; j < 4; j++) {
                    acc[j][m] = fmaf(w[j].x, hv.x, acc[j][m]);
                    acc[j][m] = fmaf(w[j].y, hv.y, acc[j][m]);
                    acc[j][m] = fmaf(w[j].z, hv.z, acc[j][m]);
                    acc[j][m] = fmaf(w[j].w, hv.w, acc[j][m]);
                }
            }
        }
        #pragma unroll
        for (int j = 0; j < 4; j++) {
            int cc = tid + j * 256;
            if (cc < 3 * HD) {
                float bb = bhh[cc];
                #pragma unroll
                for (int m = 0; m < MPB; m++)
                    gh_s[m * 912 + cc] = acc[j][m] + bb;
            }
        }
        __syncthreads();

        for (int i = tid; i < mc * HD; i += 256) {
            int m = i / HD, hh = i - m * HD;
            int row = (mol0 + m) * ASIZE + t;
            float ir = xp[row * (3*HD) + hh];
            float iz = xp[row * (3*HD) + HD + hh];
            float in = xp[row * (3*HD) + 2*HD + hh];
            float hr = gh_s[m * 912 + hh];
            float hz = gh_s[m * 912 + HD + hh];
            float hn = gh_s[m * 912 + 2*HD + hh];
            float r = sigmoidf_(ir + hr);
            float z = sigmoidf_(iz + hz);
            float n = tanhf(in + r * hn);
            float hp = h_s[m * 304 + hh];
            float hnew = (1.f - z) * n + z * hp;
            h_s[m * 304 + hh] = hnew;
            out[row * (2*HD) + dir * HD + hh] = hnew;
        }
        __syncthreads();
    }
}

// ======================= host orchestration =======================
static inline dim3 mma_grid(int M, int N) { return dim3((N + 63) / 64, (M + 127) / 128); }
static inline int  blocks_for(int n)      { return (n + 255) / 256; }

extern "C" void kernel_launch(void* const* d_in, const int* in_sizes, int n_in,
                              void* d_out, int out_size)
{
    const float* f_atoms  = (const float*)d_in[0];
    const float* f_bonds  = (const float*)d_in[1];
    const float* Wi_atom  = (const float*)d_in[2];
    const float* Wi_bond  = (const float*)d_in[3];
    const float* Wh0      = (const float*)d_in[4];
    const float* Wh1      = (const float*)d_in[5];
    const float* W_lr     = (const float*)d_in[6];
    const float* W_o      = (const float*)d_in[7];
    const float* b_o      = (const float*)d_in[8];
    const float* gru_bias = (const float*)d_in[9];
    const float* gWih_f   = (const float*)d_in[10];
    const float* gWhh_f   = (const float*)d_in[11];
    const float* gbih_f   = (const float*)d_in[12];
    const float* gbhh_f   = (const float*)d_in[13];
    const float* gWih_b   = (const float*)d_in[14];
    const float* gWhh_b   = (const float*)d_in[15];
    const float* gbih_b   = (const float*)d_in[16];
    const float* gbhh_b   = (const float*)d_in[17];
    const int*   a2b      = (const int*)d_in[18];
    const int*   b2a      = (const int*)d_in[19];
    const int*   b2revb   = (const int*)d_in[20];
    float* out = (float*)d_out;

    float *inA, *mA, *inB, *mB0, *mB1, *cc, *aggW, *msg, *xpf, *xpb, *h0, *gout, *hid;
    cudaGetSymbolAddress((void**)&inA,  g_input_atom);
    cudaGetSymbolAddress((void**)&mA,   g_message_atom);
    cudaGetSymbolAddress((void**)&inB,  g_input_bond);
    cudaGetSymbolAddress((void**)&mB0,  g_bondA);
    cudaGetSymbolAddress((void**)&mB1,  g_bondB);
    cudaGetSymbolAddress((void**)&cc,   g_concat);
    cudaGetSymbolAddress((void**)&aggW, g_aggW);
    cudaGetSymbolAddress((void**)&msg,  g_msg);
    cudaGetSymbolAddress((void**)&xpf,  g_xpf);
    cudaGetSymbolAddress((void**)&xpb,  g_xpb);
    cudaGetSymbolAddress((void**)&h0,   g_h0);
    cudaGetSymbolAddress((void**)&gout, g_out);
    cudaGetSymbolAddress((void**)&hid,  g_hid);

    const int gru_smem = (MPB * 304 + MPB * 912) * (int)sizeof(float);
    cudaFuncSetAttribute(gru_fused, cudaFuncAttributeMaxDynamicSharedMemorySize, gru_smem);

    // 1. input_atom = relu(f_atoms @ Wi_atom); dual-store into message_atom
    mma_gemm<false, 1, true, false><<<mma_grid(NATOMS, HD), 256>>>(
        f_atoms, Wi_atom, nullptr, nullptr, inA, mA, nullptr, nullptr, nullptr, nullptr,
        NATOMS, HD, AFDIM);

    // 2. input_bond = relu(f_bonds @ Wi_bond); dual-store into bond-message ping (mB0)
    mma_gemm<false, 1, true, false><<<mma_grid(NBONDS, HD), 256>>>(
        f_bonds, Wi_bond, nullptr, nullptr, inB, mB0, nullptr, nullptr, nullptr, nullptr,
        NBONDS, HD, BFDIM);

    // 3. two message-passing steps; mb gather fused into GEMM A-loader.
    //    PING-PONG: gather source and GEMM output must be different buffers.
    agg_update_kernel<<<blocks_for(NATOMS * HD4), 256>>>(mB0, a2b, mA);
    mma_gemm<false, 2, false, true><<<mma_grid(NBONDS, HD), 256>>>(
        nullptr, Wh0, inB, nullptr, mB1, nullptr, b2a, b2revb, mA, mB0,
        NBONDS, HD, HD);
    agg_update_kernel<<<blocks_for(NATOMS * HD4), 256>>>(mB1, a2b, mA);
    mma_gemm<false, 2, false, true><<<mma_grid(NBONDS, HD), 256>>>(
        nullptr, Wh1, inB, nullptr, mB0, nullptr, b2a, b2revb, mA, mB1,
        NBONDS, HD, HD);

    // 4. final aggregation + concat + W_lr  (reads mB0; atom rows 1..NSEQ)
    final_concat_kernel<<<blocks_for(NSEQ * HD4), 256>>>(mB0, a2b, mA, inA, cc);
    mma_gemm<false, 0, false, false><<<mma_grid(NSEQ, HD), 256>>>(
        cc, W_lr, nullptr, nullptr, aggW, nullptr, nullptr, nullptr, nullptr, nullptr,
        NSEQ, HD, 3 * HD);

    // 5. BatchGRU prep
    msg_kernel<<<blocks_for(NSEQ * HD4), 256>>>(aggW, gru_bias, msg);
    h0_kernel<<<blocks_for(NMOLS * HD4), 256>>>(aggW, h0);

    // input projections: xp = msg @ Wih^T + bih
    mma_gemm<true, 3, false, false><<<mma_grid(NSEQ, 3 * HD), 256>>>(
        msg, gWih_f, nullptr, gbih_f, xpf, nullptr, nullptr, nullptr, nullptr, nullptr,
        NSEQ, 3 * HD, HD);
    mma_gemm<true, 3, false, false><<<mma_grid(NSEQ, 3 * HD), 256>>>(
        msg, gWih_b, nullptr, gbih_b, xpb, nullptr, nullptr, nullptr, nullptr, nullptr,
        NSEQ, 3 * HD, HD);

    // 6+7. both GRU directions, all 40 steps, one kernel
    {
        dim3 grid((NMOLS + MPB - 1) / MPB, 2);
        gru_fused<<<grid, 256, gru_smem>>>(xpf, xpb, gWhh_f, gWhh_b, gbhh_f, gbhh_b, h0, gout);
    }

    // 8. atom_hiddens = relu(out @ W_o + b_o); mol_vecs = per-mol mean
    mma_gemm<false, 4, false, false><<<mma_grid(NSEQ, HD), 256>>>(
        gout, W_o, nullptr, b_o, hid, nullptr, nullptr, nullptr, nullptr, nullptr,
        NSEQ, HD, 2 * HD);
    mean_kernel<<<blocks_for(NMOLS * HD4), 256>>>(hid, out);
}

// round 10
// speedup vs baseline: 1.5968x; 1.0213x over previous
#include <cuda_runtime.h>
#include <math.h>
#include <stdint.h>

#define NATOMS 40001
#define NBONDS 160001
#define NNB    6
#define AFDIM  133
#define BFDIM  147
#define HD     300
#define NMOLS  1000
#define ASIZE  40
#define NSEQ   (NMOLS * ASIZE)   /* 40000 */

// ---------------- scratch (static device globals; no runtime allocation) ----------------
__device__ float g_input_atom  [NATOMS * HD];
__device__ float g_message_atom[NATOMS * HD];
__device__ float g_input_bond  [NBONDS * HD];
__device__ float g_bondA       [NBONDS * HD];   // bond-message ping
__device__ float g_bondB       [NBONDS * HD];   // bond-message pong
__device__ float g_concat      [NSEQ * 3 * HD];
__device__ float g_aggW        [NSEQ * HD];
__device__ float g_msg         [NSEQ * HD];
__device__ float g_xpf         [NSEQ * 3 * HD];
__device__ float g_xpb         [NSEQ * 3 * HD];
__device__ float g_h0          [NMOLS * HD];
__device__ float g_out         [NSEQ * 2 * HD];
__device__ float g_hid         [NSEQ * HD];

// ======================= 3xTF32 split-precision tensor-core GEMM =======================
// (unchanged from round 9 — asymmetric split placement, occupancy-capped)

__device__ __forceinline__ void mma_tf32(float c[4], const uint32_t a[4], const uint32_t b[2]) {
    asm volatile(
        "mma.sync.aligned.m16n8k8.row.col.f32.tf32.tf32.f32 "
        "{%0,%1,%2,%3}, {%4,%5,%6,%7}, {%8,%9}, {%0,%1,%2,%3};"
        : "+f"(c[0]), "+f"(c[1]), "+f"(c[2]), "+f"(c[3])
        : "r"(a[0]), "r"(a[1]), "r"(a[2]), "r"(a[3]), "r"(b[0]), "r"(b[1]));
}

__device__ __forceinline__ float f2tf32(float v) {
    uint32_t t;
    asm("cvt.rna.tf32.f32 %0, %1;" : "=r"(t) : "f"(v));
    return __uint_as_float(t);
}

__device__ __forceinline__ void split_tf32(float v, uint32_t& hi, uint32_t& lo) {
    float h = f2tf32(v);
    hi = __float_as_uint(h);
    lo = __float_as_uint(f2tf32(v - h));
}

template<bool TRANSB, int EPI, bool DUAL, bool GATHER>
__global__ __launch_bounds__(256, 3)
void mma_gemm(const float* __restrict__ A, const float* __restrict__ B,
              const float* __restrict__ ADD, const float* __restrict__ bias,
              float* __restrict__ C, float* __restrict__ C2,
              const int* __restrict__ idxA, const int* __restrict__ idxB,
              const float* __restrict__ GA, const float* __restrict__ GB,
              int M, int N, int K)
{
    __shared__ float As[128][20];   // [m][k] raw fp32
    __shared__ float Bh[16][68];    // [k][n] tf32 hi
    __shared__ float Bl[16][68];    // [k][n] tf32 lo

    const int tid  = threadIdx.x;
    const int warp = tid >> 5, lane = tid & 31;
    const int wm   = warp & 3, wn = warp >> 2;
    const int gid  = lane >> 2, tig = lane & 3;
    const int bM   = blockIdx.y * 128, bN = blockIdx.x * 64;

    const int aRow = tid >> 2;
    const int aCol = (tid & 3) * 4;

    float aR[8], bR[4];
    float c[2][4][4] = {};

    const int nCh = (K + 15) >> 4;

    auto loadA = [&](int kt) {
        #pragma unroll
        for (int r = 0; r < 2; r++) {
            int gm  = bM + aRow + 64 * r;
            int gk0 = kt + aCol;
            if (GATHER) {
                if (gm < M) {
                    int ia = __ldg(&idxA[gm]);
                    int ib = __ldg(&idxB[gm]);
                    if (gk0 + 3 < K) {
                        float4 va = __ldg((const float4*)&GA[(size_t)ia * K + gk0]);
                        float4 vb = __ldg((const float4*)&GB[(size_t)ib * K + gk0]);
                        aR[r*4+0] = va.x - vb.x; aR[r*4+1] = va.y - vb.y;
                        aR[r*4+2] = va.z - vb.z; aR[r*4+3] = va.w - vb.w;
                    } else {
                        #pragma unroll
                        for (int i = 0; i < 4; i++) {
                            int gk = gk0 + i;
                            aR[r*4+i] = (gk < K)
                                ? __ldg(&GA[(size_t)ia * K + gk]) - __ldg(&GB[(size_t)ib * K + gk])
                                : 0.f;
                        }
                    }
                } else {
                    #pragma unroll
                    for (int i = 0; i < 4; i++) aR[r*4+i] = 0.f;
                }
            } else {
                #pragma unroll
                for (int i = 0; i < 4; i++) {
                    int gk = gk0 + i;
                    aR[r*4+i] = (gm < M && gk < K) ? A[(size_t)gm * K + gk] : 0.f;
                }
            }
        }
    };
    auto loadB = [&](int kt) {
        if (!TRANSB) {
            int k = tid >> 4, n0 = (tid & 15) * 4;
            #pragma unroll
            for (int i = 0; i < 4; i++) {
                int gk = kt + k, gn = bN + n0 + i;
                bR[i] = (gk < K && gn < N) ? B[(size_t)gk * N + gn] : 0.f;
            }
        } else {
            int n = tid >> 2, k0 = (tid & 3) * 4;
            #pragma unroll
            for (int i = 0; i < 4; i++) {
                int gk = kt + k0 + i, gn = bN + n;
                bR[i] = (gk < K && gn < N) ? B[(size_t)gn * K + gk] : 0.f;
            }
        }
    };

    loadA(0);
    loadB(0);

    for (int ch = 0; ch < nCh; ch++) {
        #pragma unroll
        for (int r = 0; r < 2; r++)
            *(float4*)&As[aRow + 64*r][aCol] =
                make_float4(aR[r*4+0], aR[r*4+1], aR[r*4+2], aR[r*4+3]);
        if (!TRANSB) {
            int k = tid >> 4, n0 = (tid & 15) * 4;
            float4 h, l;
            h.x = f2tf32(bR[0]); l.x = f2tf32(bR[0] - h.x);
            h.y = f2tf32(bR[1]); l.y = f2tf32(bR[1] - h.y);
            h.z = f2tf32(bR[2]); l.z = f2tf32(bR[2] - h.z);
            h.w = f2tf32(bR[3]); l.w = f2tf32(bR[3] - h.w);
            *(float4*)&Bh[k][n0] = h;
            *(float4*)&Bl[k][n0] = l;
        } else {
            int n = tid >> 2, k0 = (tid & 3) * 4;
            #pragma unroll
            for (int i = 0; i < 4; i++) {
                float h = f2tf32(bR[i]);
                Bh[k0 + i][n] = h;
                Bl[k0 + i][n] = f2tf32(bR[i] - h);
            }
        }
        __syncthreads();

        if (ch + 1 < nCh) {
            loadA((ch + 1) << 4);
            loadB((ch + 1) << 4);
        }

        #pragma unroll
        for (int kk = 0; kk < 16; kk += 8) {
            uint32_t ah[2][4], al[2][4], bh_[4][2], bl_[4][2];
            #pragma unroll
            for (int mt = 0; mt < 2; mt++) {
                int m0 = wm * 32 + mt * 16 + gid;
                split_tf32(As[m0    ][kk + tig    ], ah[mt][0], al[mt][0]);
                split_tf32(As[m0 + 8][kk + tig    ], ah[mt][1], al[mt][1]);
                split_tf32(As[m0    ][kk + tig + 4], ah[mt][2], al[mt][2]);
                split_tf32(As[m0 + 8][kk + tig + 4], ah[mt][3], al[mt][3]);
            }
            #pragma unroll
            for (int nt = 0; nt < 4; nt++) {
                int n0 = wn * 32 + nt * 8 + gid;
                bh_[nt][0] = __float_as_uint(Bh[kk + tig    ][n0]);
                bh_[nt][1] = __float_as_uint(Bh[kk + tig + 4][n0]);
                bl_[nt][0] = __float_as_uint(Bl[kk + tig    ][n0]);
                bl_[nt][1] = __float_as_uint(Bl[kk + tig + 4][n0]);
            }
            #pragma unroll
            for (int mt = 0; mt < 2; mt++)
                #pragma unroll
                for (int nt = 0; nt < 4; nt++) {
                    mma_tf32(c[mt][nt], ah[mt], bl_[nt]);
                    mma_tf32(c[mt][nt], al[mt], bh_[nt]);
                    mma_tf32(c[mt][nt], ah[mt], bh_[nt]);
                }
        }
        __syncthreads();
    }

    #pragma unroll
    for (int mt = 0; mt < 2; mt++)
        #pragma unroll
        for (int nt = 0; nt < 4; nt++)
            #pragma unroll
            for (int e = 0; e < 4; e++) {
                int row = bM + wm * 32 + mt * 16 + gid + ((e >= 2) ? 8 : 0);
                int col = bN + wn * 32 + nt * 8 + tig * 2 + (e & 1);
                if (row < M && col < N) {
                    float v = c[mt][nt][e];
                    if (EPI == 2)             v += ADD[(size_t)row * N + col];
                    if (EPI == 3 || EPI == 4) v += bias[col];
                    if (EPI == 1 || EPI == 2 || EPI == 4) v = fmaxf(v, 0.f);
                    C[(size_t)row * N + col] = v;
                    if (DUAL) C2[(size_t)row * N + col] = v;
                }
            }
}

// ======================= float4 gather/pointwise helpers =======================
#define HD4 (HD / 4)   /* 75 */

__device__ __forceinline__ float4 f4max(float4 a, float4 b) {
    return make_float4(fmaxf(a.x,b.x), fmaxf(a.y,b.y), fmaxf(a.z,b.z), fmaxf(a.w,b.w));
}
__device__ __forceinline__ float4 f4add(float4 a, float4 b) {
    return make_float4(a.x+b.x, a.y+b.y, a.z+b.z, a.w+b.w);
}

__global__ void agg_update_kernel(const float* __restrict__ mbond, const int* __restrict__ a2b,
                                  float* __restrict__ matom)
{
    int idx = blockIdx.x * blockDim.x + threadIdx.x;
    if (idx >= NATOMS * HD4) return;
    int a = idx / HD4, h4 = idx - a * HD4;
    float4 s  = make_float4(0.f, 0.f, 0.f, 0.f);
    float4 mx = make_float4(-INFINITY, -INFINITY, -INFINITY, -INFINITY);
    #pragma unroll
    for (int j = 0; j < NNB; j++) {
        int b = __ldg(&a2b[a * NNB + j]);
        float4 v = __ldg((const float4*)&mbond[b * HD] + h4);
        s = f4add(s, v); mx = f4max(mx, v);
    }
    float4* dst = (float4*)&matom[a * HD] + h4;
    float4 cur = *dst;
    cur.x += s.x * mx.x; cur.y += s.y * mx.y; cur.z += s.z * mx.z; cur.w += s.w * mx.w;
    *dst = cur;
}

__global__ void final_concat_kernel(const float* __restrict__ mbond, const int* __restrict__ a2b,
                                    const float* __restrict__ matom, const float* __restrict__ iatom,
                                    float* __restrict__ cc)
{
    int idx = blockIdx.x * blockDim.x + threadIdx.x;
    if (idx >= NSEQ * HD4) return;
    int row = idx / HD4, h4 = idx - row * HD4;
    int a = row + 1;
    float4 s  = make_float4(0.f, 0.f, 0.f, 0.f);
    float4 mx = make_float4(-INFINITY, -INFINITY, -INFINITY, -INFINITY);
    #pragma unroll
    for (int j = 0; j < NNB; j++) {
        int b = __ldg(&a2b[a * NNB + j]);
        float4 v = __ldg((const float4*)&mbond[b * HD] + h4);
        s = f4add(s, v); mx = f4max(mx, v);
    }
    float4 agg = make_float4(s.x*mx.x, s.y*mx.y, s.z*mx.z, s.w*mx.w);
    *((float4*)&cc[row * (3*HD)] + h4)            = agg;
    *((float4*)&cc[row * (3*HD) + HD] + h4)       = __ldg((const float4*)&matom[a * HD] + h4);
    *((float4*)&cc[row * (3*HD) + 2*HD] + h4)     = __ldg((const float4*)&iatom[a * HD] + h4);
}

__global__ void msg_kernel(const float* __restrict__ aggW, const float* __restrict__ gbias,
                           float* __restrict__ msg)
{
    int idx = blockIdx.x * blockDim.x + threadIdx.x;
    if (idx >= NSEQ * HD4) return;
    int h4 = idx % HD4;
    float4 v = __ldg((const float4*)aggW + idx);
    float4 b = __ldg((const float4*)gbias + h4);
    ((float4*)msg)[idx] = make_float4(fmaxf(v.x+b.x,0.f), fmaxf(v.y+b.y,0.f),
                                      fmaxf(v.z+b.z,0.f), fmaxf(v.w+b.w,0.f));
}

__global__ void h0_kernel(const float* __restrict__ aggW, float* __restrict__ h0)
{
    int idx = blockIdx.x * blockDim.x + threadIdx.x;
    if (idx >= NMOLS * HD4) return;
    int mol = idx / HD4, h4 = idx - mol * HD4;
    float4 mx = make_float4(-INFINITY, -INFINITY, -INFINITY, -INFINITY);
    for (int t = 0; t < ASIZE; t++)
        mx = f4max(mx, __ldg((const float4*)&aggW[(mol * ASIZE + t) * HD] + h4));
    ((float4*)h0)[idx] = mx;
}

__global__ void mean_kernel(const float* __restrict__ hid, float* __restrict__ out)
{
    int idx = blockIdx.x * blockDim.x + threadIdx.x;
    if (idx >= NMOLS * HD4) return;
    int mol = idx / HD4, h4 = idx - mol * HD4;
    float4 s = make_float4(0.f, 0.f, 0.f, 0.f);
    for (int t = 0; t < ASIZE; t++)
        s = f4add(s, __ldg((const float4*)&hid[(mol * ASIZE + t) * HD] + h4));
    ((float4*)out)[idx] = make_float4(s.x*(1.f/ASIZE), s.y*(1.f/ASIZE),
                                      s.z*(1.f/ASIZE), s.w*(1.f/ASIZE));
}

// ======================= fused bidirectional GRU (packed f32x2 FMA) =======================
// Matvec gh = h @ Whh^T now uses Blackwell fma.rn.f32x2: adjacent k-pairs packed into
// 64-bit registers (both Whh rows and h_s rows are k-contiguous, 16B aligned), halving
// FMA instruction count (128 MAC/cyc/SM vs 64). Packed pair accumulators, horizontal
// add at the end (pairwise summation; fp32 throughout).
#define MPB 14   /* 72 blocks x 2 dirs = 144 <= 148 SMs, single wave */

__device__ __forceinline__ float sigmoidf_(float x) { return 1.f / (1.f + expf(-x)); }

__device__ __forceinline__ void fma2(uint64_t& d, uint64_t a, uint64_t b) {
    asm("fma.rn.f32x2 %0, %1, %2, %0;" : "+l"(d) : "l"(a), "l"(b));
}

__global__ __launch_bounds__(256)
void gru_fused(const float* __restrict__ xp_f, const float* __restrict__ xp_b,
               const float* __restrict__ Whh_f, const float* __restrict__ Whh_b,  // [3H, H]
               const float* __restrict__ bhh_f, const float* __restrict__ bhh_b,
               const float* __restrict__ h0, float* __restrict__ out)
{
    extern __shared__ float sm[];
    float* h_s  = sm;               // [MPB][304]
    float* gh_s = sm + MPB * 304;   // [MPB][912]

    const int tid  = threadIdx.x;
    const int dir  = blockIdx.y;
    const int mol0 = blockIdx.x * MPB;
    const int mc   = min(MPB, NMOLS - mol0);

    const float* xp  = dir ? xp_b  : xp_f;
    const float* Whh = dir ? Whh_b : Whh_f;
    const float* bhh = dir ? bhh_b : bhh_f;

    for (int i = tid; i < MPB * 304; i += 256) h_s[i] = 0.f;
    __syncthreads();
    for (int i = tid; i < mc * HD; i += 256) {
        int m = i / HD, hh = i - m * HD;
        h_s[m * 304 + hh] = h0[(mol0 + m) * HD + hh];
    }
    __syncthreads();

    const int c3ok = (tid + 768 < 3 * HD);

    for (int s = 0; s < ASIZE; s++) {
        const int t = dir ? (ASIZE - 1 - s) : s;

        // packed pair accumulators: acc[j][m] holds {sum_even_k, sum_odd_k}
        uint64_t acc[4][MPB];
        #pragma unroll
        for (int j = 0; j < 4; j++)
            #pragma unroll
            for (int m = 0; m < MPB; m++) acc[j][m] = 0ull;   // bits 0 == {0.f, 0.f}

        for (int k = 0; k < HD; k += 4) {
            // each 16B load = 2 packed f32x2 operands {k,k+1},{k+2,k+3}
            ulonglong2 w[4];
            #pragma unroll
            for (int j = 0; j < 3; j++)
                w[j] = *(const ulonglong2*)&Whh[(tid + j * 256) * HD + k];
            w[3] = c3ok ? *(const ulonglong2*)&Whh[(tid + 768) * HD + k]
                        : make_ulonglong2(0ull, 0ull);
            #pragma unroll
            for (int m = 0; m < MPB; m++) {
                ulonglong2 hv = *(const ulonglong2*)&h_s[m * 304 + k];
                #pragma unroll
                for (int j = 0; j < 4; j++) {
                    fma2(acc[j][m], w[j].x, hv.x);
                    fma2(acc[j][m], w[j].y, hv.y);
                }
            }
        }
        #pragma unroll
        for (int j = 0; j < 4; j++) {
            int cc = tid + j * 256;
            if (cc < 3 * HD) {
                float bb = bhh[cc];
                #pragma unroll
                for (int m = 0; m < MPB; m++) {
                    float2 p = *reinterpret_cast<float2*>(&acc[j][m]);
                    gh_s[m * 912 + cc] = p.x + p.y + bb;
                }
            }
        }
        __syncthreads();

        for (int i = tid; i < mc * HD; i += 256) {
            int m = i / HD, hh = i - m * HD;
            int row = (mol0 + m) * ASIZE + t;
            float ir = xp[row * (3*HD) + hh];
            float iz = xp[row * (3*HD) + HD + hh];
            float in = xp[row * (3*HD) + 2*HD + hh];
            float hr = gh_s[m * 912 + hh];
            float hz = gh_s[m * 912 + HD + hh];
            float hn = gh_s[m * 912 + 2*HD + hh];
            float r = sigmoidf_(ir + hr);
            float z = sigmoidf_(iz + hz);
            float n = tanhf(in + r * hn);
            float hp = h_s[m * 304 + hh];
            float hnew = (1.f - z) * n + z * hp;
            h_s[m * 304 + hh] = hnew;
            out[row * (2*HD) + dir * HD + hh] = hnew;
        }
        __syncthreads();
    }
}

// ======================= host orchestration =======================
static inline dim3 mma_grid(int M, int N) { return dim3((N + 63) / 64, (M + 127) / 128); }
static inline int  blocks_for(int n)      { return (n + 255) / 256; }

extern "C" void kernel_launch(void* const* d_in, const int* in_sizes, int n_in,
                              void* d_out, int out_size)
{
    const float* f_atoms  = (const float*)d_in[0];
    const float* f_bonds  = (const float*)d_in[1];
    const float* Wi_atom  = (const float*)d_in[2];
    const float* Wi_bond  = (const float*)d_in[3];
    const float* Wh0      = (const float*)d_in[4];
    const float* Wh1      = (const float*)d_in[5];
    const float* W_lr     = (const float*)d_in[6];
    const float* W_o      = (const float*)d_in[7];
    const float* b_o      = (const float*)d_in[8];
    const float* gru_bias = (const float*)d_in[9];
    const float* gWih_f   = (const float*)d_in[10];
    const float* gWhh_f   = (const float*)d_in[11];
    const float* gbih_f   = (const float*)d_in[12];
    const float* gbhh_f   = (const float*)d_in[13];
    const float* gWih_b   = (const float*)d_in[14];
    const float* gWhh_b   = (const float*)d_in[15];
    const float* gbih_b   = (const float*)d_in[16];
    const float* gbhh_b   = (const float*)d_in[17];
    const int*   a2b      = (const int*)d_in[18];
    const int*   b2a      = (const int*)d_in[19];
    const int*   b2revb   = (const int*)d_in[20];
    float* out = (float*)d_out;

    float *inA, *mA, *inB, *mB0, *mB1, *cc, *aggW, *msg, *xpf, *xpb, *h0, *gout, *hid;
    cudaGetSymbolAddress((void**)&inA,  g_input_atom);
    cudaGetSymbolAddress((void**)&mA,   g_message_atom);
    cudaGetSymbolAddress((void**)&inB,  g_input_bond);
    cudaGetSymbolAddress((void**)&mB0,  g_bondA);
    cudaGetSymbolAddress((void**)&mB1,  g_bondB);
    cudaGetSymbolAddress((void**)&cc,   g_concat);
    cudaGetSymbolAddress((void**)&aggW, g_aggW);
    cudaGetSymbolAddress((void**)&msg,  g_msg);
    cudaGetSymbolAddress((void**)&xpf,  g_xpf);
    cudaGetSymbolAddress((void**)&xpb,  g_xpb);
    cudaGetSymbolAddress((void**)&h0,   g_h0);
    cudaGetSymbolAddress((void**)&gout, g_out);
    cudaGetSymbolAddress((void**)&hid,  g_hid);

    const int gru_smem = (MPB * 304 + MPB * 912) * (int)sizeof(float);
    cudaFuncSetAttribute(gru_fused, cudaFuncAttributeMaxDynamicSharedMemorySize, gru_smem);

    // 1. input_atom = relu(f_atoms @ Wi_atom); dual-store into message_atom
    mma_gemm<false, 1, true, false><<<mma_grid(NATOMS, HD), 256>>>(
        f_atoms, Wi_atom, nullptr, nullptr, inA, mA, nullptr, nullptr, nullptr, nullptr,
        NATOMS, HD, AFDIM);

    // 2. input_bond = relu(f_bonds @ Wi_bond); dual-store into bond-message ping (mB0)
    mma_gemm<false, 1, true, false><<<mma_grid(NBONDS, HD), 256>>>(
        f_bonds, Wi_bond, nullptr, nullptr, inB, mB0, nullptr, nullptr, nullptr, nullptr,
        NBONDS, HD, BFDIM);

    // 3. two message-passing steps; mb gather fused into GEMM A-loader (ping-pong).
    agg_update_kernel<<<blocks_for(NATOMS * HD4), 256>>>(mB0, a2b, mA);
    mma_gemm<false, 2, false, true><<<mma_grid(NBONDS, HD), 256>>>(
        nullptr, Wh0, inB, nullptr, mB1, nullptr, b2a, b2revb, mA, mB0,
        NBONDS, HD, HD);
    agg_update_kernel<<<blocks_for(NATOMS * HD4), 256>>>(mB1, a2b, mA);
    mma_gemm<false, 2, false, true><<<mma_grid(NBONDS, HD), 256>>>(
        nullptr, Wh1, inB, nullptr, mB0, nullptr, b2a, b2revb, mA, mB1,
        NBONDS, HD, HD);

    // 4. final aggregation + concat + W_lr  (reads mB0; atom rows 1..NSEQ)
    final_concat_kernel<<<blocks_for(NSEQ * HD4), 256>>>(mB0, a2b, mA, inA, cc);
    mma_gemm<false, 0, false, false><<<mma_grid(NSEQ, HD), 256>>>(
        cc, W_lr, nullptr, nullptr, aggW, nullptr, nullptr, nullptr, nullptr, nullptr,
        NSEQ, HD, 3 * HD);

    // 5. BatchGRU prep
    msg_kernel<<<blocks_for(NSEQ * HD4), 256>>>(aggW, gru_bias, msg);
    h0_kernel<<<blocks_for(NMOLS * HD4), 256>>>(aggW, h0);

    // input projections: xp = msg @ Wih^T + bih
    mma_gemm<true, 3, false, false><<<mma_grid(NSEQ, 3 * HD), 256>>>(
        msg, gWih_f, nullptr, gbih_f, xpf, nullptr, nullptr, nullptr, nullptr, nullptr,
        NSEQ, 3 * HD, HD);
    mma_gemm<true, 3, false, false><<<mma_grid(NSEQ, 3 * HD), 256>>>(
        msg, gWih_b, nullptr, gbih_b, xpb, nullptr, nullptr, nullptr, nullptr, nullptr,
        NSEQ, 3 * HD, HD);

    // 6+7. both GRU directions, all 40 steps, one kernel
    {
        dim3 grid((NMOLS + MPB - 1) / MPB, 2);
        gru_fused<<<grid, 256, gru_smem>>>(xpf, xpb, gWhh_f, gWhh_b, gbhh_f, gbhh_b, h0, gout);
    }

    // 8. atom_hiddens = relu(out @ W_o + b_o); mol_vecs = per-mol mean
    mma_gemm<false, 4, false, false><<<mma_grid(NSEQ, HD), 256>>>(
        gout, W_o, nullptr, b_o, hid, nullptr, nullptr, nullptr, nullptr, nullptr,
        NSEQ, HD, 2 * HD);
    mean_kernel<<<blocks_for(NMOLS * HD4), 256>>>(hid, out);
}

// round 11
// speedup vs baseline: 1.6381x; 1.0259x over previous
#include <cuda_runtime.h>
#include <math.h>
#include <stdint.h>

#define NATOMS 40001
#define NBONDS 160001
#define NNB    6
#define AFDIM  133
#define BFDIM  147
#define HD     300
#define NMOLS  1000
#define ASIZE  40
#define NSEQ   (NMOLS * ASIZE)   /* 40000 */

// ---------------- scratch (static device globals; no runtime allocation) ----------------
__device__ float g_input_atom  [NATOMS * HD];
__device__ float g_message_atom[NATOMS * HD];
__device__ float g_input_bond  [NBONDS * HD];
__device__ float g_bondA       [NBONDS * HD];   // bond-message ping
__device__ float g_bondB       [NBONDS * HD];   // bond-message pong
__device__ float g_concat      [NSEQ * 3 * HD];
__device__ float g_aggW        [NSEQ * HD];
__device__ float g_msg         [NSEQ * HD];
__device__ float g_xpf         [NSEQ * 3 * HD];
__device__ float g_xpb         [NSEQ * 3 * HD];
__device__ float g_h0          [NMOLS * HD];
__device__ float g_out         [NSEQ * 2 * HD];
__device__ float g_hid         [NSEQ * HD];

// ======================= 3xTF32 split-precision tensor-core GEMM =======================
// Same as round 10 except B smem padding 68 -> 72: bank = tig*8+gid, fully
// disjoint across the 4 tig rows -> conflict-free B fragment LDS (was 2-way).

__device__ __forceinline__ void mma_tf32(float c[4], const uint32_t a[4], const uint32_t b[2]) {
    asm volatile(
        "mma.sync.aligned.m16n8k8.row.col.f32.tf32.tf32.f32 "
        "{%0,%1,%2,%3}, {%4,%5,%6,%7}, {%8,%9}, {%0,%1,%2,%3};"
        : "+f"(c[0]), "+f"(c[1]), "+f"(c[2]), "+f"(c[3])
        : "r"(a[0]), "r"(a[1]), "r"(a[2]), "r"(a[3]), "r"(b[0]), "r"(b[1]));
}

__device__ __forceinline__ float f2tf32(float v) {
    uint32_t t;
    asm("cvt.rna.tf32.f32 %0, %1;" : "=r"(t) : "f"(v));
    return __uint_as_float(t);
}

__device__ __forceinline__ void split_tf32(float v, uint32_t& hi, uint32_t& lo) {
    float h = f2tf32(v);
    hi = __float_as_uint(h);
    lo = __float_as_uint(f2tf32(v - h));
}

#define BPAD 72

template<bool TRANSB, int EPI, bool DUAL, bool GATHER>
__global__ __launch_bounds__(256, 3)
void mma_gemm(const float* __restrict__ A, const float* __restrict__ B,
              const float* __restrict__ ADD, const float* __restrict__ bias,
              float* __restrict__ C, float* __restrict__ C2,
              const int* __restrict__ idxA, const int* __restrict__ idxB,
              const float* __restrict__ GA, const float* __restrict__ GB,
              int M, int N, int K)
{
    __shared__ float As[128][20];    // [m][k] raw fp32 (conflict-free)
    __shared__ float Bh[16][BPAD];   // [k][n] tf32 hi (conflict-free @72)
    __shared__ float Bl[16][BPAD];   // [k][n] tf32 lo

    const int tid  = threadIdx.x;
    const int warp = tid >> 5, lane = tid & 31;
    const int wm   = warp & 3, wn = warp >> 2;
    const int gid  = lane >> 2, tig = lane & 3;
    const int bM   = blockIdx.y * 128, bN = blockIdx.x * 64;

    const int aRow = tid >> 2;
    const int aCol = (tid & 3) * 4;

    float aR[8], bR[4];
    float c[2][4][4] = {};

    const int nCh = (K + 15) >> 4;

    auto loadA = [&](int kt) {
        #pragma unroll
        for (int r = 0; r < 2; r++) {
            int gm  = bM + aRow + 64 * r;
            int gk0 = kt + aCol;
            if (GATHER) {
                if (gm < M) {
                    int ia = __ldg(&idxA[gm]);
                    int ib = __ldg(&idxB[gm]);
                    if (gk0 + 3 < K) {
                        float4 va = __ldg((const float4*)&GA[(size_t)ia * K + gk0]);
                        float4 vb = __ldg((const float4*)&GB[(size_t)ib * K + gk0]);
                        aR[r*4+0] = va.x - vb.x; aR[r*4+1] = va.y - vb.y;
                        aR[r*4+2] = va.z - vb.z; aR[r*4+3] = va.w - vb.w;
                    } else {
                        #pragma unroll
                        for (int i = 0; i < 4; i++) {
                            int gk = gk0 + i;
                            aR[r*4+i] = (gk < K)
                                ? __ldg(&GA[(size_t)ia * K + gk]) - __ldg(&GB[(size_t)ib * K + gk])
                                : 0.f;
                        }
                    }
                } else {
                    #pragma unroll
                    for (int i = 0; i < 4; i++) aR[r*4+i] = 0.f;
                }
            } else {
                #pragma unroll
                for (int i = 0; i < 4; i++) {
                    int gk = gk0 + i;
                    aR[r*4+i] = (gm < M && gk < K) ? A[(size_t)gm * K + gk] : 0.f;
                }
            }
        }
    };
    auto loadB = [&](int kt) {
        if (!TRANSB) {
            int k = tid >> 4, n0 = (tid & 15) * 4;
            #pragma unroll
            for (int i = 0; i < 4; i++) {
                int gk = kt + k, gn = bN + n0 + i;
                bR[i] = (gk < K && gn < N) ? B[(size_t)gk * N + gn] : 0.f;
            }
        } else {
            int n = tid >> 2, k0 = (tid & 3) * 4;
            #pragma unroll
            for (int i = 0; i < 4; i++) {
                int gk = kt + k0 + i, gn = bN + n;
                bR[i] = (gk < K && gn < N) ? B[(size_t)gn * K + gk] : 0.f;
            }
        }
    };

    loadA(0);
    loadB(0);

    for (int ch = 0; ch < nCh; ch++) {
        #pragma unroll
        for (int r = 0; r < 2; r++)
            *(float4*)&As[aRow + 64*r][aCol] =
                make_float4(aR[r*4+0], aR[r*4+1], aR[r*4+2], aR[r*4+3]);
        if (!TRANSB) {
            int k = tid >> 4, n0 = (tid & 15) * 4;
            float4 h, l;
            h.x = f2tf32(bR[0]); l.x = f2tf32(bR[0] - h.x);
            h.y = f2tf32(bR[1]); l.y = f2tf32(bR[1] - h.y);
            h.z = f2tf32(bR[2]); l.z = f2tf32(bR[2] - h.z);
            h.w = f2tf32(bR[3]); l.w = f2tf32(bR[3] - h.w);
            *(float4*)&Bh[k][n0] = h;
            *(float4*)&Bl[k][n0] = l;
        } else {
            int n = tid >> 2, k0 = (tid & 3) * 4;
            #pragma unroll
            for (int i = 0; i < 4; i++) {
                float h = f2tf32(bR[i]);
                Bh[k0 + i][n] = h;
                Bl[k0 + i][n] = f2tf32(bR[i] - h);
            }
        }
        __syncthreads();

        if (ch + 1 < nCh) {
            loadA((ch + 1) << 4);
            loadB((ch + 1) << 4);
        }

        #pragma unroll
        for (int kk = 0; kk < 16; kk += 8) {
            uint32_t ah[2][4], al[2][4], bh_[4][2], bl_[4][2];
            #pragma unroll
            for (int mt = 0; mt < 2; mt++) {
                int m0 = wm * 32 + mt * 16 + gid;
                split_tf32(As[m0    ][kk + tig    ], ah[mt][0], al[mt][0]);
                split_tf32(As[m0 + 8][kk + tig    ], ah[mt][1], al[mt][1]);
                split_tf32(As[m0    ][kk + tig + 4], ah[mt][2], al[mt][2]);
                split_tf32(As[m0 + 8][kk + tig + 4], ah[mt][3], al[mt][3]);
            }
            #pragma unroll
            for (int nt = 0; nt < 4; nt++) {
                int n0 = wn * 32 + nt * 8 + gid;
                bh_[nt][0] = __float_as_uint(Bh[kk + tig    ][n0]);
                bh_[nt][1] = __float_as_uint(Bh[kk + tig + 4][n0]);
                bl_[nt][0] = __float_as_uint(Bl[kk + tig    ][n0]);
                bl_[nt][1] = __float_as_uint(Bl[kk + tig + 4][n0]);
            }
            #pragma unroll
            for (int mt = 0; mt < 2; mt++)
                #pragma unroll
                for (int nt = 0; nt < 4; nt++) {
                    mma_tf32(c[mt][nt], ah[mt], bl_[nt]);
                    mma_tf32(c[mt][nt], al[mt], bh_[nt]);
                    mma_tf32(c[mt][nt], ah[mt], bh_[nt]);
                }
        }
        __syncthreads();
    }

    #pragma unroll
    for (int mt = 0; mt < 2; mt++)
        #pragma unroll
        for (int nt = 0; nt < 4; nt++)
            #pragma unroll
            for (int e = 0; e < 4; e++) {
                int row = bM + wm * 32 + mt * 16 + gid + ((e >= 2) ? 8 : 0);
                int col = bN + wn * 32 + nt * 8 + tig * 2 + (e & 1);
                if (row < M && col < N) {
                    float v = c[mt][nt][e];
                    if (EPI == 2)             v += ADD[(size_t)row * N + col];
                    if (EPI == 3 || EPI == 4) v += bias[col];
                    if (EPI == 1 || EPI == 2 || EPI == 4) v = fmaxf(v, 0.f);
                    C[(size_t)row * N + col] = v;
                    if (DUAL) C2[(size_t)row * N + col] = v;
                }
            }
}

// ======================= float4 gather/pointwise helpers =======================
#define HD4 (HD / 4)   /* 75 */

__device__ __forceinline__ float4 f4max(float4 a, float4 b) {
    return make_float4(fmaxf(a.x,b.x), fmaxf(a.y,b.y), fmaxf(a.z,b.z), fmaxf(a.w,b.w));
}
__device__ __forceinline__ float4 f4add(float4 a, float4 b) {
    return make_float4(a.x+b.x, a.y+b.y, a.z+b.z, a.w+b.w);
}

__global__ void agg_update_kernel(const float* __restrict__ mbond, const int* __restrict__ a2b,
                                  float* __restrict__ matom)
{
    int idx = blockIdx.x * blockDim.x + threadIdx.x;
    if (idx >= NATOMS * HD4) return;
    int a = idx / HD4, h4 = idx - a * HD4;
    float4 s  = make_float4(0.f, 0.f, 0.f, 0.f);
    float4 mx = make_float4(-INFINITY, -INFINITY, -INFINITY, -INFINITY);
    #pragma unroll
    for (int j = 0; j < NNB; j++) {
        int b = __ldg(&a2b[a * NNB + j]);
        float4 v = __ldg((const float4*)&mbond[b * HD] + h4);
        s = f4add(s, v); mx = f4max(mx, v);
    }
    float4* dst = (float4*)&matom[a * HD] + h4;
    float4 cur = *dst;
    cur.x += s.x * mx.x; cur.y += s.y * mx.y; cur.z += s.z * mx.z; cur.w += s.w * mx.w;
    *dst = cur;
}

__global__ void final_concat_kernel(const float* __restrict__ mbond, const int* __restrict__ a2b,
                                    const float* __restrict__ matom, const float* __restrict__ iatom,
                                    float* __restrict__ cc)
{
    int idx = blockIdx.x * blockDim.x + threadIdx.x;
    if (idx >= NSEQ * HD4) return;
    int row = idx / HD4, h4 = idx - row * HD4;
    int a = row + 1;
    float4 s  = make_float4(0.f, 0.f, 0.f, 0.f);
    float4 mx = make_float4(-INFINITY, -INFINITY, -INFINITY, -INFINITY);
    #pragma unroll
    for (int j = 0; j < NNB; j++) {
        int b = __ldg(&a2b[a * NNB + j]);
        float4 v = __ldg((const float4*)&mbond[b * HD] + h4);
        s = f4add(s, v); mx = f4max(mx, v);
    }
    float4 agg = make_float4(s.x*mx.x, s.y*mx.y, s.z*mx.z, s.w*mx.w);
    *((float4*)&cc[row * (3*HD)] + h4)            = agg;
    *((float4*)&cc[row * (3*HD) + HD] + h4)       = __ldg((const float4*)&matom[a * HD] + h4);
    *((float4*)&cc[row * (3*HD) + 2*HD] + h4)     = __ldg((const float4*)&iatom[a * HD] + h4);
}

__global__ void msg_kernel(const float* __restrict__ aggW, const float* __restrict__ gbias,
                           float* __restrict__ msg)
{
    int idx = blockIdx.x * blockDim.x + threadIdx.x;
    if (idx >= NSEQ * HD4) return;
    int h4 = idx % HD4;
    float4 v = __ldg((const float4*)aggW + idx);
    float4 b = __ldg((const float4*)gbias + h4);
    ((float4*)msg)[idx] = make_float4(fmaxf(v.x+b.x,0.f), fmaxf(v.y+b.y,0.f),
                                      fmaxf(v.z+b.z,0.f), fmaxf(v.w+b.w,0.f));
}

__global__ void h0_kernel(const float* __restrict__ aggW, float* __restrict__ h0)
{
    int idx = blockIdx.x * blockDim.x + threadIdx.x;
    if (idx >= NMOLS * HD4) return;
    int mol = idx / HD4, h4 = idx - mol * HD4;
    float4 mx = make_float4(-INFINITY, -INFINITY, -INFINITY, -INFINITY);
    for (int t = 0; t < ASIZE; t++)
        mx = f4max(mx, __ldg((const float4*)&aggW[(mol * ASIZE + t) * HD] + h4));
    ((float4*)h0)[idx] = mx;
}

__global__ void mean_kernel(const float* __restrict__ hid, float* __restrict__ out)
{
    int idx = blockIdx.x * blockDim.x + threadIdx.x;
    if (idx >= NMOLS * HD4) return;
    int mol = idx / HD4, h4 = idx - mol * HD4;
    float4 s = make_float4(0.f, 0.f, 0.f, 0.f);
    for (int t = 0; t < ASIZE; t++)
        s = f4add(s, __ldg((const float4*)&hid[(mol * ASIZE + t) * HD] + h4));
    ((float4*)out)[idx] = make_float4(s.x*(1.f/ASIZE), s.y*(1.f/ASIZE),
                                      s.z*(1.f/ASIZE), s.w*(1.f/ASIZE));
}

// ======================= fused bidirectional GRU (packed f32x2 FMA) =======================
#define MPB 14   /* 72 blocks x 2 dirs = 144 <= 148 SMs, single wave */

__device__ __forceinline__ float sigmoidf_(float x) { return 1.f / (1.f + expf(-x)); }

__device__ __forceinline__ void fma2(uint64_t& d, uint64_t a, uint64_t b) {
    asm("fma.rn.f32x2 %0, %1, %2, %0;" : "+l"(d) : "l"(a), "l"(b));
}

__global__ __launch_bounds__(256)
void gru_fused(const float* __restrict__ xp_f, const float* __restrict__ xp_b,
               const float* __restrict__ Whh_f, const float* __restrict__ Whh_b,  // [3H, H]
               const float* __restrict__ bhh_f, const float* __restrict__ bhh_b,
               const float* __restrict__ h0, float* __restrict__ out)
{
    extern __shared__ float sm[];
    float* h_s  = sm;               // [MPB][304]
    float* gh_s = sm + MPB * 304;   // [MPB][912]

    const int tid  = threadIdx.x;
    const int dir  = blockIdx.y;
    const int mol0 = blockIdx.x * MPB;
    const int mc   = min(MPB, NMOLS - mol0);

    const float* xp  = dir ? xp_b  : xp_f;
    const float* Whh = dir ? Whh_b : Whh_f;
    const float* bhh = dir ? bhh_b : bhh_f;

    for (int i = tid; i < MPB * 304; i += 256) h_s[i] = 0.f;
    __syncthreads();
    for (int i = tid; i < mc * HD; i += 256) {
        int m = i / HD, hh = i - m * HD;
        h_s[m * 304 + hh] = h0[(mol0 + m) * HD + hh];
    }
    __syncthreads();

    const int c3ok = (tid + 768 < 3 * HD);

    for (int s = 0; s < ASIZE; s++) {
        const int t = dir ? (ASIZE - 1 - s) : s;

        uint64_t acc[4][MPB];
        #pragma unroll
        for (int j = 0; j < 4; j++)
            #pragma unroll
            for (int m = 0; m < MPB; m++) acc[j][m] = 0ull;

        for (int k = 0; k < HD; k += 4) {
            ulonglong2 w[4];
            #pragma unroll
            for (int j = 0; j < 3; j++)
                w[j] = *(const ulonglong2*)&Whh[(tid + j * 256) * HD + k];
            w[3] = c3ok ? *(const ulonglong2*)&Whh[(tid + 768) * HD + k]
                        : make_ulonglong2(0ull, 0ull);
            #pragma unroll
            for (int m = 0; m < MPB; m++) {
                ulonglong2 hv = *(const ulonglong2*)&h_s[m * 304 + k];
                #pragma unroll
                for (int j = 0; j < 4; j++) {
                    fma2(acc[j][m], w[j].x, hv.x);
                    fma2(acc[j][m], w[j].y, hv.y);
                }
            }
        }
        #pragma unroll
        for (int j = 0; j < 4; j++) {
            int cc = tid + j * 256;
            if (cc < 3 * HD) {
                float bb = bhh[cc];
                #pragma unroll
                for (int m = 0; m < MPB; m++) {
                    float2 p = *reinterpret_cast<float2*>(&acc[j][m]);
                    gh_s[m * 912 + cc] = p.x + p.y + bb;
                }
            }
        }
        __syncthreads();

        for (int i = tid; i < mc * HD; i += 256) {
            int m = i / HD, hh = i - m * HD;
            int row = (mol0 + m) * ASIZE + t;
            float ir = xp[row * (3*HD) + hh];
            float iz = xp[row * (3*HD) + HD + hh];
            float in = xp[row * (3*HD) + 2*HD + hh];
            float hr = gh_s[m * 912 + hh];
            float hz = gh_s[m * 912 + HD + hh];
            float hn = gh_s[m * 912 + 2*HD + hh];
            float r = sigmoidf_(ir + hr);
            float z = sigmoidf_(iz + hz);
            float n = tanhf(in + r * hn);
            float hp = h_s[m * 304 + hh];
            float hnew = (1.f - z) * n + z * hp;
            h_s[m * 304 + hh] = hnew;
            out[row * (2*HD) + dir * HD + hh] = hnew;
        }
        __syncthreads();
    }
}

// ======================= host orchestration =======================
static inline dim3 mma_grid(int M, int N) { return dim3((N + 63) / 64, (M + 127) / 128); }
static inline int  blocks_for(int n)      { return (n + 255) / 256; }

extern "C" void kernel_launch(void* const* d_in, const int* in_sizes, int n_in,
                              void* d_out, int out_size)
{
    const float* f_atoms  = (const float*)d_in[0];
    const float* f_bonds  = (const float*)d_in[1];
    const float* Wi_atom  = (const float*)d_in[2];
    const float* Wi_bond  = (const float*)d_in[3];
    const float* Wh0      = (const float*)d_in[4];
    const float* Wh1      = (const float*)d_in[5];
    const float* W_lr     = (const float*)d_in[6];
    const float* W_o      = (const float*)d_in[7];
    const float* b_o      = (const float*)d_in[8];
    const float* gru_bias = (const float*)d_in[9];
    const float* gWih_f   = (const float*)d_in[10];
    const float* gWhh_f   = (const float*)d_in[11];
    const float* gbih_f   = (const float*)d_in[12];
    const float* gbhh_f   = (const float*)d_in[13];
    const float* gWih_b   = (const float*)d_in[14];
    const float* gWhh_b   = (const float*)d_in[15];
    const float* gbih_b   = (const float*)d_in[16];
    const float* gbhh_b   = (const float*)d_in[17];
    const int*   a2b      = (const int*)d_in[18];
    const int*   b2a      = (const int*)d_in[19];
    const int*   b2revb   = (const int*)d_in[20];
    float* out = (float*)d_out;

    float *inA, *mA, *inB, *mB0, *mB1, *cc, *aggW, *msg, *xpf, *xpb, *h0, *gout, *hid;
    cudaGetSymbolAddress((void**)&inA,  g_input_atom);
    cudaGetSymbolAddress((void**)&mA,   g_message_atom);
    cudaGetSymbolAddress((void**)&inB,  g_input_bond);
    cudaGetSymbolAddress((void**)&mB0,  g_bondA);
    cudaGetSymbolAddress((void**)&mB1,  g_bondB);
    cudaGetSymbolAddress((void**)&cc,   g_concat);
    cudaGetSymbolAddress((void**)&aggW, g_aggW);
    cudaGetSymbolAddress((void**)&msg,  g_msg);
    cudaGetSymbolAddress((void**)&xpf,  g_xpf);
    cudaGetSymbolAddress((void**)&xpb,  g_xpb);
    cudaGetSymbolAddress((void**)&h0,   g_h0);
    cudaGetSymbolAddress((void**)&gout, g_out);
    cudaGetSymbolAddress((void**)&hid,  g_hid);

    const int gru_smem = (MPB * 304 + MPB * 912) * (int)sizeof(float);
    cudaFuncSetAttribute(gru_fused, cudaFuncAttributeMaxDynamicSharedMemorySize, gru_smem);

    // 1. input_atom = relu(f_atoms @ Wi_atom); dual-store into message_atom
    mma_gemm<false, 1, true, false><<<mma_grid(NATOMS, HD), 256>>>(
        f_atoms, Wi_atom, nullptr, nullptr, inA, mA, nullptr, nullptr, nullptr, nullptr,
        NATOMS, HD, AFDIM);

    // 2. input_bond = relu(f_bonds @ Wi_bond); dual-store into bond-message ping (mB0)
    mma_gemm<false, 1, true, false><<<mma_grid(NBONDS, HD), 256>>>(
        f_bonds, Wi_bond, nullptr, nullptr, inB, mB0, nullptr, nullptr, nullptr, nullptr,
        NBONDS, HD, BFDIM);

    // 3. two message-passing steps; mb gather fused into GEMM A-loader (ping-pong).
    agg_update_kernel<<<blocks_for(NATOMS * HD4), 256>>>(mB0, a2b, mA);
    mma_gemm<false, 2, false, true><<<mma_grid(NBONDS, HD), 256>>>(
        nullptr, Wh0, inB, nullptr, mB1, nullptr, b2a, b2revb, mA, mB0,
        NBONDS, HD, HD);
    agg_update_kernel<<<blocks_for(NATOMS * HD4), 256>>>(mB1, a2b, mA);
    mma_gemm<false, 2, false, true><<<mma_grid(NBONDS, HD), 256>>>(
        nullptr, Wh1, inB, nullptr, mB0, nullptr, b2a, b2revb, mA, mB1,
        NBONDS, HD, HD);

    // 4. final aggregation + concat + W_lr  (reads mB0; atom rows 1..NSEQ)
    final_concat_kernel<<<blocks_for(NSEQ * HD4), 256>>>(mB0, a2b, mA, inA, cc);
    mma_gemm<false, 0, false, false><<<mma_grid(NSEQ, HD), 256>>>(
        cc, W_lr, nullptr, nullptr, aggW, nullptr, nullptr, nullptr, nullptr, nullptr,
        NSEQ, HD, 3 * HD);

    // 5. BatchGRU prep
    msg_kernel<<<blocks_for(NSEQ * HD4), 256>>>(aggW, gru_bias, msg);
    h0_kernel<<<blocks_for(NMOLS * HD4), 256>>>(aggW, h0);

    // input projections: xp = msg @ Wih^T + bih
    mma_gemm<true, 3, false, false><<<mma_grid(NSEQ, 3 * HD), 256>>>(
        msg, gWih_f, nullptr, gbih_f, xpf, nullptr, nullptr, nullptr, nullptr, nullptr,
        NSEQ, 3 * HD, HD);
    mma_gemm<true, 3, false, false><<<mma_grid(NSEQ, 3 * HD), 256>>>(
        msg, gWih_b, nullptr, gbih_b, xpb, nullptr, nullptr, nullptr, nullptr, nullptr,
        NSEQ, 3 * HD, HD);

    // 6+7. both GRU directions, all 40 steps, one kernel
    {
        dim3 grid((NMOLS + MPB - 1) / MPB, 2);
        gru_fused<<<grid, 256, gru_smem>>>(xpf, xpb, gWhh_f, gWhh_b, gbhh_f, gbhh_b, h0, gout);
    }

    // 8. atom_hiddens = relu(out @ W_o + b_o); mol_vecs = per-mol mean
    mma_gemm<false, 4, false, false><<<mma_grid(NSEQ, HD), 256>>>(
        gout, W_o, nullptr, b_o, hid, nullptr, nullptr, nullptr, nullptr, nullptr,
        NSEQ, HD, 2 * HD);
    mean_kernel<<<blocks_for(NMOLS * HD4), 256>>>(hid, out);
}

// round 12
// speedup vs baseline: 1.6408x; 1.0017x over previous
#include <cuda_runtime.h>
#include <math.h>
#include <stdint.h>

#define NATOMS 40001
#define NBONDS 160001
#define NNB    6
#define AFDIM  133
#define BFDIM  147
#define HD     300
#define NMOLS  1000
#define ASIZE  40
#define NSEQ   (NMOLS * ASIZE)   /* 40000 */

// ---------------- scratch (static device globals; no runtime allocation) ----------------
__device__ float g_input_atom  [NATOMS * HD];
__device__ float g_message_atom[NATOMS * HD];
__device__ float g_input_bond  [NBONDS * HD];
__device__ float g_bondA       [NBONDS * HD];   // bond-message ping
__device__ float g_bondB       [NBONDS * HD];   // bond-message pong
__device__ float g_concat      [NSEQ * 3 * HD];
__device__ float g_aggW        [NSEQ * HD];
__device__ float g_msg         [NSEQ * HD];
__device__ float g_xpf         [NSEQ * 3 * HD];
__device__ float g_xpb         [NSEQ * 3 * HD];
__device__ float g_h0          [NMOLS * HD];
__device__ float g_out         [NSEQ * 2 * HD];
__device__ float g_hid         [NSEQ * HD];

// ======================= 3xTF32 split-precision tensor-core GEMM =======================
// Round 12: DOUBLE-BUFFERED smem (one __syncthreads per K-chunk; STS of chunk n+1
// overlaps compute of chunk n), float4 TRANSB B-loads, STG.64 epilogue.
// Numerics identical to round 11 (asymmetric hi/lo split, conflict-free BPAD=72).

__device__ __forceinline__ void mma_tf32(float c[4], const uint32_t a[4], const uint32_t b[2]) {
    asm volatile(
        "mma.sync.aligned.m16n8k8.row.col.f32.tf32.tf32.f32 "
        "{%0,%1,%2,%3}, {%4,%5,%6,%7}, {%8,%9}, {%0,%1,%2,%3};"
        : "+f"(c[0]), "+f"(c[1]), "+f"(c[2]), "+f"(c[3])
        : "r"(a[0]), "r"(a[1]), "r"(a[2]), "r"(a[3]), "r"(b[0]), "r"(b[1]));
}

__device__ __forceinline__ float f2tf32(float v) {
    uint32_t t;
    asm("cvt.rna.tf32.f32 %0, %1;" : "=r"(t) : "f"(v));
    return __uint_as_float(t);
}

__device__ __forceinline__ void split_tf32(float v, uint32_t& hi, uint32_t& lo) {
    float h = f2tf32(v);
    hi = __float_as_uint(h);
    lo = __float_as_uint(f2tf32(v - h));
}

#define BPAD 72

template<bool TRANSB, int EPI, bool DUAL, bool GATHER>
__global__ __launch_bounds__(256, 3)
void mma_gemm(const float* __restrict__ A, const float* __restrict__ B,
              const float* __restrict__ ADD, const float* __restrict__ bias,
              float* __restrict__ C, float* __restrict__ C2,
              const int* __restrict__ idxA, const int* __restrict__ idxB,
              const float* __restrict__ GA, const float* __restrict__ GB,
              int M, int N, int K)
{
    __shared__ float As[2][128][20];    // [buf][m][k] raw fp32 (conflict-free)
    __shared__ float Bh[2][16][BPAD];   // [buf][k][n] tf32 hi (conflict-free @72)
    __shared__ float Bl[2][16][BPAD];   // [buf][k][n] tf32 lo

    const int tid  = threadIdx.x;
    const int warp = tid >> 5, lane = tid & 31;
    const int wm   = warp & 3, wn = warp >> 2;
    const int gid  = lane >> 2, tig = lane & 3;
    const int bM   = blockIdx.y * 128, bN = blockIdx.x * 64;

    const int aRow = tid >> 2;
    const int aCol = (tid & 3) * 4;

    float aR[8], bR[4];
    float c[2][4][4] = {};

    const int nCh = (K + 15) >> 4;

    auto loadA = [&](int kt) {
        #pragma unroll
        for (int r = 0; r < 2; r++) {
            int gm  = bM + aRow + 64 * r;
            int gk0 = kt + aCol;
            if (GATHER) {
                if (gm < M) {
                    int ia = __ldg(&idxA[gm]);
                    int ib = __ldg(&idxB[gm]);
                    if (gk0 + 3 < K) {
                        float4 va = __ldg((const float4*)&GA[(size_t)ia * K + gk0]);
                        float4 vb = __ldg((const float4*)&GB[(size_t)ib * K + gk0]);
                        aR[r*4+0] = va.x - vb.x; aR[r*4+1] = va.y - vb.y;
                        aR[r*4+2] = va.z - vb.z; aR[r*4+3] = va.w - vb.w;
                    } else {
                        #pragma unroll
                        for (int i = 0; i < 4; i++) {
                            int gk = gk0 + i;
                            aR[r*4+i] = (gk < K)
                                ? __ldg(&GA[(size_t)ia * K + gk]) - __ldg(&GB[(size_t)ib * K + gk])
                                : 0.f;
                        }
                    }
                } else {
                    #pragma unroll
                    for (int i = 0; i < 4; i++) aR[r*4+i] = 0.f;
                }
            } else {
                #pragma unroll
                for (int i = 0; i < 4; i++) {
                    int gk = gk0 + i;
                    aR[r*4+i] = (gm < M && gk < K) ? A[(size_t)gm * K + gk] : 0.f;
                }
            }
        }
    };
    auto loadB = [&](int kt) {
        if (!TRANSB) {
            int k = tid >> 4, n0 = (tid & 15) * 4;
            #pragma unroll
            for (int i = 0; i < 4; i++) {
                int gk = kt + k, gn = bN + n0 + i;
                bR[i] = (gk < K && gn < N) ? B[(size_t)gk * N + gn] : 0.f;
            }
        } else {
            int n = tid >> 2, k0 = (tid & 3) * 4;
            int gn = bN + n, gk0 = kt + k0;
            if (gn < N && gk0 + 3 < K) {   // K multiple of 4 in all TRANSB uses -> 16B aligned
                float4 v = __ldg((const float4*)&B[(size_t)gn * K + gk0]);
                bR[0] = v.x; bR[1] = v.y; bR[2] = v.z; bR[3] = v.w;
            } else {
                #pragma unroll
                for (int i = 0; i < 4; i++) {
                    int gk = gk0 + i;
                    bR[i] = (gk < K && gn < N) ? B[(size_t)gn * K + gk] : 0.f;
                }
            }
        }
    };
    auto stsA = [&](int bs) {
        #pragma unroll
        for (int r = 0; r < 2; r++)
            *(float4*)&As[bs][aRow + 64*r][aCol] =
                make_float4(aR[r*4+0], aR[r*4+1], aR[r*4+2], aR[r*4+3]);
    };
    auto stsB = [&](int bs) {
        if (!TRANSB) {
            int k = tid >> 4, n0 = (tid & 15) * 4;
            float4 h, l;
            h.x = f2tf32(bR[0]); l.x = f2tf32(bR[0] - h.x);
            h.y = f2tf32(bR[1]); l.y = f2tf32(bR[1] - h.y);
            h.z = f2tf32(bR[2]); l.z = f2tf32(bR[2] - h.z);
            h.w = f2tf32(bR[3]); l.w = f2tf32(bR[3] - h.w);
            *(float4*)&Bh[bs][k][n0] = h;
            *(float4*)&Bl[bs][k][n0] = l;
        } else {
            int n = tid >> 2, k0 = (tid & 3) * 4;
            #pragma unroll
            for (int i = 0; i < 4; i++) {
                float h = f2tf32(bR[i]);
                Bh[bs][k0 + i][n] = h;
                Bl[bs][k0 + i][n] = f2tf32(bR[i] - h);
            }
        }
    };

    // prologue: chunk0 -> buf0; chunk1 -> regs
    loadA(0); loadB(0);
    stsA(0);  stsB(0);
    if (nCh > 1) { loadA(16); loadB(16); }

    for (int ch = 0; ch < nCh; ch++) {
        const int cur = ch & 1;
        __syncthreads();
        // stage chunk ch+1 into the other buffer; fetch chunk ch+2 into regs
        if (ch + 1 < nCh) { stsA(1 - cur); stsB(1 - cur); }
        if (ch + 2 < nCh) { loadA((ch + 2) << 4); loadB((ch + 2) << 4); }

        // compute chunk ch from buf[cur]
        #pragma unroll
        for (int kk = 0; kk < 16; kk += 8) {
            uint32_t ah[2][4], al[2][4], bh_[4][2], bl_[4][2];
            #pragma unroll
            for (int mt = 0; mt < 2; mt++) {
                int m0 = wm * 32 + mt * 16 + gid;
                split_tf32(As[cur][m0    ][kk + tig    ], ah[mt][0], al[mt][0]);
                split_tf32(As[cur][m0 + 8][kk + tig    ], ah[mt][1], al[mt][1]);
                split_tf32(As[cur][m0    ][kk + tig + 4], ah[mt][2], al[mt][2]);
                split_tf32(As[cur][m0 + 8][kk + tig + 4], ah[mt][3], al[mt][3]);
            }
            #pragma unroll
            for (int nt = 0; nt < 4; nt++) {
                int n0 = wn * 32 + nt * 8 + gid;
                bh_[nt][0] = __float_as_uint(Bh[cur][kk + tig    ][n0]);
                bh_[nt][1] = __float_as_uint(Bh[cur][kk + tig + 4][n0]);
                bl_[nt][0] = __float_as_uint(Bl[cur][kk + tig    ][n0]);
                bl_[nt][1] = __float_as_uint(Bl[cur][kk + tig + 4][n0]);
            }
            #pragma unroll
            for (int mt = 0; mt < 2; mt++)
                #pragma unroll
                for (int nt = 0; nt < 4; nt++) {
                    mma_tf32(c[mt][nt], ah[mt], bl_[nt]);
                    mma_tf32(c[mt][nt], al[mt], bh_[nt]);
                    mma_tf32(c[mt][nt], ah[mt], bh_[nt]);
                }
        }
    }

    // ---- epilogue: paired 64-bit stores (N even in all uses; col even) ----
    #pragma unroll
    for (int mt = 0; mt < 2; mt++)
        #pragma unroll
        for (int nt = 0; nt < 4; nt++)
            #pragma unroll
            for (int p = 0; p < 2; p++) {
                int row = bM + wm * 32 + mt * 16 + gid + p * 8;
                int col = bN + wn * 32 + nt * 8 + tig * 2;
                if (row < M && col < N) {
                    float2 v = make_float2(c[mt][nt][p*2], c[mt][nt][p*2 + 1]);
                    if (EPI == 2) {
                        float2 ad = *(const float2*)&ADD[(size_t)row * N + col];
                        v.x += ad.x; v.y += ad.y;
                    }
                    if (EPI == 3 || EPI == 4) { v.x += bias[col]; v.y += bias[col + 1]; }
                    if (EPI == 1 || EPI == 2 || EPI == 4) {
                        v.x = fmaxf(v.x, 0.f); v.y = fmaxf(v.y, 0.f);
                    }
                    *(float2*)&C[(size_t)row * N + col] = v;
                    if (DUAL) *(float2*)&C2[(size_t)row * N + col] = v;
                }
            }
}

// ======================= float4 gather/pointwise helpers =======================
#define HD4 (HD / 4)   /* 75 */

__device__ __forceinline__ float4 f4max(float4 a, float4 b) {
    return make_float4(fmaxf(a.x,b.x), fmaxf(a.y,b.y), fmaxf(a.z,b.z), fmaxf(a.w,b.w));
}
__device__ __forceinline__ float4 f4add(float4 a, float4 b) {
    return make_float4(a.x+b.x, a.y+b.y, a.z+b.z, a.w+b.w);
}

__global__ void agg_update_kernel(const float* __restrict__ mbond, const int* __restrict__ a2b,
                                  float* __restrict__ matom)
{
    int idx = blockIdx.x * blockDim.x + threadIdx.x;
    if (idx >= NATOMS * HD4) return;
    int a = idx / HD4, h4 = idx - a * HD4;
    float4 s  = make_float4(0.f, 0.f, 0.f, 0.f);
    float4 mx = make_float4(-INFINITY, -INFINITY, -INFINITY, -INFINITY);
    #pragma unroll
    for (int j = 0; j < NNB; j++) {
        int b = __ldg(&a2b[a * NNB + j]);
        float4 v = __ldg((const float4*)&mbond[b * HD] + h4);
        s = f4add(s, v); mx = f4max(mx, v);
    }
    float4* dst = (float4*)&matom[a * HD] + h4;
    float4 cur = *dst;
    cur.x += s.x * mx.x; cur.y += s.y * mx.y; cur.z += s.z * mx.z; cur.w += s.w * mx.w;
    *dst = cur;
}

__global__ void final_concat_kernel(const float* __restrict__ mbond, const int* __restrict__ a2b,
                                    const float* __restrict__ matom, const float* __restrict__ iatom,
                                    float* __restrict__ cc)
{
    int idx = blockIdx.x * blockDim.x + threadIdx.x;
    if (idx >= NSEQ * HD4) return;
    int row = idx / HD4, h4 = idx - row * HD4;
    int a = row + 1;
    float4 s  = make_float4(0.f, 0.f, 0.f, 0.f);
    float4 mx = make_float4(-INFINITY, -INFINITY, -INFINITY, -INFINITY);
    #pragma unroll
    for (int j = 0; j < NNB; j++) {
        int b = __ldg(&a2b[a * NNB + j]);
        float4 v = __ldg((const float4*)&mbond[b * HD] + h4);
        s = f4add(s, v); mx = f4max(mx, v);
    }
    float4 agg = make_float4(s.x*mx.x, s.y*mx.y, s.z*mx.z, s.w*mx.w);
    *((float4*)&cc[row * (3*HD)] + h4)            = agg;
    *((float4*)&cc[row * (3*HD) + HD] + h4)       = __ldg((const float4*)&matom[a * HD] + h4);
    *((float4*)&cc[row * (3*HD) + 2*HD] + h4)     = __ldg((const float4*)&iatom[a * HD] + h4);
}

__global__ void msg_kernel(const float* __restrict__ aggW, const float* __restrict__ gbias,
                           float* __restrict__ msg)
{
    int idx = blockIdx.x * blockDim.x + threadIdx.x;
    if (idx >= NSEQ * HD4) return;
    int h4 = idx % HD4;
    float4 v = __ldg((const float4*)aggW + idx);
    float4 b = __ldg((const float4*)gbias + h4);
    ((float4*)msg)[idx] = make_float4(fmaxf(v.x+b.x,0.f), fmaxf(v.y+b.y,0.f),
                                      fmaxf(v.z+b.z,0.f), fmaxf(v.w+b.w,0.f));
}

__global__ void h0_kernel(const float* __restrict__ aggW, float* __restrict__ h0)
{
    int idx = blockIdx.x * blockDim.x + threadIdx.x;
    if (idx >= NMOLS * HD4) return;
    int mol = idx / HD4, h4 = idx - mol * HD4;
    float4 mx = make_float4(-INFINITY, -INFINITY, -INFINITY, -INFINITY);
    for (int t = 0; t < ASIZE; t++)
        mx = f4max(mx, __ldg((const float4*)&aggW[(mol * ASIZE + t) * HD] + h4));
    ((float4*)h0)[idx] = mx;
}

__global__ void mean_kernel(const float* __restrict__ hid, float* __restrict__ out)
{
    int idx = blockIdx.x * blockDim.x + threadIdx.x;
    if (idx >= NMOLS * HD4) return;
    int mol = idx / HD4, h4 = idx - mol * HD4;
    float4 s = make_float4(0.f, 0.f, 0.f, 0.f);
    for (int t = 0; t < ASIZE; t++)
        s = f4add(s, __ldg((const float4*)&hid[(mol * ASIZE + t) * HD] + h4));
    ((float4*)out)[idx] = make_float4(s.x*(1.f/ASIZE), s.y*(1.f/ASIZE),
                                      s.z*(1.f/ASIZE), s.w*(1.f/ASIZE));
}

// ======================= fused bidirectional GRU (packed f32x2 FMA) =======================
#define MPB 14   /* 72 blocks x 2 dirs = 144 <= 148 SMs, single wave */

__device__ __forceinline__ float sigmoidf_(float x) { return 1.f / (1.f + expf(-x)); }

__device__ __forceinline__ void fma2(uint64_t& d, uint64_t a, uint64_t b) {
    asm("fma.rn.f32x2 %0, %1, %2, %0;" : "+l"(d) : "l"(a), "l"(b));
}

__global__ __launch_bounds__(256)
void gru_fused(const float* __restrict__ xp_f, const float* __restrict__ xp_b,
               const float* __restrict__ Whh_f, const float* __restrict__ Whh_b,  // [3H, H]
               const float* __restrict__ bhh_f, const float* __restrict__ bhh_b,
               const float* __restrict__ h0, float* __restrict__ out)
{
    extern __shared__ float sm[];
    float* h_s  = sm;               // [MPB][304]
    float* gh_s = sm + MPB * 304;   // [MPB][912]

    const int tid  = threadIdx.x;
    const int dir  = blockIdx.y;
    const int mol0 = blockIdx.x * MPB;
    const int mc   = min(MPB, NMOLS - mol0);

    const float* xp  = dir ? xp_b  : xp_f;
    const float* Whh = dir ? Whh_b : Whh_f;
    const float* bhh = dir ? bhh_b : bhh_f;

    for (int i = tid; i < MPB * 304; i += 256) h_s[i] = 0.f;
    __syncthreads();
    for (int i = tid; i < mc * HD; i += 256) {
        int m = i / HD, hh = i - m * HD;
        h_s[m * 304 + hh] = h0[(mol0 + m) * HD + hh];
    }
    __syncthreads();

    const int c3ok = (tid + 768 < 3 * HD);

    for (int s = 0; s < ASIZE; s++) {
        const int t = dir ? (ASIZE - 1 - s) : s;

        uint64_t acc[4][MPB];
        #pragma unroll
        for (int j = 0; j < 4; j++)
            #pragma unroll
            for (int m = 0; m < MPB; m++) acc[j][m] = 0ull;

        for (int k = 0; k < HD; k += 4) {
            ulonglong2 w[4];
            #pragma unroll
            for (int j = 0; j < 3; j++)
                w[j] = *(const ulonglong2*)&Whh[(tid + j * 256) * HD + k];
            w[3] = c3ok ? *(const ulonglong2*)&Whh[(tid + 768) * HD + k]
                        : make_ulonglong2(0ull, 0ull);
            #pragma unroll
            for (int m = 0; m < MPB; m++) {
                ulonglong2 hv = *(const ulonglong2*)&h_s[m * 304 + k];
                #pragma unroll
                for (int j = 0; j < 4; j++) {
                    fma2(acc[j][m], w[j].x, hv.x);
                    fma2(acc[j][m], w[j].y, hv.y);
                }
            }
        }
        #pragma unroll
        for (int j = 0; j < 4; j++) {
            int cc = tid + j * 256;
            if (cc < 3 * HD) {
                float bb = bhh[cc];
                #pragma unroll
                for (int m = 0; m < MPB; m++) {
                    float2 p = *reinterpret_cast<float2*>(&acc[j][m]);
                    gh_s[m * 912 + cc] = p.x + p.y + bb;
                }
            }
        }
        __syncthreads();

        for (int i = tid; i < mc * HD; i += 256) {
            int m = i / HD, hh = i - m * HD;
            int row = (mol0 + m) * ASIZE + t;
            float ir = xp[row * (3*HD) + hh];
            float iz = xp[row * (3*HD) + HD + hh];
            float in = xp[row * (3*HD) + 2*HD + hh];
            float hr = gh_s[m * 912 + hh];
            float hz = gh_s[m * 912 + HD + hh];
            float hn = gh_s[m * 912 + 2*HD + hh];
            float r = sigmoidf_(ir + hr);
            float z = sigmoidf_(iz + hz);
            float n = tanhf(in + r * hn);
            float hp = h_s[m * 304 + hh];
            float hnew = (1.f - z) * n + z * hp;
            h_s[m * 304 + hh] = hnew;
            out[row * (2*HD) + dir * HD + hh] = hnew;
        }
        __syncthreads();
    }
}

// ======================= host orchestration =======================
static inline dim3 mma_grid(int M, int N) { return dim3((N + 63) / 64, (M + 127) / 128); }
static inline int  blocks_for(int n)      { return (n + 255) / 256; }

extern "C" void kernel_launch(void* const* d_in, const int* in_sizes, int n_in,
                              void* d_out, int out_size)
{
    const float* f_atoms  = (const float*)d_in[0];
    const float* f_bonds  = (const float*)d_in[1];
    const float* Wi_atom  = (const float*)d_in[2];
    const float* Wi_bond  = (const float*)d_in[3];
    const float* Wh0      = (const float*)d_in[4];
    const float* Wh1      = (const float*)d_in[5];
    const float* W_lr     = (const float*)d_in[6];
    const float* W_o      = (const float*)d_in[7];
    const float* b_o      = (const float*)d_in[8];
    const float* gru_bias = (const float*)d_in[9];
    const float* gWih_f   = (const float*)d_in[10];
    const float* gWhh_f   = (const float*)d_in[11];
    const float* gbih_f   = (const float*)d_in[12];
    const float* gbhh_f   = (const float*)d_in[13];
    const float* gWih_b   = (const float*)d_in[14];
    const float* gWhh_b   = (const float*)d_in[15];
    const float* gbih_b   = (const float*)d_in[16];
    const float* gbhh_b   = (const float*)d_in[17];
    const int*   a2b      = (const int*)d_in[18];
    const int*   b2a      = (const int*)d_in[19];
    const int*   b2revb   = (const int*)d_in[20];
    float* out = (float*)d_out;

    float *inA, *mA, *inB, *mB0, *mB1, *cc, *aggW, *msg, *xpf, *xpb, *h0, *gout, *hid;
    cudaGetSymbolAddress((void**)&inA,  g_input_atom);
    cudaGetSymbolAddress((void**)&mA,   g_message_atom);
    cudaGetSymbolAddress((void**)&inB,  g_input_bond);
    cudaGetSymbolAddress((void**)&mB0,  g_bondA);
    cudaGetSymbolAddress((void**)&mB1,  g_bondB);
    cudaGetSymbolAddress((void**)&cc,   g_concat);
    cudaGetSymbolAddress((void**)&aggW, g_aggW);
    cudaGetSymbolAddress((void**)&msg,  g_msg);
    cudaGetSymbolAddress((void**)&xpf,  g_xpf);
    cudaGetSymbolAddress((void**)&xpb,  g_xpb);
    cudaGetSymbolAddress((void**)&h0,   g_h0);
    cudaGetSymbolAddress((void**)&gout, g_out);
    cudaGetSymbolAddress((void**)&hid,  g_hid);

    const int gru_smem = (MPB * 304 + MPB * 912) * (int)sizeof(float);
    cudaFuncSetAttribute(gru_fused, cudaFuncAttributeMaxDynamicSharedMemorySize, gru_smem);

    // 1. input_atom = relu(f_atoms @ Wi_atom); dual-store into message_atom
    mma_gemm<false, 1, true, false><<<mma_grid(NATOMS, HD), 256>>>(
        f_atoms, Wi_atom, nullptr, nullptr, inA, mA, nullptr, nullptr, nullptr, nullptr,
        NATOMS, HD, AFDIM);

    // 2. input_bond = relu(f_bonds @ Wi_bond); dual-store into bond-message ping (mB0)
    mma_gemm<false, 1, true, false><<<mma_grid(NBONDS, HD), 256>>>(
        f_bonds, Wi_bond, nullptr, nullptr, inB, mB0, nullptr, nullptr, nullptr, nullptr,
        NBONDS, HD, BFDIM);

    // 3. two message-passing steps; mb gather fused into GEMM A-loader (ping-pong).
    agg_update_kernel<<<blocks_for(NATOMS * HD4), 256>>>(mB0, a2b, mA);
    mma_gemm<false, 2, false, true><<<mma_grid(NBONDS, HD), 256>>>(
        nullptr, Wh0, inB, nullptr, mB1, nullptr, b2a, b2revb, mA, mB0,
        NBONDS, HD, HD);
    agg_update_kernel<<<blocks_for(NATOMS * HD4), 256>>>(mB1, a2b, mA);
    mma_gemm<false, 2, false, true><<<mma_grid(NBONDS, HD), 256>>>(
        nullptr, Wh1, inB, nullptr, mB0, nullptr, b2a, b2revb, mA, mB1,
        NBONDS, HD, HD);

    // 4. final aggregation + concat + W_lr  (reads mB0; atom rows 1..NSEQ)
    final_concat_kernel<<<blocks_for(NSEQ * HD4), 256>>>(mB0, a2b, mA, inA, cc);
    mma_gemm<false, 0, false, false><<<mma_grid(NSEQ, HD), 256>>>(
        cc, W_lr, nullptr, nullptr, aggW, nullptr, nullptr, nullptr, nullptr, nullptr,
        NSEQ, HD, 3 * HD);

    // 5. BatchGRU prep
    msg_kernel<<<blocks_for(NSEQ * HD4), 256>>>(aggW, gru_bias, msg);
    h0_kernel<<<blocks_for(NMOLS * HD4), 256>>>(aggW, h0);

    // input projections: xp = msg @ Wih^T + bih
    mma_gemm<true, 3, false, false><<<mma_grid(NSEQ, 3 * HD), 256>>>(
        msg, gWih_f, nullptr, gbih_f, xpf, nullptr, nullptr, nullptr, nullptr, nullptr,
        NSEQ, 3 * HD, HD);
    mma_gemm<true, 3, false, false><<<mma_grid(NSEQ, 3 * HD), 256>>>(
        msg, gWih_b, nullptr, gbih_b, xpb, nullptr, nullptr, nullptr, nullptr, nullptr,
        NSEQ, 3 * HD, HD);

    // 6+7. both GRU directions, all 40 steps, one kernel
    {
        dim3 grid((NMOLS + MPB - 1) / MPB, 2);
        gru_fused<<<grid, 256, gru_smem>>>(xpf, xpb, gWhh_f, gWhh_b, gbhh_f, gbhh_b, h0, gout);
    }

    // 8. atom_hiddens = relu(out @ W_o + b_o); mol_vecs = per-mol mean
    mma_gemm<false, 4, false, false><<<mma_grid(NSEQ, HD), 256>>>(
        gout, W_o, nullptr, b_o, hid, nullptr, nullptr, nullptr, nullptr, nullptr,
        NSEQ, HD, 2 * HD);
    mean_kernel<<<blocks_for(NMOLS * HD4), 256>>>(hid, out);
}

// round 13
// speedup vs baseline: 1.6922x; 1.0313x over previous
#include <cuda_runtime.h>
#include <math.h>
#include <stdint.h>

#define NATOMS 40001
#define NBONDS 160001
#define NNB    6
#define AFDIM  133
#define BFDIM  147
#define HD     300
#define NMOLS  1000
#define ASIZE  40
#define NSEQ   (NMOLS * ASIZE)   /* 40000 */

// ---------------- scratch (static device globals; no runtime allocation) ----------------
__device__ float g_input_atom  [NATOMS * HD];
__device__ float g_message_atom[NATOMS * HD];
__device__ float g_input_bond  [NBONDS * HD];
__device__ float g_bondA       [NBONDS * HD];   // bond-message ping
__device__ float g_bondB       [NBONDS * HD];   // bond-message pong
__device__ float g_concat      [NSEQ * 3 * HD];
__device__ float g_aggW        [NSEQ * HD];
__device__ float g_msg         [NSEQ * HD];
__device__ float g_xpf         [NSEQ * 3 * HD];
__device__ float g_xpb         [NSEQ * 3 * HD];
__device__ float g_h0          [NMOLS * HD];
__device__ float g_out         [NSEQ * 2 * HD];
__device__ float g_hid         [NSEQ * HD];

// ======================= 3xTF32 split-precision tensor-core GEMM =======================
// Round 13 = Round 11 single-buffer pipeline (verified fastest) + the two R12 riders:
// float4 TRANSB B-loads and float2 (STG.64) epilogue. Double-buffering reverted
// (measured regression: runtime buffer indexing + STS/compute smem-port contention).
// Asymmetric split: A raw fp32 in smem (split in regs, x2 redundancy);
// B pre-split Bh/Bl in smem (split once by loaders). BPAD=72 -> conflict-free.

__device__ __forceinline__ void mma_tf32(float c[4], const uint32_t a[4], const uint32_t b[2]) {
    asm volatile(
        "mma.sync.aligned.m16n8k8.row.col.f32.tf32.tf32.f32 "
        "{%0,%1,%2,%3}, {%4,%5,%6,%7}, {%8,%9}, {%0,%1,%2,%3};"
        : "+f"(c[0]), "+f"(c[1]), "+f"(c[2]), "+f"(c[3])
        : "r"(a[0]), "r"(a[1]), "r"(a[2]), "r"(a[3]), "r"(b[0]), "r"(b[1]));
}

__device__ __forceinline__ float f2tf32(float v) {
    uint32_t t;
    asm("cvt.rna.tf32.f32 %0, %1;" : "=r"(t) : "f"(v));
    return __uint_as_float(t);
}

__device__ __forceinline__ void split_tf32(float v, uint32_t& hi, uint32_t& lo) {
    float h = f2tf32(v);
    hi = __float_as_uint(h);
    lo = __float_as_uint(f2tf32(v - h));
}

#define BPAD 72

template<bool TRANSB, int EPI, bool DUAL, bool GATHER>
__global__ __launch_bounds__(256, 3)
void mma_gemm(const float* __restrict__ A, const float* __restrict__ B,
              const float* __restrict__ ADD, const float* __restrict__ bias,
              float* __restrict__ C, float* __restrict__ C2,
              const int* __restrict__ idxA, const int* __restrict__ idxB,
              const float* __restrict__ GA, const float* __restrict__ GB,
              int M, int N, int K)
{
    __shared__ float As[128][20];    // [m][k] raw fp32 (conflict-free)
    __shared__ float Bh[16][BPAD];   // [k][n] tf32 hi (conflict-free @72)
    __shared__ float Bl[16][BPAD];   // [k][n] tf32 lo

    const int tid  = threadIdx.x;
    const int warp = tid >> 5, lane = tid & 31;
    const int wm   = warp & 3, wn = warp >> 2;
    const int gid  = lane >> 2, tig = lane & 3;
    const int bM   = blockIdx.y * 128, bN = blockIdx.x * 64;

    const int aRow = tid >> 2;
    const int aCol = (tid & 3) * 4;

    float aR[8], bR[4];
    float c[2][4][4] = {};

    const int nCh = (K + 15) >> 4;

    auto loadA = [&](int kt) {
        #pragma unroll
        for (int r = 0; r < 2; r++) {
            int gm  = bM + aRow + 64 * r;
            int gk0 = kt + aCol;
            if (GATHER) {
                if (gm < M) {
                    int ia = __ldg(&idxA[gm]);
                    int ib = __ldg(&idxB[gm]);
                    if (gk0 + 3 < K) {
                        float4 va = __ldg((const float4*)&GA[(size_t)ia * K + gk0]);
                        float4 vb = __ldg((const float4*)&GB[(size_t)ib * K + gk0]);
                        aR[r*4+0] = va.x - vb.x; aR[r*4+1] = va.y - vb.y;
                        aR[r*4+2] = va.z - vb.z; aR[r*4+3] = va.w - vb.w;
                    } else {
                        #pragma unroll
                        for (int i = 0; i < 4; i++) {
                            int gk = gk0 + i;
                            aR[r*4+i] = (gk < K)
                                ? __ldg(&GA[(size_t)ia * K + gk]) - __ldg(&GB[(size_t)ib * K + gk])
                                : 0.f;
                        }
                    }
                } else {
                    #pragma unroll
                    for (int i = 0; i < 4; i++) aR[r*4+i] = 0.f;
                }
            } else {
                #pragma unroll
                for (int i = 0; i < 4; i++) {
                    int gk = gk0 + i;
                    aR[r*4+i] = (gm < M && gk < K) ? A[(size_t)gm * K + gk] : 0.f;
                }
            }
        }
    };
    auto loadB = [&](int kt) {
        if (!TRANSB) {
            int k = tid >> 4, n0 = (tid & 15) * 4;
            #pragma unroll
            for (int i = 0; i < 4; i++) {
                int gk = kt + k, gn = bN + n0 + i;
                bR[i] = (gk < K && gn < N) ? B[(size_t)gk * N + gn] : 0.f;
            }
        } else {
            int n = tid >> 2, k0 = (tid & 3) * 4;
            int gn = bN + n, gk0 = kt + k0;
            if (gn < N && gk0 + 3 < K) {   // K multiple of 4 in all TRANSB uses -> 16B aligned
                float4 v = __ldg((const float4*)&B[(size_t)gn * K + gk0]);
                bR[0] = v.x; bR[1] = v.y; bR[2] = v.z; bR[3] = v.w;
            } else {
                #pragma unroll
                for (int i = 0; i < 4; i++) {
                    int gk = gk0 + i;
                    bR[i] = (gk < K && gn < N) ? B[(size_t)gn * K + gk] : 0.f;
                }
            }
        }
    };

    loadA(0);
    loadB(0);

    for (int ch = 0; ch < nCh; ch++) {
        // ---- STS: A raw; B split once here ----
        #pragma unroll
        for (int r = 0; r < 2; r++)
            *(float4*)&As[aRow + 64*r][aCol] =
                make_float4(aR[r*4+0], aR[r*4+1], aR[r*4+2], aR[r*4+3]);
        if (!TRANSB) {
            int k = tid >> 4, n0 = (tid & 15) * 4;
            float4 h, l;
            h.x = f2tf32(bR[0]); l.x = f2tf32(bR[0] - h.x);
            h.y = f2tf32(bR[1]); l.y = f2tf32(bR[1] - h.y);
            h.z = f2tf32(bR[2]); l.z = f2tf32(bR[2] - h.z);
            h.w = f2tf32(bR[3]); l.w = f2tf32(bR[3] - h.w);
            *(float4*)&Bh[k][n0] = h;
            *(float4*)&Bl[k][n0] = l;
        } else {
            int n = tid >> 2, k0 = (tid & 3) * 4;
            #pragma unroll
            for (int i = 0; i < 4; i++) {
                float h = f2tf32(bR[i]);
                Bh[k0 + i][n] = h;
                Bl[k0 + i][n] = f2tf32(bR[i] - h);
            }
        }
        __syncthreads();

        if (ch + 1 < nCh) {
            loadA((ch + 1) << 4);
            loadB((ch + 1) << 4);
        }

        // ---- compute chunk: A split in regs, B pre-split in smem ----
        #pragma unroll
        for (int kk = 0; kk < 16; kk += 8) {
            uint32_t ah[2][4], al[2][4], bh_[4][2], bl_[4][2];
            #pragma unroll
            for (int mt = 0; mt < 2; mt++) {
                int m0 = wm * 32 + mt * 16 + gid;
                split_tf32(As[m0    ][kk + tig    ], ah[mt][0], al[mt][0]);
                split_tf32(As[m0 + 8][kk + tig    ], ah[mt][1], al[mt][1]);
                split_tf32(As[m0    ][kk + tig + 4], ah[mt][2], al[mt][2]);
                split_tf32(As[m0 + 8][kk + tig + 4], ah[mt][3], al[mt][3]);
            }
            #pragma unroll
            for (int nt = 0; nt < 4; nt++) {
                int n0 = wn * 32 + nt * 8 + gid;
                bh_[nt][0] = __float_as_uint(Bh[kk + tig    ][n0]);
                bh_[nt][1] = __float_as_uint(Bh[kk + tig + 4][n0]);
                bl_[nt][0] = __float_as_uint(Bl[kk + tig    ][n0]);
                bl_[nt][1] = __float_as_uint(Bl[kk + tig + 4][n0]);
            }
            #pragma unroll
            for (int mt = 0; mt < 2; mt++)
                #pragma unroll
                for (int nt = 0; nt < 4; nt++) {
                    mma_tf32(c[mt][nt], ah[mt], bl_[nt]);
                    mma_tf32(c[mt][nt], al[mt], bh_[nt]);
                    mma_tf32(c[mt][nt], ah[mt], bh_[nt]);
                }
        }
        __syncthreads();
    }

    // ---- epilogue: paired 64-bit stores (N even in all uses; col even) ----
    #pragma unroll
    for (int mt = 0; mt < 2; mt++)
        #pragma unroll
        for (int nt = 0; nt < 4; nt++)
            #pragma unroll
            for (int p = 0; p < 2; p++) {
                int row = bM + wm * 32 + mt * 16 + gid + p * 8;
                int col = bN + wn * 32 + nt * 8 + tig * 2;
                if (row < M && col < N) {
                    float2 v = make_float2(c[mt][nt][p*2], c[mt][nt][p*2 + 1]);
                    if (EPI == 2) {
                        float2 ad = *(const float2*)&ADD[(size_t)row * N + col];
                        v.x += ad.x; v.y += ad.y;
                    }
                    if (EPI == 3 || EPI == 4) { v.x += bias[col]; v.y += bias[col + 1]; }
                    if (EPI == 1 || EPI == 2 || EPI == 4) {
                        v.x = fmaxf(v.x, 0.f); v.y = fmaxf(v.y, 0.f);
                    }
                    *(float2*)&C[(size_t)row * N + col] = v;
                    if (DUAL) *(float2*)&C2[(size_t)row * N + col] = v;
                }
            }
}

// ======================= float4 gather/pointwise helpers =======================
#define HD4 (HD / 4)   /* 75 */

__device__ __forceinline__ float4 f4max(float4 a, float4 b) {
    return make_float4(fmaxf(a.x,b.x), fmaxf(a.y,b.y), fmaxf(a.z,b.z), fmaxf(a.w,b.w));
}
__device__ __forceinline__ float4 f4add(float4 a, float4 b) {
    return make_float4(a.x+b.x, a.y+b.y, a.z+b.z, a.w+b.w);
}

__global__ void agg_update_kernel(const float* __restrict__ mbond, const int* __restrict__ a2b,
                                  float* __restrict__ matom)
{
    int idx = blockIdx.x * blockDim.x + threadIdx.x;
    if (idx >= NATOMS * HD4) return;
    int a = idx / HD4, h4 = idx - a * HD4;
    float4 s  = make_float4(0.f, 0.f, 0.f, 0.f);
    float4 mx = make_float4(-INFINITY, -INFINITY, -INFINITY, -INFINITY);
    #pragma unroll
    for (int j = 0; j < NNB; j++) {
        int b = __ldg(&a2b[a * NNB + j]);
        float4 v = __ldg((const float4*)&mbond[b * HD] + h4);
        s = f4add(s, v); mx = f4max(mx, v);
    }
    float4* dst = (float4*)&matom[a * HD] + h4;
    float4 cur = *dst;
    cur.x += s.x * mx.x; cur.y += s.y * mx.y; cur.z += s.z * mx.z; cur.w += s.w * mx.w;
    *dst = cur;
}

__global__ void final_concat_kernel(const float* __restrict__ mbond, const int* __restrict__ a2b,
                                    const float* __restrict__ matom, const float* __restrict__ iatom,
                                    float* __restrict__ cc)
{
    int idx = blockIdx.x * blockDim.x + threadIdx.x;
    if (idx >= NSEQ * HD4) return;
    int row = idx / HD4, h4 = idx - row * HD4;
    int a = row + 1;
    float4 s  = make_float4(0.f, 0.f, 0.f, 0.f);
    float4 mx = make_float4(-INFINITY, -INFINITY, -INFINITY, -INFINITY);
    #pragma unroll
    for (int j = 0; j < NNB; j++) {
        int b = __ldg(&a2b[a * NNB + j]);
        float4 v = __ldg((const float4*)&mbond[b * HD] + h4);
        s = f4add(s, v); mx = f4max(mx, v);
    }
    float4 agg = make_float4(s.x*mx.x, s.y*mx.y, s.z*mx.z, s.w*mx.w);
    *((float4*)&cc[row * (3*HD)] + h4)            = agg;
    *((float4*)&cc[row * (3*HD) + HD] + h4)       = __ldg((const float4*)&matom[a * HD] + h4);
    *((float4*)&cc[row * (3*HD) + 2*HD] + h4)     = __ldg((const float4*)&iatom[a * HD] + h4);
}

__global__ void msg_kernel(const float* __restrict__ aggW, const float* __restrict__ gbias,
                           float* __restrict__ msg)
{
    int idx = blockIdx.x * blockDim.x + threadIdx.x;
    if (idx >= NSEQ * HD4) return;
    int h4 = idx % HD4;
    float4 v = __ldg((const float4*)aggW + idx);
    float4 b = __ldg((const float4*)gbias + h4);
    ((float4*)msg)[idx] = make_float4(fmaxf(v.x+b.x,0.f), fmaxf(v.y+b.y,0.f),
                                      fmaxf(v.z+b.z,0.f), fmaxf(v.w+b.w,0.f));
}

__global__ void h0_kernel(const float* __restrict__ aggW, float* __restrict__ h0)
{
    int idx = blockIdx.x * blockDim.x + threadIdx.x;
    if (idx >= NMOLS * HD4) return;
    int mol = idx / HD4, h4 = idx - mol * HD4;
    float4 mx = make_float4(-INFINITY, -INFINITY, -INFINITY, -INFINITY);
    for (int t = 0; t < ASIZE; t++)
        mx = f4max(mx, __ldg((const float4*)&aggW[(mol * ASIZE + t) * HD] + h4));
    ((float4*)h0)[idx] = mx;
}

__global__ void mean_kernel(const float* __restrict__ hid, float* __restrict__ out)
{
    int idx = blockIdx.x * blockDim.x + threadIdx.x;
    if (idx >= NMOLS * HD4) return;
    int mol = idx / HD4, h4 = idx - mol * HD4;
    float4 s = make_float4(0.f, 0.f, 0.f, 0.f);
    for (int t = 0; t < ASIZE; t++)
        s = f4add(s, __ldg((const float4*)&hid[(mol * ASIZE + t) * HD] + h4));
    ((float4*)out)[idx] = make_float4(s.x*(1.f/ASIZE), s.y*(1.f/ASIZE),
                                      s.z*(1.f/ASIZE), s.w*(1.f/ASIZE));
}

// ======================= fused bidirectional GRU (packed f32x2 FMA) =======================
#define MPB 14   /* 72 blocks x 2 dirs = 144 <= 148 SMs, single wave */

__device__ __forceinline__ float sigmoidf_(float x) { return 1.f / (1.f + expf(-x)); }

__device__ __forceinline__ void fma2(uint64_t& d, uint64_t a, uint64_t b) {
    asm("fma.rn.f32x2 %0, %1, %2, %0;" : "+l"(d) : "l"(a), "l"(b));
}

__global__ __launch_bounds__(256)
void gru_fused(const float* __restrict__ xp_f, const float* __restrict__ xp_b,
               const float* __restrict__ Whh_f, const float* __restrict__ Whh_b,  // [3H, H]
               const float* __restrict__ bhh_f, const float* __restrict__ bhh_b,
               const float* __restrict__ h0, float* __restrict__ out)
{
    extern __shared__ float sm[];
    float* h_s  = sm;               // [MPB][304]
    float* gh_s = sm + MPB * 304;   // [MPB][912]

    const int tid  = threadIdx.x;
    const int dir  = blockIdx.y;
    const int mol0 = blockIdx.x * MPB;
    const int mc   = min(MPB, NMOLS - mol0);

    const float* xp  = dir ? xp_b  : xp_f;
    const float* Whh = dir ? Whh_b : Whh_f;
    const float* bhh = dir ? bhh_b : bhh_f;

    for (int i = tid; i < MPB * 304; i += 256) h_s[i] = 0.f;
    __syncthreads();
    for (int i = tid; i < mc * HD; i += 256) {
        int m = i / HD, hh = i - m * HD;
        h_s[m * 304 + hh] = h0[(mol0 + m) * HD + hh];
    }
    __syncthreads();

    const int c3ok = (tid + 768 < 3 * HD);

    for (int s = 0; s < ASIZE; s++) {
        const int t = dir ? (ASIZE - 1 - s) : s;

        uint64_t acc[4][MPB];
        #pragma unroll
        for (int j = 0; j < 4; j++)
            #pragma unroll
            for (int m = 0; m < MPB; m++) acc[j][m] = 0ull;

        for (int k = 0; k < HD; k += 4) {
            ulonglong2 w[4];
            #pragma unroll
            for (int j = 0; j < 3; j++)
                w[j] = *(const ulonglong2*)&Whh[(tid + j * 256) * HD + k];
            w[3] = c3ok ? *(const ulonglong2*)&Whh[(tid + 768) * HD + k]
                        : make_ulonglong2(0ull, 0ull);
            #pragma unroll
            for (int m = 0; m < MPB; m++) {
                ulonglong2 hv = *(const ulonglong2*)&h_s[m * 304 + k];
                #pragma unroll
                for (int j = 0; j < 4; j++) {
                    fma2(acc[j][m], w[j].x, hv.x);
                    fma2(acc[j][m], w[j].y, hv.y);
                }
            }
        }
        #pragma unroll
        for (int j = 0; j < 4; j++) {
            int cc = tid + j * 256;
            if (cc < 3 * HD) {
                float bb = bhh[cc];
                #pragma unroll
                for (int m = 0; m < MPB; m++) {
                    float2 p = *reinterpret_cast<float2*>(&acc[j][m]);
                    gh_s[m * 912 + cc] = p.x + p.y + bb;
                }
            }
        }
        __syncthreads();

        for (int i = tid; i < mc * HD; i += 256) {
            int m = i / HD, hh = i - m * HD;
            int row = (mol0 + m) * ASIZE + t;
            float ir = xp[row * (3*HD) + hh];
            float iz = xp[row * (3*HD) + HD + hh];
            float in = xp[row * (3*HD) + 2*HD + hh];
            float hr = gh_s[m * 912 + hh];
            float hz = gh_s[m * 912 + HD + hh];
            float hn = gh_s[m * 912 + 2*HD + hh];
            float r = sigmoidf_(ir + hr);
            float z = sigmoidf_(iz + hz);
            float n = tanhf(in + r * hn);
            float hp = h_s[m * 304 + hh];
            float hnew = (1.f - z) * n + z * hp;
            h_s[m * 304 + hh] = hnew;
            out[row * (2*HD) + dir * HD + hh] = hnew;
        }
        __syncthreads();
    }
}

// ======================= host orchestration =======================
static inline dim3 mma_grid(int M, int N) { return dim3((N + 63) / 64, (M + 127) / 128); }
static inline int  blocks_for(int n)      { return (n + 255) / 256; }

extern "C" void kernel_launch(void* const* d_in, const int* in_sizes, int n_in,
                              void* d_out, int out_size)
{
    const float* f_atoms  = (const float*)d_in[0];
    const float* f_bonds  = (const float*)d_in[1];
    const float* Wi_atom  = (const float*)d_in[2];
    const float* Wi_bond  = (const float*)d_in[3];
    const float* Wh0      = (const float*)d_in[4];
    const float* Wh1      = (const float*)d_in[5];
    const float* W_lr     = (const float*)d_in[6];
    const float* W_o      = (const float*)d_in[7];
    const float* b_o      = (const float*)d_in[8];
    const float* gru_bias = (const float*)d_in[9];
    const float* gWih_f   = (const float*)d_in[10];
    const float* gWhh_f   = (const float*)d_in[11];
    const float* gbih_f   = (const float*)d_in[12];
    const float* gbhh_f   = (const float*)d_in[13];
    const float* gWih_b   = (const float*)d_in[14];
    const float* gWhh_b   = (const float*)d_in[15];
    const float* gbih_b   = (const float*)d_in[16];
    const float* gbhh_b   = (const float*)d_in[17];
    const int*   a2b      = (const int*)d_in[18];
    const int*   b2a      = (const int*)d_in[19];
    const int*   b2revb   = (const int*)d_in[20];
    float* out = (float*)d_out;

    float *inA, *mA, *inB, *mB0, *mB1, *cc, *aggW, *msg, *xpf, *xpb, *h0, *gout, *hid;
    cudaGetSymbolAddress((void**)&inA,  g_input_atom);
    cudaGetSymbolAddress((void**)&mA,   g_message_atom);
    cudaGetSymbolAddress((void**)&inB,  g_input_bond);
    cudaGetSymbolAddress((void**)&mB0,  g_bondA);
    cudaGetSymbolAddress((void**)&mB1,  g_bondB);
    cudaGetSymbolAddress((void**)&cc,   g_concat);
    cudaGetSymbolAddress((void**)&aggW, g_aggW);
    cudaGetSymbolAddress((void**)&msg,  g_msg);
    cudaGetSymbolAddress((void**)&xpf,  g_xpf);
    cudaGetSymbolAddress((void**)&xpb,  g_xpb);
    cudaGetSymbolAddress((void**)&h0,   g_h0);
    cudaGetSymbolAddress((void**)&gout, g_out);
    cudaGetSymbolAddress((void**)&hid,  g_hid);

    const int gru_smem = (MPB * 304 + MPB * 912) * (int)sizeof(float);
    cudaFuncSetAttribute(gru_fused, cudaFuncAttributeMaxDynamicSharedMemorySize, gru_smem);

    // 1. input_atom = relu(f_atoms @ Wi_atom); dual-store into message_atom
    mma_gemm<false, 1, true, false><<<mma_grid(NATOMS, HD), 256>>>(
        f_atoms, Wi_atom, nullptr, nullptr, inA, mA, nullptr, nullptr, nullptr, nullptr,
        NATOMS, HD, AFDIM);

    // 2. input_bond = relu(f_bonds @ Wi_bond); dual-store into bond-message ping (mB0)
    mma_gemm<false, 1, true, false><<<mma_grid(NBONDS, HD), 256>>>(
        f_bonds, Wi_bond, nullptr, nullptr, inB, mB0, nullptr, nullptr, nullptr, nullptr,
        NBONDS, HD, BFDIM);

    // 3. two message-passing steps; mb gather fused into GEMM A-loader (ping-pong).
    agg_update_kernel<<<blocks_for(NATOMS * HD4), 256>>>(mB0, a2b, mA);
    mma_gemm<false, 2, false, true><<<mma_grid(NBONDS, HD), 256>>>(
        nullptr, Wh0, inB, nullptr, mB1, nullptr, b2a, b2revb, mA, mB0,
        NBONDS, HD, HD);
    agg_update_kernel<<<blocks_for(NATOMS * HD4), 256>>>(mB1, a2b, mA);
    mma_gemm<false, 2, false, true><<<mma_grid(NBONDS, HD), 256>>>(
        nullptr, Wh1, inB, nullptr, mB0, nullptr, b2a, b2revb, mA, mB1,
        NBONDS, HD, HD);

    // 4. final aggregation + concat + W_lr  (reads mB0; atom rows 1..NSEQ)
    final_concat_kernel<<<blocks_for(NSEQ * HD4), 256>>>(mB0, a2b, mA, inA, cc);
    mma_gemm<false, 0, false, false><<<mma_grid(NSEQ, HD), 256>>>(
        cc, W_lr, nullptr, nullptr, aggW, nullptr, nullptr, nullptr, nullptr, nullptr,
        NSEQ, HD, 3 * HD);

    // 5. BatchGRU prep
    msg_kernel<<<blocks_for(NSEQ * HD4), 256>>>(aggW, gru_bias, msg);
    h0_kernel<<<blocks_for(NMOLS * HD4), 256>>>(aggW, h0);

    // input projections: xp = msg @ Wih^T + bih
    mma_gemm<true, 3, false, false><<<mma_grid(NSEQ, 3 * HD), 256>>>(
        msg, gWih_f, nullptr, gbih_f, xpf, nullptr, nullptr, nullptr, nullptr, nullptr,
        NSEQ, 3 * HD, HD);
    mma_gemm<true, 3, false, false><<<mma_grid(NSEQ, 3 * HD), 256>>>(
        msg, gWih_b, nullptr, gbih_b, xpb, nullptr, nullptr, nullptr, nullptr, nullptr,
        NSEQ, 3 * HD, HD);

    // 6+7. both GRU directions, all 40 steps, one kernel
    {
        dim3 grid((NMOLS + MPB - 1) / MPB, 2);
        gru_fused<<<grid, 256, gru_smem>>>(xpf, xpb, gWhh_f, gWhh_b, gbhh_f, gbhh_b, h0, gout);
    }

    // 8. atom_hiddens = relu(out @ W_o + b_o); mol_vecs = per-mol mean
    mma_gemm<false, 4, false, false><<<mma_grid(NSEQ, HD), 256>>>(
        gout, W_o, nullptr, b_o, hid, nullptr, nullptr, nullptr, nullptr, nullptr,
        NSEQ, HD, 2 * HD);
    mean_kernel<<<blocks_for(NMOLS * HD4), 256>>>(hid, out);
}